// round 3
// baseline (speedup 1.0000x reference)
#include <cuda_runtime.h>

// ---------------------------------------------------------------------------
// ChunkParallelGRU: B=64, T=512, D=1024, H=1024, CHUNK=4
//
// Decomposition:
//   pre[g][m][n] = x[m] @ Wg_x + bg          (g in {z,r,h}, m = b*T+t)  -> big GEMM
//   per step t (sequential):
//     z_pre = pre_z + h @ Wz_h ; r_pre = pre_r + h @ Wr_h     (phase 1)
//     cand  = tanh(pre_h + (sigmoid(r_pre)*h) @ Wh_h)
//     h_new = (1-z)*h + z*cand ; out[t] = h_new               (phase 2)
//     on chunk boundary: h = tanh(h_new @ Wp + bp)            (phase 3)
// ---------------------------------------------------------------------------

#define BB 64
#define TT 512
#define DD 1024
#define HH 1024
#define BT (BB * TT)
#define NB 128          // persistent grid size (<= 148 SMs -> all co-resident)

// Scratch (static __device__ arrays: allocation-free per harness rules)
__device__ float g_pre[(size_t)BT * 3072];      // [m][z|r|h] 402 MB
__device__ float g_wt_zr[2048 * 1024];          // transposed h-parts of Wz|Wr: [n][k]
__device__ float g_wt_h[1024 * 1024];           // transposed h-part of Wh
__device__ float g_wt_p[1024 * 1024];           // transposed Wp
__device__ float g_hbuf[2][BB * HH];            // double-buffered state
__device__ float g_zr[BB * 2048];               // z_pre | r_pre for current step
__device__ unsigned g_bar_count;                // zero-init
__device__ unsigned g_bar_gen;                  // zero-init, monotonically grows

__device__ __forceinline__ float sigmoidf_(float x) {
    return 1.0f / (1.0f + __expf(-x));
}

// ---------------------------------------------------------------------------
// Grid-wide barrier (manual; all NB blocks are resident since NB <= #SMs).
// ---------------------------------------------------------------------------
__device__ __forceinline__ void grid_barrier() {
    __syncthreads();
    if (threadIdx.x == 0) {
        __threadfence();
        unsigned g = *(volatile unsigned*)&g_bar_gen;   // stable: gen bumps only after all arrive
        unsigned arrived = atomicAdd(&g_bar_count, 1u);
        if (arrived == NB - 1) {
            atomicExch(&g_bar_count, 0u);
            __threadfence();
            atomicAdd(&g_bar_gen, 1u);
        } else {
            while (*(volatile unsigned*)&g_bar_gen == g) { __nanosleep(40); }
        }
        __threadfence();
    }
    __syncthreads();
}

// ---------------------------------------------------------------------------
// Weight transpose: dst[n][k] = src[srcOff + k][n]   (1024x1024 tiles)
//   z=0: Wz h-part -> g_wt_zr[0:1024]
//   z=1: Wr h-part -> g_wt_zr[1024:2048]
//   z=2: Wh h-part -> g_wt_h
//   z=3: Wp        -> g_wt_p
// ---------------------------------------------------------------------------
__global__ void transpose_weights(const float* __restrict__ Wz,
                                  const float* __restrict__ Wr,
                                  const float* __restrict__ Wh,
                                  const float* __restrict__ Wp) {
    __shared__ float tile[32][33];
    const int z = blockIdx.z;
    const float* src;
    float* dst;
    int srcOff;
    if (z == 0)      { src = Wz; dst = g_wt_zr;               srcOff = 1024; }
    else if (z == 1) { src = Wr; dst = g_wt_zr + 1024 * 1024; srcOff = 1024; }
    else if (z == 2) { src = Wh; dst = g_wt_h;                srcOff = 1024; }
    else             { src = Wp; dst = g_wt_p;                srcOff = 0;    }
    const int kBase = blockIdx.x * 32;
    const int cBase = blockIdx.y * 32;
    tile[threadIdx.y][threadIdx.x] =
        src[(srcOff + kBase + threadIdx.y) * 1024 + cBase + threadIdx.x];
    __syncthreads();
    dst[(cBase + threadIdx.y) * 1024 + kBase + threadIdx.x] =
        tile[threadIdx.x][threadIdx.y];
}

__global__ void init_h(const float* __restrict__ h0) {
    int i = blockIdx.x * blockDim.x + threadIdx.x;
    if (i < BB * HH) g_hbuf[0][i] = h0[i];
}

// ---------------------------------------------------------------------------
// Precompute GEMM: g_pre[m][g*1024+n] = sum_d X[m][d]*Wg[d][n] + bg[n]
// Classic 128x128x8 SGEMM, 256 threads, 8x8 register tiles.
// ---------------------------------------------------------------------------
__global__ void __launch_bounds__(256) sgemm_pre(
    const float* __restrict__ X,
    const float* __restrict__ Wz, const float* __restrict__ Wr, const float* __restrict__ Wh,
    const float* __restrict__ bz, const float* __restrict__ br, const float* __restrict__ bh) {
    const int g = blockIdx.z;
    const float* Bw   = (g == 0) ? Wz : (g == 1) ? Wr : Wh;
    const float* bias = (g == 0) ? bz : (g == 1) ? br : bh;
    const int m0 = blockIdx.y * 128;
    const int n0 = blockIdx.x * 128;

    __shared__ float As[8 * 128];   // [k][m] (transposed)
    __shared__ float Bs[8 * 128];   // [k][n]

    const int tid = threadIdx.x;
    const int tr = (tid / 16) * 8;
    const int tc = (tid % 16) * 8;

    const int arow = tid / 2;            // 0..127
    const int acol = (tid % 2) * 4;      // 0 / 4
    const int brow = tid / 32;           // 0..7
    const int bcol = (tid % 32) * 4;     // 0..124

    float acc[8][8];
#pragma unroll
    for (int i = 0; i < 8; i++)
#pragma unroll
        for (int j = 0; j < 8; j++) acc[i][j] = 0.0f;

    for (int k0 = 0; k0 < 1024; k0 += 8) {
        float4 av = *reinterpret_cast<const float4*>(&X[(size_t)(m0 + arow) * 1024 + k0 + acol]);
        As[(acol + 0) * 128 + arow] = av.x;
        As[(acol + 1) * 128 + arow] = av.y;
        As[(acol + 2) * 128 + arow] = av.z;
        As[(acol + 3) * 128 + arow] = av.w;
        float4 bv = *reinterpret_cast<const float4*>(&Bw[(size_t)(k0 + brow) * 1024 + n0 + bcol]);
        *reinterpret_cast<float4*>(&Bs[brow * 128 + bcol]) = bv;
        __syncthreads();

#pragma unroll
        for (int k = 0; k < 8; k++) {
            float regM[8], regN[8];
            *reinterpret_cast<float4*>(&regM[0]) = *reinterpret_cast<const float4*>(&As[k * 128 + tr]);
            *reinterpret_cast<float4*>(&regM[4]) = *reinterpret_cast<const float4*>(&As[k * 128 + tr + 4]);
            *reinterpret_cast<float4*>(&regN[0]) = *reinterpret_cast<const float4*>(&Bs[k * 128 + tc]);
            *reinterpret_cast<float4*>(&regN[4]) = *reinterpret_cast<const float4*>(&Bs[k * 128 + tc + 4]);
#pragma unroll
            for (int i = 0; i < 8; i++)
#pragma unroll
                for (int j = 0; j < 8; j++) acc[i][j] += regM[i] * regN[j];
        }
        __syncthreads();
    }

    float4 bv0 = *reinterpret_cast<const float4*>(&bias[n0 + tc]);
    float4 bv1 = *reinterpret_cast<const float4*>(&bias[n0 + tc + 4]);
#pragma unroll
    for (int i = 0; i < 8; i++) {
        size_t base = (size_t)(m0 + tr + i) * 3072 + (size_t)g * 1024 + n0 + tc;
        float4 o0 = make_float4(acc[i][0] + bv0.x, acc[i][1] + bv0.y,
                                acc[i][2] + bv0.z, acc[i][3] + bv0.w);
        float4 o1 = make_float4(acc[i][4] + bv1.x, acc[i][5] + bv1.y,
                                acc[i][6] + bv1.z, acc[i][7] + bv1.w);
        *reinterpret_cast<float4*>(&g_pre[base])     = o0;
        *reinterpret_cast<float4*>(&g_pre[base + 4]) = o1;
    }
}

// ---------------------------------------------------------------------------
// Skinny GEMM tile for the recurrent step:
//   acc[rows] += A(64x1024) @ Wt(rows n0..n0+CT-1, each 1024 contiguous)
//   RSIG: A element-wise replaced by sigmoid(Rpre)*A during the smem load.
// Thread map: col = tid%CT, rowgroup = tid/CT, RPT rows per thread.
// ---------------------------------------------------------------------------
template <int CT, int RPT, bool RSIG>
__device__ __forceinline__ void gemm_tile(const float* __restrict__ A,
                                          const float* __restrict__ Rpre,
                                          const float* __restrict__ Wt,
                                          int n0, float* acc, int tid,
                                          float* As /*32*68*/, float* Bs /*32*CT*/) {
    const int col  = tid % CT;
    const int rg   = tid / CT;
    const int row0 = rg * RPT;
    const int lr = tid >> 3;          // 0..31
    const int lc = (tid & 7) * 4;     // k offset within 32-chunk

    for (int k0 = 0; k0 < 1024; k0 += 32) {
        // --- load A chunk: 64 rows x 32 k, store transposed [k][row] (stride 68)
#pragma unroll
        for (int pass = 0; pass < 2; pass++) {
            int r = pass * 32 + lr;
            float4 v = *reinterpret_cast<const float4*>(&A[r * 1024 + k0 + lc]);
            if (RSIG) {
                float4 rv = *reinterpret_cast<const float4*>(&Rpre[r * 2048 + 1024 + k0 + lc]);
                v.x *= sigmoidf_(rv.x);
                v.y *= sigmoidf_(rv.y);
                v.z *= sigmoidf_(rv.z);
                v.w *= sigmoidf_(rv.w);
            }
            As[(lc + 0) * 68 + r] = v.x;
            As[(lc + 1) * 68 + r] = v.y;
            As[(lc + 2) * 68 + r] = v.z;
            As[(lc + 3) * 68 + r] = v.w;
        }
        // --- load W chunk: CT cols x 32 k, store [k][col]
        if (tid < CT * 8) {
            int wr = tid >> 3;
            int wc = (tid & 7) * 4;
            float4 v = *reinterpret_cast<const float4*>(&Wt[(n0 + wr) * 1024 + k0 + wc]);
            Bs[(wc + 0) * CT + wr] = v.x;
            Bs[(wc + 1) * CT + wr] = v.y;
            Bs[(wc + 2) * CT + wr] = v.z;
            Bs[(wc + 3) * CT + wr] = v.w;
        }
        __syncthreads();
#pragma unroll
        for (int kk = 0; kk < 32; kk++) {
            float bv = Bs[kk * CT + col];
            if (RPT == 4) {
                float4 a = *reinterpret_cast<const float4*>(&As[kk * 68 + row0]);
                acc[0] += a.x * bv;
                acc[1] += a.y * bv;
                acc[2] += a.z * bv;
                acc[3] += a.w * bv;
            } else {
                float2 a = *reinterpret_cast<const float2*>(&As[kk * 68 + row0]);
                acc[0] += a.x * bv;
                acc[1] += a.y * bv;
            }
        }
        __syncthreads();
    }
}

// ---------------------------------------------------------------------------
// Persistent recurrent kernel: 128 blocks x 256 threads, 512 steps.
// ---------------------------------------------------------------------------
__global__ void __launch_bounds__(256, 1) gru_recurrent(const float* __restrict__ bp,
                                                        float* __restrict__ out) {
    __shared__ float As[32 * 68];
    __shared__ float Bs[32 * 16];
    const int tid = threadIdx.x;
    const int bid = blockIdx.x;

    int p = 0;  // h lives in g_hbuf[p] at step start

#pragma unroll 1
    for (int t = 0; t < TT; t++) {
        const float* h = g_hbuf[p];

        // ---- phase 1: z_pre | r_pre (2048 cols, 16 per block) ----
        {
            const int n0 = bid * 16;
            float acc[4] = {0.f, 0.f, 0.f, 0.f};
            gemm_tile<16, 4, false>(h, nullptr, g_wt_zr, n0, acc, tid, As, Bs);
            const int col = tid % 16;
            const int rg  = tid / 16;
            const int c   = n0 + col;
#pragma unroll
            for (int i = 0; i < 4; i++) {
                int b = rg * 4 + i;
                g_zr[b * 2048 + c] = acc[i] + g_pre[(size_t)(b * TT + t) * 3072 + c];
            }
        }
        grid_barrier();

        // ---- phase 2: candidate + gate combine (1024 cols, 8 per block) ----
        {
            const int n0 = bid * 8;
            float acc[2] = {0.f, 0.f};
            gemm_tile<8, 2, true>(h, g_zr, g_wt_h, n0, acc, tid, As, Bs);
            const int col = tid % 8;
            const int rg  = tid / 8;
            const int c   = n0 + col;
            float* hnext = g_hbuf[1 - p];
#pragma unroll
            for (int i = 0; i < 2; i++) {
                int b = rg * 2 + i;
                float cand = tanhf(acc[i] + g_pre[(size_t)(b * TT + t) * 3072 + 2048 + c]);
                float z    = sigmoidf_(g_zr[b * 2048 + c]);
                float hold = h[b * 1024 + c];
                float hn   = (1.0f - z) * hold + z * cand;
                out[(size_t)(b * TT + t) * 1024 + c] = hn;
                hnext[b * 1024 + c] = hn;
            }
        }
        grid_barrier();

        // ---- phase 3: chunk-boundary projection ----
        const bool prop = ((t & 3) == 3) && (t != TT - 1);
        if (prop) {
            const float* hn = g_hbuf[1 - p];
            const int n0 = bid * 8;
            float acc[2] = {0.f, 0.f};
            gemm_tile<8, 2, false>(hn, nullptr, g_wt_p, n0, acc, tid, As, Bs);
            const int col = tid % 8;
            const int rg  = tid / 8;
            const int c   = n0 + col;
            float* hdst = g_hbuf[p];
#pragma unroll
            for (int i = 0; i < 2; i++) {
                int b = rg * 2 + i;
                hdst[b * 1024 + c] = tanhf(acc[i] + bp[c]);
            }
            grid_barrier();
            // h now back in g_hbuf[p]; p unchanged
        } else {
            p ^= 1;
        }
    }
}

// ---------------------------------------------------------------------------
extern "C" void kernel_launch(void* const* d_in, const int* in_sizes, int n_in,
                              void* d_out, int out_size) {
    (void)in_sizes; (void)n_in; (void)out_size;
    const float* x  = (const float*)d_in[0];
    const float* h0 = (const float*)d_in[1];
    const float* Wz = (const float*)d_in[2];
    const float* bz = (const float*)d_in[3];
    const float* Wr = (const float*)d_in[4];
    const float* br = (const float*)d_in[5];
    const float* Wh = (const float*)d_in[6];
    const float* bh = (const float*)d_in[7];
    const float* Wp = (const float*)d_in[8];
    const float* bp = (const float*)d_in[9];
    float* out = (float*)d_out;

    transpose_weights<<<dim3(32, 32, 4), dim3(32, 32)>>>(Wz, Wr, Wh, Wp);
    init_h<<<64, 1024>>>(h0);
    sgemm_pre<<<dim3(8, 256, 3), 256>>>(x, Wz, Wr, Wh, bz, br, bh);
    gru_recurrent<<<NB, 256>>>(bp, out);
}

// round 4
// speedup vs baseline: 2.4241x; 2.4241x over previous
#include <cuda_runtime.h>

// ---------------------------------------------------------------------------
// ChunkParallelGRU: B=64, T=512, D=1024, H=1024, CHUNK=4
//
//   pre[g][m][n] = x[m] @ Wg_x + bg                (big GEMM, parallel)
//   per step t (sequential, persistent kernel):
//     P1: zr = sigmoid(pre_zr + h @ Wzr_h)          (2048 cols / 128 blocks)
//     P2: cand = tanh(pre_h + (r*h) @ Wh_h);
//         h_new = h + z*(cand-h); out[t] = h_new    (1024 cols / 128 blocks)
//     P3 (chunk boundary): h = tanh(h_new @ Wp + bp)
//
// v2: weights SMEM-resident per block, 512 thr/block, double-buffered A tiles,
//     distributed-flag grid barrier, double-buffered sgemm_pre.
// ---------------------------------------------------------------------------

#define BB 64
#define TT 512
#define BT (BB * TT)
#define NB 128          // persistent grid (<=148 SMs -> co-resident)

// Scratch (static device arrays; allocation-free)
__device__ float g_pre[(size_t)BT * 3072];      // [m][z|r|h]
__device__ float g_wt_zr[2048 * 1024];          // transposed h-parts of Wz|Wr: [n][k]
__device__ float g_wt_h[1024 * 1024];           // transposed h-part of Wh
__device__ float g_wt_p[1024 * 1024];           // transposed Wp
__device__ float g_hbuf[2][BB * 1024];          // double-buffered state
__device__ float g_zr[BB * 2048];               // sigmoided z|r for current step
__device__ unsigned g_flags[NB];                // barrier arrival flags (epochs)

__device__ __forceinline__ float sig_(float x) {
    return 1.0f / (1.0f + __expf(-x));
}
__device__ __forceinline__ float tanh_(float x) {
    x = fminf(15.0f, fmaxf(-15.0f, x));
    float e = __expf(-2.0f * x);
    return (1.0f - e) / (1.0f + e);
}

// ---------------------------------------------------------------------------
// Grid barrier: distributed flags, monotonic epochs (reset kernel zeroes flags
// before each launch). Release: fence + flag store. Acquire: fence (CCTL.IVALL)
// after all flags observed.
// ---------------------------------------------------------------------------
__device__ __forceinline__ void grid_barrier(unsigned ep) {
    __syncthreads();
    if (threadIdx.x == 0) {
        __threadfence();
        asm volatile("st.global.cg.u32 [%0], %1;" :: "l"(&g_flags[blockIdx.x]), "r"(ep) : "memory");
    }
    if (threadIdx.x < NB / 4) {
        const uint4* pf = reinterpret_cast<const uint4*>(g_flags) + threadIdx.x;
        for (;;) {
            uint4 v;
            asm volatile("ld.global.cg.v4.u32 {%0,%1,%2,%3}, [%4];"
                         : "=r"(v.x), "=r"(v.y), "=r"(v.z), "=r"(v.w) : "l"(pf) : "memory");
            if (v.x >= ep && v.y >= ep && v.z >= ep && v.w >= ep) break;
            __nanosleep(64);
        }
    }
    __syncthreads();
    if (threadIdx.x == 0) __threadfence();   // invalidate L1 before cross-block reads
    __syncthreads();
}

__global__ void reset_flags() {
    if (threadIdx.x < NB) g_flags[threadIdx.x] = 0u;
}

// ---------------------------------------------------------------------------
// Weight transpose: dst[n][k] = src[srcOff + k][n]
// ---------------------------------------------------------------------------
__global__ void transpose_weights(const float* __restrict__ Wz,
                                  const float* __restrict__ Wr,
                                  const float* __restrict__ Wh,
                                  const float* __restrict__ Wp) {
    __shared__ float tile[32][33];
    const int z = blockIdx.z;
    const float* src; float* dst; int srcOff;
    if (z == 0)      { src = Wz; dst = g_wt_zr;               srcOff = 1024; }
    else if (z == 1) { src = Wr; dst = g_wt_zr + 1024 * 1024; srcOff = 1024; }
    else if (z == 2) { src = Wh; dst = g_wt_h;                srcOff = 1024; }
    else             { src = Wp; dst = g_wt_p;                srcOff = 0;    }
    const int kBase = blockIdx.x * 32;
    const int cBase = blockIdx.y * 32;
    tile[threadIdx.y][threadIdx.x] =
        src[(srcOff + kBase + threadIdx.y) * 1024 + cBase + threadIdx.x];
    __syncthreads();
    dst[(cBase + threadIdx.y) * 1024 + kBase + threadIdx.x] =
        tile[threadIdx.x][threadIdx.y];
}

__global__ void init_h(const float* __restrict__ h0) {
    int i = blockIdx.x * blockDim.x + threadIdx.x;
    if (i < BB * 1024) g_hbuf[0][i] = h0[i];
}

// ---------------------------------------------------------------------------
// Precompute GEMM (double-buffered 128x128x8 SGEMM, 256 thr, 8x8 microtiles)
// ---------------------------------------------------------------------------
__global__ void __launch_bounds__(256, 2) sgemm_pre(
    const float* __restrict__ X,
    const float* __restrict__ Wz, const float* __restrict__ Wr, const float* __restrict__ Wh,
    const float* __restrict__ bz, const float* __restrict__ br, const float* __restrict__ bh) {
    const int g = blockIdx.z;
    const float* Bw   = (g == 0) ? Wz : (g == 1) ? Wr : Wh;
    const float* bias = (g == 0) ? bz : (g == 1) ? br : bh;
    const int m0 = blockIdx.y * 128;
    const int n0 = blockIdx.x * 128;

    __shared__ float As[2][8 * 128];   // [k][m]
    __shared__ float Bs[2][8 * 128];   // [k][n]

    const int tid = threadIdx.x;
    const int tr = (tid / 16) * 8;
    const int tc = (tid % 16) * 8;

    const int arow = tid / 2;
    const int acol = (tid % 2) * 4;
    const int brow = tid / 32;
    const int bcol = (tid % 32) * 4;

    float acc[8][8];
#pragma unroll
    for (int i = 0; i < 8; i++)
#pragma unroll
        for (int j = 0; j < 8; j++) acc[i][j] = 0.0f;

    // initial chunk
    {
        float4 av = *reinterpret_cast<const float4*>(&X[(size_t)(m0 + arow) * 1024 + acol]);
        As[0][(acol + 0) * 128 + arow] = av.x;
        As[0][(acol + 1) * 128 + arow] = av.y;
        As[0][(acol + 2) * 128 + arow] = av.z;
        As[0][(acol + 3) * 128 + arow] = av.w;
        float4 bv = *reinterpret_cast<const float4*>(&Bw[(size_t)brow * 1024 + n0 + bcol]);
        *reinterpret_cast<float4*>(&Bs[0][brow * 128 + bcol]) = bv;
    }
    __syncthreads();

    int buf = 0;
#pragma unroll 1
    for (int k0 = 0; k0 < 1024; k0 += 8) {
        float4 av2, bv2;
        const bool hasNext = (k0 + 8 < 1024);
        if (hasNext) {
            av2 = *reinterpret_cast<const float4*>(&X[(size_t)(m0 + arow) * 1024 + k0 + 8 + acol]);
            bv2 = *reinterpret_cast<const float4*>(&Bw[(size_t)(k0 + 8 + brow) * 1024 + n0 + bcol]);
        }
#pragma unroll
        for (int k = 0; k < 8; k++) {
            float regM[8], regN[8];
            *reinterpret_cast<float4*>(&regM[0]) = *reinterpret_cast<const float4*>(&As[buf][k * 128 + tr]);
            *reinterpret_cast<float4*>(&regM[4]) = *reinterpret_cast<const float4*>(&As[buf][k * 128 + tr + 4]);
            *reinterpret_cast<float4*>(&regN[0]) = *reinterpret_cast<const float4*>(&Bs[buf][k * 128 + tc]);
            *reinterpret_cast<float4*>(&regN[4]) = *reinterpret_cast<const float4*>(&Bs[buf][k * 128 + tc + 4]);
#pragma unroll
            for (int i = 0; i < 8; i++)
#pragma unroll
                for (int j = 0; j < 8; j++) acc[i][j] += regM[i] * regN[j];
        }
        if (hasNext) {
            const int nb = buf ^ 1;
            As[nb][(acol + 0) * 128 + arow] = av2.x;
            As[nb][(acol + 1) * 128 + arow] = av2.y;
            As[nb][(acol + 2) * 128 + arow] = av2.z;
            As[nb][(acol + 3) * 128 + arow] = av2.w;
            *reinterpret_cast<float4*>(&Bs[nb][brow * 128 + bcol]) = bv2;
        }
        __syncthreads();
        buf ^= 1;
    }

    float4 bv0 = *reinterpret_cast<const float4*>(&bias[n0 + tc]);
    float4 bv1 = *reinterpret_cast<const float4*>(&bias[n0 + tc + 4]);
#pragma unroll
    for (int i = 0; i < 8; i++) {
        size_t base = (size_t)(m0 + tr + i) * 3072 + (size_t)g * 1024 + n0 + tc;
        float4 o0 = make_float4(acc[i][0] + bv0.x, acc[i][1] + bv0.y,
                                acc[i][2] + bv0.z, acc[i][3] + bv0.w);
        float4 o1 = make_float4(acc[i][4] + bv1.x, acc[i][5] + bv1.y,
                                acc[i][6] + bv1.z, acc[i][7] + bv1.w);
        *reinterpret_cast<float4*>(&g_pre[base])     = o0;
        *reinterpret_cast<float4*>(&g_pre[base + 4]) = o1;
    }
}

// ---------------------------------------------------------------------------
// Recurrent GEMM tile: acc[RPT] = A(64x1024) @ Ws(CT cols, SMEM-resident).
// A double-buffered in SMEM (2 x 64x128 chunks, padded stride 132).
// RSIG: A multiplied elementwise by sig(r) (already sigmoided in g_zr r-half).
// 512 threads. c = tid%CT, rows = (tid/CT)*RPT.
// ---------------------------------------------------------------------------
#define KC 128
#define AST 132                          // padded row stride (floats)
#define ABUF (64 * AST)                  // one A buffer

template <int CT, int RPT, bool RSIG>
__device__ __forceinline__ void rec_gemm(const float* __restrict__ A,
                                         const float* __restrict__ Rsig,
                                         const float* __restrict__ Ws,
                                         float* __restrict__ As,
                                         float* __restrict__ acc, int tid) {
    const int c  = tid % CT;
    const int rg = tid / CT;
    const int r0 = rg * RPT;
    float accB[RPT];
#pragma unroll
    for (int i = 0; i < RPT; i++) { acc[i] = 0.0f; accB[i] = 0.0f; }

    // preload chunk 0 (64 rows x 128 k = 2048 float4 / 512 thr = 4 passes)
#pragma unroll
    for (int p = 0; p < 4; p++) {
        int pos = p * 512 + tid;
        int row = pos >> 5, kq = (pos & 31) << 2;
        float4 v = *reinterpret_cast<const float4*>(&A[row * 1024 + kq]);
        if (RSIG) {
            float4 s = *reinterpret_cast<const float4*>(&Rsig[row * 2048 + 1024 + kq]);
            v.x *= s.x; v.y *= s.y; v.z *= s.z; v.w *= s.w;
        }
        *reinterpret_cast<float4*>(&As[row * AST + kq]) = v;
    }
    __syncthreads();

#pragma unroll 1
    for (int ch = 0; ch < 1024 / KC; ch++) {
        float4 nv[4];
        const bool hasNext = (ch < 1024 / KC - 1);
        if (hasNext) {
            const int kb = (ch + 1) << 7;
#pragma unroll
            for (int p = 0; p < 4; p++) {
                int pos = p * 512 + tid;
                int row = pos >> 5, kq = (pos & 31) << 2;
                float4 v = *reinterpret_cast<const float4*>(&A[row * 1024 + kb + kq]);
                if (RSIG) {
                    float4 s = *reinterpret_cast<const float4*>(&Rsig[row * 2048 + 1024 + kb + kq]);
                    v.x *= s.x; v.y *= s.y; v.z *= s.z; v.w *= s.w;
                }
                nv[p] = v;
            }
        }
        const float* wrow = Ws + c * 1028 + (ch << 7);
        const float* cur  = As + (ch & 1) * ABUF;
#pragma unroll
        for (int k4 = 0; k4 < KC; k4 += 4) {
            float4 w = *reinterpret_cast<const float4*>(&wrow[k4]);
#pragma unroll
            for (int i = 0; i < RPT; i++) {
                float4 a = *reinterpret_cast<const float4*>(&cur[(r0 + i) * AST + k4]);
                acc[i]  = fmaf(a.x, w.x, acc[i]);
                acc[i]  = fmaf(a.y, w.y, acc[i]);
                accB[i] = fmaf(a.z, w.z, accB[i]);
                accB[i] = fmaf(a.w, w.w, accB[i]);
            }
        }
        if (hasNext) {
            float* nxt = As + ((ch + 1) & 1) * ABUF;
#pragma unroll
            for (int p = 0; p < 4; p++) {
                int pos = p * 512 + tid;
                int row = pos >> 5, kq = (pos & 31) << 2;
                *reinterpret_cast<float4*>(&nxt[row * AST + kq]) = nv[p];
            }
        }
        __syncthreads();
    }
#pragma unroll
    for (int i = 0; i < RPT; i++) acc[i] += accB[i];
}

// SMEM layout (floats): Ws1[16][1028] | Ws2[8][1028] | Ws3[8][1028] | As[2][64*132]
#define OFF_WS1 0
#define OFF_WS2 (16 * 1028)
#define OFF_WS3 (24 * 1028)
#define OFF_AS  (32 * 1028)
#define SMEM_REC_FLOATS (OFF_AS + 2 * ABUF)
#define SMEM_REC_BYTES  (SMEM_REC_FLOATS * 4)

// ---------------------------------------------------------------------------
// Persistent recurrent kernel: 128 blocks x 512 threads, 512 steps.
// ---------------------------------------------------------------------------
__global__ void __launch_bounds__(512, 1) gru_recurrent(const float* __restrict__ bp,
                                                        float* __restrict__ out) {
    extern __shared__ float smem[];
    float* Ws1 = smem + OFF_WS1;
    float* Ws2 = smem + OFF_WS2;
    float* Ws3 = smem + OFF_WS3;
    float* As  = smem + OFF_AS;

    const int tid = threadIdx.x;
    const int bid = blockIdx.x;

    // Load this block's weight columns into SMEM once.
    for (int idx = tid; idx < 16 * 256; idx += 512) {   // Ws1: 16 cols x 256 float4
        int i = idx >> 8, kq = (idx & 255) << 2;
        float4 v = *reinterpret_cast<const float4*>(&g_wt_zr[(size_t)(bid * 16 + i) * 1024 + kq]);
        *reinterpret_cast<float4*>(&Ws1[i * 1028 + kq]) = v;
    }
    for (int idx = tid; idx < 8 * 256; idx += 512) {
        int i = idx >> 8, kq = (idx & 255) << 2;
        float4 v = *reinterpret_cast<const float4*>(&g_wt_h[(size_t)(bid * 8 + i) * 1024 + kq]);
        *reinterpret_cast<float4*>(&Ws2[i * 1028 + kq]) = v;
        float4 w = *reinterpret_cast<const float4*>(&g_wt_p[(size_t)(bid * 8 + i) * 1024 + kq]);
        *reinterpret_cast<float4*>(&Ws3[i * 1028 + kq]) = w;
    }
    __syncthreads();

    unsigned ep = 1;
    int p = 0;   // h lives in g_hbuf[p] at step start

#pragma unroll 1
    for (int t = 0; t < TT; t++) {
        const float* h = g_hbuf[p];

        // ---- phase 1: zr = sigmoid(pre_zr + h @ Wzr_h) ----
        {
            const int c  = tid & 15;
            const int rg = tid >> 4;          // 0..31
            const int cz = bid * 16 + c;      // 0..2047
            const int b0 = rg * 2;
            float pre0 = g_pre[(size_t)(b0 * TT + t) * 3072 + cz];
            float pre1 = g_pre[(size_t)((b0 + 1) * TT + t) * 3072 + cz];
            float acc[2];
            rec_gemm<16, 2, false>(h, nullptr, Ws1, As, acc, tid);
            g_zr[b0 * 2048 + cz]       = sig_(acc[0] + pre0);
            g_zr[(b0 + 1) * 2048 + cz] = sig_(acc[1] + pre1);
        }
        grid_barrier(ep++);

        // ---- phase 2: cand + gate combine ----
        float* hnext = g_hbuf[p ^ 1];
        {
            const int c  = tid & 7;
            const int b  = tid >> 3;          // 0..63
            const int c1 = bid * 8 + c;       // 0..1023
            float preh = g_pre[(size_t)(b * TT + t) * 3072 + 2048 + c1];
            float zv   = g_zr[b * 2048 + c1];         // already sigmoided
            float hold = h[b * 1024 + c1];
            float acc[1];
            rec_gemm<8, 1, true>(h, g_zr, Ws2, As, acc, tid);
            float cand = tanh_(acc[0] + preh);
            float hn = fmaf(zv, cand - hold, hold);
            out[(size_t)(b * TT + t) * 1024 + c1] = hn;
            hnext[b * 1024 + c1] = hn;
        }
        grid_barrier(ep++);

        // ---- phase 3: chunk-boundary projection ----
        const bool prop = ((t & 3) == 3) && (t != TT - 1);
        if (prop) {
            const int c  = tid & 7;
            const int b  = tid >> 3;
            const int c1 = bid * 8 + c;
            float bpv = bp[c1];
            float acc[1];
            rec_gemm<8, 1, false>(hnext, nullptr, Ws3, As, acc, tid);
            g_hbuf[p][b * 1024 + c1] = tanh_(acc[0] + bpv);
            grid_barrier(ep++);
            // h stays in g_hbuf[p]
        } else {
            p ^= 1;
        }
    }
}

// ---------------------------------------------------------------------------
extern "C" void kernel_launch(void* const* d_in, const int* in_sizes, int n_in,
                              void* d_out, int out_size) {
    (void)in_sizes; (void)n_in; (void)out_size;
    const float* x  = (const float*)d_in[0];
    const float* h0 = (const float*)d_in[1];
    const float* Wz = (const float*)d_in[2];
    const float* bz = (const float*)d_in[3];
    const float* Wr = (const float*)d_in[4];
    const float* br = (const float*)d_in[5];
    const float* Wh = (const float*)d_in[6];
    const float* bh = (const float*)d_in[7];
    const float* Wp = (const float*)d_in[8];
    const float* bp = (const float*)d_in[9];
    float* out = (float*)d_out;

    static bool attr_set = false;
    if (!attr_set) {
        cudaFuncSetAttribute(gru_recurrent, cudaFuncAttributeMaxDynamicSharedMemorySize,
                             SMEM_REC_BYTES);
        attr_set = true;
    }

    transpose_weights<<<dim3(32, 32, 4), dim3(32, 32)>>>(Wz, Wr, Wh, Wp);
    init_h<<<64, 1024>>>(h0);
    reset_flags<<<1, 128>>>();
    sgemm_pre<<<dim3(8, 256, 3), 256>>>(x, Wz, Wr, Wh, bz, br, bh);
    gru_recurrent<<<NB, 512, SMEM_REC_BYTES>>>(bp, out);
}

// round 5
// speedup vs baseline: 2.8365x; 1.1701x over previous
#include <cuda_runtime.h>

// ---------------------------------------------------------------------------
// ChunkParallelGRU: B=64, T=512, D=1024, H=1024, CHUNK=4
//
//   pre[g][m][n] = x[m] @ Wg_x + bg                (big GEMM, parallel)
//   per step t (sequential, persistent kernel):
//     P1: zr = sigmoid(pre_zr + h @ Wzr_h)          (2048 cols / 128 blocks)
//     P2: cand = tanh(pre_h + (r*h) @ Wh_h);
//         h_new = h + z*(cand-h); out[t] = h_new    (1024 cols / 128 blocks)
//     P3 (chunk boundary): h = tanh(h_new @ Wp + bp)
//
// v3: 256 thr/block with 2x2 register microtiles (bytes/FMA 6->3),
//     packed fma.rn.f32x2 everywhere, conflict-free smem layouts,
//     epilogue-operand prefetch, FFMA2 sgemm_pre.
// ---------------------------------------------------------------------------

#define BB 64
#define TT 512
#define BT (BB * TT)
#define NB 128          // persistent grid (<=148 SMs -> co-resident)
#define THR 256

typedef unsigned long long ull;

// Scratch (static device arrays; allocation-free)
__device__ float g_pre[(size_t)BT * 3072];      // [m][z|r|h]
__device__ float g_wt_zr[2048 * 1024];          // transposed h-parts of Wz|Wr: [n][k]
__device__ float g_wt_h[1024 * 1024];           // transposed h-part of Wh
__device__ float g_wt_p[1024 * 1024];           // transposed Wp
__device__ float g_hbuf[2][BB * 1024];          // double-buffered state
__device__ float g_zr[BB * 2048];               // sigmoided z|r for current step
__device__ unsigned g_flags[NB];                // barrier arrival flags (epochs)

__device__ __forceinline__ float sig_(float x) {
    return 1.0f / (1.0f + __expf(-x));
}
__device__ __forceinline__ float tanh_(float x) {
    x = fminf(15.0f, fmaxf(-15.0f, x));
    float e = __expf(-2.0f * x);
    return (1.0f - e) / (1.0f + e);
}

// packed fp32x2 FMA (Blackwell): d = a*b + d elementwise on 2 packed floats
__device__ __forceinline__ void ffma2(ull& d, ull a, ull b) {
    asm("fma.rn.f32x2 %0, %1, %2, %3;" : "=l"(d) : "l"(a), "l"(b), "l"(d));
}
__device__ __forceinline__ ull splat2(float x) {
    unsigned u = __float_as_uint(x);
    return (ull)u | ((ull)u << 32);
}
__device__ __forceinline__ float hsum2(ull u) {
    return __uint_as_float((unsigned)u) + __uint_as_float((unsigned)(u >> 32));
}

union U4 { float4 f; ull u[2]; };

// ---------------------------------------------------------------------------
// Grid barrier: distributed flags, monotonic epochs.
// ---------------------------------------------------------------------------
__device__ __forceinline__ void grid_barrier(unsigned ep) {
    __syncthreads();
    if (threadIdx.x == 0) {
        __threadfence();
        asm volatile("st.global.cg.u32 [%0], %1;" :: "l"(&g_flags[blockIdx.x]), "r"(ep) : "memory");
    }
    if (threadIdx.x < NB / 4) {
        const uint4* pf = reinterpret_cast<const uint4*>(g_flags) + threadIdx.x;
        for (;;) {
            uint4 v;
            asm volatile("ld.global.cg.v4.u32 {%0,%1,%2,%3}, [%4];"
                         : "=r"(v.x), "=r"(v.y), "=r"(v.z), "=r"(v.w) : "l"(pf) : "memory");
            if (v.x >= ep && v.y >= ep && v.z >= ep && v.w >= ep) break;
            __nanosleep(40);
        }
    }
    __syncthreads();
    if (threadIdx.x == 0) __threadfence();   // CCTL.IVALL: invalidate L1 before cross-block reads
    __syncthreads();
}

__global__ void reset_flags() {
    if (threadIdx.x < NB) g_flags[threadIdx.x] = 0u;
}

// ---------------------------------------------------------------------------
// Weight transpose: dst[n][k] = src[srcOff + k][n]
// ---------------------------------------------------------------------------
__global__ void transpose_weights(const float* __restrict__ Wz,
                                  const float* __restrict__ Wr,
                                  const float* __restrict__ Wh,
                                  const float* __restrict__ Wp) {
    __shared__ float tile[32][33];
    const int z = blockIdx.z;
    const float* src; float* dst; int srcOff;
    if (z == 0)      { src = Wz; dst = g_wt_zr;               srcOff = 1024; }
    else if (z == 1) { src = Wr; dst = g_wt_zr + 1024 * 1024; srcOff = 1024; }
    else if (z == 2) { src = Wh; dst = g_wt_h;                srcOff = 1024; }
    else             { src = Wp; dst = g_wt_p;                srcOff = 0;    }
    const int kBase = blockIdx.x * 32;
    const int cBase = blockIdx.y * 32;
    tile[threadIdx.y][threadIdx.x] =
        src[(srcOff + kBase + threadIdx.y) * 1024 + cBase + threadIdx.x];
    __syncthreads();
    dst[(cBase + threadIdx.y) * 1024 + kBase + threadIdx.x] =
        tile[threadIdx.x][threadIdx.y];
}

__global__ void init_h(const float* __restrict__ h0) {
    int i = blockIdx.x * blockDim.x + threadIdx.x;
    if (i < BB * 1024) g_hbuf[0][i] = h0[i];
}

// ---------------------------------------------------------------------------
// Precompute GEMM (double-buffered 128x128x8, 256 thr, 8x8 microtiles, FFMA2)
// ---------------------------------------------------------------------------
__global__ void __launch_bounds__(256, 2) sgemm_pre(
    const float* __restrict__ X,
    const float* __restrict__ Wz, const float* __restrict__ Wr, const float* __restrict__ Wh,
    const float* __restrict__ bz, const float* __restrict__ br, const float* __restrict__ bh) {
    const int g = blockIdx.z;
    const float* Bw   = (g == 0) ? Wz : (g == 1) ? Wr : Wh;
    const float* bias = (g == 0) ? bz : (g == 1) ? br : bh;
    const int m0 = blockIdx.y * 128;
    const int n0 = blockIdx.x * 128;

    __shared__ float As[2][8 * 128];   // [k][m]
    __shared__ float Bs[2][8 * 128];   // [k][n]

    const int tid = threadIdx.x;
    const int tr = (tid / 16) * 8;
    const int tc = (tid % 16) * 8;

    const int arow = tid / 2;
    const int acol = (tid % 2) * 4;
    const int brow = tid / 32;
    const int bcol = (tid % 32) * 4;

    ull acc2[8][4];
#pragma unroll
    for (int i = 0; i < 8; i++)
#pragma unroll
        for (int j = 0; j < 4; j++) acc2[i][j] = 0ull;

    {
        float4 av = *reinterpret_cast<const float4*>(&X[(size_t)(m0 + arow) * 1024 + acol]);
        As[0][(acol + 0) * 128 + arow] = av.x;
        As[0][(acol + 1) * 128 + arow] = av.y;
        As[0][(acol + 2) * 128 + arow] = av.z;
        As[0][(acol + 3) * 128 + arow] = av.w;
        float4 bv = *reinterpret_cast<const float4*>(&Bw[(size_t)brow * 1024 + n0 + bcol]);
        *reinterpret_cast<float4*>(&Bs[0][brow * 128 + bcol]) = bv;
    }
    __syncthreads();

    int buf = 0;
#pragma unroll 1
    for (int k0 = 0; k0 < 1024; k0 += 8) {
        float4 av2, bv2;
        const bool hasNext = (k0 + 8 < 1024);
        if (hasNext) {
            av2 = *reinterpret_cast<const float4*>(&X[(size_t)(m0 + arow) * 1024 + k0 + 8 + acol]);
            bv2 = *reinterpret_cast<const float4*>(&Bw[(size_t)(k0 + 8 + brow) * 1024 + n0 + bcol]);
        }
#pragma unroll
        for (int k = 0; k < 8; k++) {
            float regM[8];
            U4 n0v, n1v;
            *reinterpret_cast<float4*>(&regM[0]) = *reinterpret_cast<const float4*>(&As[buf][k * 128 + tr]);
            *reinterpret_cast<float4*>(&regM[4]) = *reinterpret_cast<const float4*>(&As[buf][k * 128 + tr + 4]);
            n0v.f = *reinterpret_cast<const float4*>(&Bs[buf][k * 128 + tc]);
            n1v.f = *reinterpret_cast<const float4*>(&Bs[buf][k * 128 + tc + 4]);
#pragma unroll
            for (int i = 0; i < 8; i++) {
                ull mm = splat2(regM[i]);
                ffma2(acc2[i][0], mm, n0v.u[0]);
                ffma2(acc2[i][1], mm, n0v.u[1]);
                ffma2(acc2[i][2], mm, n1v.u[0]);
                ffma2(acc2[i][3], mm, n1v.u[1]);
            }
        }
        if (hasNext) {
            const int nb = buf ^ 1;
            As[nb][(acol + 0) * 128 + arow] = av2.x;
            As[nb][(acol + 1) * 128 + arow] = av2.y;
            As[nb][(acol + 2) * 128 + arow] = av2.z;
            As[nb][(acol + 3) * 128 + arow] = av2.w;
            *reinterpret_cast<float4*>(&Bs[nb][brow * 128 + bcol]) = bv2;
        }
        __syncthreads();
        buf ^= 1;
    }

    float4 bv0 = *reinterpret_cast<const float4*>(&bias[n0 + tc]);
    float4 bv1 = *reinterpret_cast<const float4*>(&bias[n0 + tc + 4]);
#pragma unroll
    for (int i = 0; i < 8; i++) {
        size_t base = (size_t)(m0 + tr + i) * 3072 + (size_t)g * 1024 + n0 + tc;
        float4 o0 = make_float4(__uint_as_float((unsigned)acc2[i][0])         + bv0.x,
                                __uint_as_float((unsigned)(acc2[i][0] >> 32)) + bv0.y,
                                __uint_as_float((unsigned)acc2[i][1])         + bv0.z,
                                __uint_as_float((unsigned)(acc2[i][1] >> 32)) + bv0.w);
        float4 o1 = make_float4(__uint_as_float((unsigned)acc2[i][2])         + bv1.x,
                                __uint_as_float((unsigned)(acc2[i][2] >> 32)) + bv1.y,
                                __uint_as_float((unsigned)acc2[i][3])         + bv1.z,
                                __uint_as_float((unsigned)(acc2[i][3] >> 32)) + bv1.w);
        *reinterpret_cast<float4*>(&g_pre[base])     = o0;
        *reinterpret_cast<float4*>(&g_pre[base + 4]) = o1;
    }
}

// ---------------------------------------------------------------------------
// Recurrent GEMM tile: 256 threads, microtile 2 rows x TN cols.
//   cp = tid%8; cols = {cp, cp+8} (TN=2) or {cp} (TN=1)   [xWS stride keeps
//   LDS conflict-free: bank(col)=4*col mod 32, distinct for cp and cp+8]
//   rp = tid>>3 (0..31); rows = {2rp, 2rp+1}
// A (64x1024) streamed gmem->smem in K=128 chunks, double buffered (reg prefetch).
// W (smem-resident, stride 1028) read directly in inner loop.
// RSIG: A multiplied elementwise by sigmoided r from g_zr during staging.
// out[i*TN+j] = acc for row i, col j.
// ---------------------------------------------------------------------------
#define KC 128
#define AST 132
#define ABUF (64 * AST)
#define WST 1028

template <int TN, bool RSIG>
__device__ __forceinline__ void rec_gemm(const float* __restrict__ A,
                                         const float* __restrict__ Rsig,
                                         const float* __restrict__ Ws,
                                         float* __restrict__ As,
                                         float* __restrict__ out, int tid) {
    const int cp = tid & 7;
    const int rp = tid >> 3;
    ull acc[2][TN][2];
#pragma unroll
    for (int i = 0; i < 2; i++)
#pragma unroll
        for (int j = 0; j < TN; j++) { acc[i][j][0] = 0ull; acc[i][j][1] = 0ull; }

    // stage chunk 0: 64 rows x 128 k = 2048 float4 / 256 thr = 8 passes
#pragma unroll
    for (int p = 0; p < 8; p++) {
        int pos = p * 256 + tid;
        int row = pos >> 5, kq = (pos & 31) << 2;
        float4 v = *reinterpret_cast<const float4*>(&A[row * 1024 + kq]);
        if (RSIG) {
            float4 s = *reinterpret_cast<const float4*>(&Rsig[row * 2048 + 1024 + kq]);
            v.x *= s.x; v.y *= s.y; v.z *= s.z; v.w *= s.w;
        }
        *reinterpret_cast<float4*>(&As[row * AST + kq]) = v;
    }
    __syncthreads();

#pragma unroll 1
    for (int ch = 0; ch < 1024 / KC; ch++) {
        float4 nv[8];
        const bool hasNext = (ch < 1024 / KC - 1);
        if (hasNext) {
            const int kb = (ch + 1) << 7;
#pragma unroll
            for (int p = 0; p < 8; p++) {
                int pos = p * 256 + tid;
                int row = pos >> 5, kq = (pos & 31) << 2;
                float4 v = *reinterpret_cast<const float4*>(&A[row * 1024 + kb + kq]);
                if (RSIG) {
                    float4 s = *reinterpret_cast<const float4*>(&Rsig[row * 2048 + 1024 + kb + kq]);
                    v.x *= s.x; v.y *= s.y; v.z *= s.z; v.w *= s.w;
                }
                nv[p] = v;
            }
        }
        const float* cur = As + (ch & 1) * ABUF;
        const float* w0p = Ws + cp * WST + (ch << 7);
        const float* w1p = Ws + (cp + 8) * WST + (ch << 7);
        const float* a0p = cur + (2 * rp) * AST;
        const float* a1p = a0p + AST;
#pragma unroll
        for (int k4 = 0; k4 < KC; k4 += 4) {
            U4 a0, a1, w0;
            a0.f = *reinterpret_cast<const float4*>(a0p + k4);
            a1.f = *reinterpret_cast<const float4*>(a1p + k4);
            w0.f = *reinterpret_cast<const float4*>(w0p + k4);
            ffma2(acc[0][0][0], a0.u[0], w0.u[0]);
            ffma2(acc[0][0][1], a0.u[1], w0.u[1]);
            ffma2(acc[1][0][0], a1.u[0], w0.u[0]);
            ffma2(acc[1][0][1], a1.u[1], w0.u[1]);
            if (TN == 2) {
                U4 w1;
                w1.f = *reinterpret_cast<const float4*>(w1p + k4);
                ffma2(acc[0][1][0], a0.u[0], w1.u[0]);
                ffma2(acc[0][1][1], a0.u[1], w1.u[1]);
                ffma2(acc[1][1][0], a1.u[0], w1.u[0]);
                ffma2(acc[1][1][1], a1.u[1], w1.u[1]);
            }
        }
        if (hasNext) {
            float* nxt = As + ((ch + 1) & 1) * ABUF;
#pragma unroll
            for (int p = 0; p < 8; p++) {
                int pos = p * 256 + tid;
                int row = pos >> 5, kq = (pos & 31) << 2;
                *reinterpret_cast<float4*>(&nxt[row * AST + kq]) = nv[p];
            }
        }
        __syncthreads();
    }
#pragma unroll
    for (int i = 0; i < 2; i++)
#pragma unroll
        for (int j = 0; j < TN; j++)
            out[i * TN + j] = hsum2(acc[i][j][0]) + hsum2(acc[i][j][1]);
}

// SMEM layout (floats): Ws1[16][1028] | Ws2[8][1028] | Ws3[8][1028] | As[2][64*132]
#define OFF_WS1 0
#define OFF_WS2 (16 * WST)
#define OFF_WS3 (24 * WST)
#define OFF_AS  (32 * WST)
#define SMEM_REC_FLOATS (OFF_AS + 2 * ABUF)
#define SMEM_REC_BYTES  (SMEM_REC_FLOATS * 4)

// ---------------------------------------------------------------------------
// Persistent recurrent kernel: 128 blocks x 256 threads, 512 steps.
// ---------------------------------------------------------------------------
__global__ void __launch_bounds__(THR, 1) gru_recurrent(const float* __restrict__ bp,
                                                        float* __restrict__ out) {
    extern __shared__ float smem[];
    float* Ws1 = smem + OFF_WS1;
    float* Ws2 = smem + OFF_WS2;
    float* Ws3 = smem + OFF_WS3;
    float* As  = smem + OFF_AS;

    const int tid = threadIdx.x;
    const int bid = blockIdx.x;
    const int cp  = tid & 7;
    const int rp  = tid >> 3;
    const int b0  = 2 * rp, b1 = 2 * rp + 1;

    // Load this block's weight columns into SMEM once.
    for (int idx = tid; idx < 16 * 256; idx += THR) {   // Ws1: 16 cols x 256 float4
        int i = idx >> 8, kq = (idx & 255) << 2;
        float4 v = *reinterpret_cast<const float4*>(&g_wt_zr[(size_t)(bid * 16 + i) * 1024 + kq]);
        *reinterpret_cast<float4*>(&Ws1[i * WST + kq]) = v;
    }
    for (int idx = tid; idx < 8 * 256; idx += THR) {
        int i = idx >> 8, kq = (idx & 255) << 2;
        float4 v = *reinterpret_cast<const float4*>(&g_wt_h[(size_t)(bid * 8 + i) * 1024 + kq]);
        *reinterpret_cast<float4*>(&Ws2[i * WST + kq]) = v;
        float4 w = *reinterpret_cast<const float4*>(&g_wt_p[(size_t)(bid * 8 + i) * 1024 + kq]);
        *reinterpret_cast<float4*>(&Ws3[i * WST + kq]) = w;
    }
    __syncthreads();

    const float bpv = bp[bid * 8 + cp];   // phase-3 bias for this thread's column
    unsigned ep = 1;
    int p = 0;   // h lives in g_hbuf[p] at step start

#pragma unroll 1
    for (int t = 0; t < TT; t++) {
        const float* h = g_hbuf[p];

        // ---- phase 1: zr = sigmoid(pre_zr + h @ Wzr_h) ----
        {
            const int c0 = (bid << 4) + cp;
            const int c1 = c0 + 8;
            // prefetch epilogue operands (DRAM latency hidden under GEMM)
            float p00 = g_pre[(size_t)(b0 * TT + t) * 3072 + c0];
            float p01 = g_pre[(size_t)(b0 * TT + t) * 3072 + c1];
            float p10 = g_pre[(size_t)(b1 * TT + t) * 3072 + c0];
            float p11 = g_pre[(size_t)(b1 * TT + t) * 3072 + c1];
            float s[4];
            rec_gemm<2, false>(h, nullptr, Ws1, As, s, tid);
            g_zr[b0 * 2048 + c0] = sig_(s[0] + p00);
            g_zr[b0 * 2048 + c1] = sig_(s[1] + p01);
            g_zr[b1 * 2048 + c0] = sig_(s[2] + p10);
            g_zr[b1 * 2048 + c1] = sig_(s[3] + p11);
        }
        grid_barrier(ep++);

        // ---- phase 2: cand + gate combine ----
        float* hnext = g_hbuf[p ^ 1];
        {
            const int c = (bid << 3) + cp;
            float ph0 = g_pre[(size_t)(b0 * TT + t) * 3072 + 2048 + c];
            float ph1 = g_pre[(size_t)(b1 * TT + t) * 3072 + 2048 + c];
            float z0  = g_zr[b0 * 2048 + c];
            float z1  = g_zr[b1 * 2048 + c];
            float h0v = h[b0 * 1024 + c];
            float h1v = h[b1 * 1024 + c];
            float s[2];
            rec_gemm<1, true>(h, g_zr, Ws2, As, s, tid);
            float hn0 = fmaf(z0, tanh_(s[0] + ph0) - h0v, h0v);
            float hn1 = fmaf(z1, tanh_(s[1] + ph1) - h1v, h1v);
            out[(size_t)(b0 * TT + t) * 1024 + c] = hn0;
            out[(size_t)(b1 * TT + t) * 1024 + c] = hn1;
            hnext[b0 * 1024 + c] = hn0;
            hnext[b1 * 1024 + c] = hn1;
        }
        grid_barrier(ep++);

        // ---- phase 3: chunk-boundary projection ----
        const bool prop = ((t & 3) == 3) && (t != TT - 1);
        if (prop) {
            const int c = (bid << 3) + cp;
            float s[2];
            rec_gemm<1, false>(hnext, nullptr, Ws3, As, s, tid);
            g_hbuf[p][b0 * 1024 + c] = tanh_(s[0] + bpv);
            g_hbuf[p][b1 * 1024 + c] = tanh_(s[1] + bpv);
            grid_barrier(ep++);
            // h stays in g_hbuf[p]
        } else {
            p ^= 1;
        }
    }
}

// ---------------------------------------------------------------------------
extern "C" void kernel_launch(void* const* d_in, const int* in_sizes, int n_in,
                              void* d_out, int out_size) {
    (void)in_sizes; (void)n_in; (void)out_size;
    const float* x  = (const float*)d_in[0];
    const float* h0 = (const float*)d_in[1];
    const float* Wz = (const float*)d_in[2];
    const float* bz = (const float*)d_in[3];
    const float* Wr = (const float*)d_in[4];
    const float* br = (const float*)d_in[5];
    const float* Wh = (const float*)d_in[6];
    const float* bh = (const float*)d_in[7];
    const float* Wp = (const float*)d_in[8];
    const float* bp = (const float*)d_in[9];
    float* out = (float*)d_out;

    static bool attr_set = false;
    if (!attr_set) {
        cudaFuncSetAttribute(gru_recurrent, cudaFuncAttributeMaxDynamicSharedMemorySize,
                             SMEM_REC_BYTES);
        attr_set = true;
    }

    transpose_weights<<<dim3(32, 32, 4), dim3(32, 32)>>>(Wz, Wr, Wh, Wp);
    init_h<<<64, 1024>>>(h0);
    reset_flags<<<1, 128>>>();
    sgemm_pre<<<dim3(8, 256, 3), 256>>>(x, Wz, Wr, Wh, bz, br, bh);
    gru_recurrent<<<NB, THR, SMEM_REC_BYTES>>>(bp, out);
}

// round 6
// speedup vs baseline: 3.0396x; 1.0716x over previous
#include <cuda_runtime.h>

// ---------------------------------------------------------------------------
// ChunkParallelGRU: B=64, T=512, D=1024, H=1024, CHUNK=4
//
//   pre[g][m][n] = x[m] @ Wg_x + bg                (big GEMM, parallel)
//   per step t (sequential, persistent kernel):
//     P1: zr = sigmoid(pre_zr + h @ Wzr_h)          (2048 cols / 128 blocks)
//     P2: cand = tanh(pre_h + (r*h) @ Wh_h);
//         h_new = h + z*(cand-h); out[t] = h_new    (1024 cols / 128 blocks)
//     P3 (chunk boundary): h = tanh(h_new @ Wp + bp)
//
// v4: latency-stall attack — lean release/acquire counter barrier (1 poller,
//     no L1 flush), all cross-block data via .cg, 512 thr/block.
// ---------------------------------------------------------------------------

#define BB 64
#define TT 512
#define BT (BB * TT)
#define NB 128          // persistent grid (<=148 SMs -> co-resident)
#define THR 512

typedef unsigned long long ull;

// Scratch (static device arrays; allocation-free)
__device__ float g_pre[(size_t)BT * 3072];      // [m][z|r|h]
__device__ float g_wt_zr[2048 * 1024];          // transposed h-parts of Wz|Wr: [n][k]
__device__ float g_wt_h[1024 * 1024];           // transposed h-part of Wh
__device__ float g_wt_p[1024 * 1024];           // transposed Wp
__device__ float g_hbuf[2][BB * 1024];          // double-buffered state
__device__ float g_zr[BB * 2048];               // sigmoided z|r for current step
__device__ unsigned g_ctr;                      // barrier arrival counter (monotonic)

__device__ __forceinline__ float sig_(float x) {
    return 1.0f / (1.0f + __expf(-x));
}
__device__ __forceinline__ float tanh_(float x) {
    x = fminf(15.0f, fmaxf(-15.0f, x));
    float e = __expf(-2.0f * x);
    return (1.0f - e) / (1.0f + e);
}

// packed fp32x2 FMA: d = a*b + d elementwise (same MAC rate as FFMA, half the
// issue slots -- used to free issue bandwidth, not for rate)
__device__ __forceinline__ void ffma2(ull& d, ull a, ull b) {
    asm("fma.rn.f32x2 %0, %1, %2, %3;" : "=l"(d) : "l"(a), "l"(b), "l"(d));
}
__device__ __forceinline__ float hsum2(ull u) {
    return __uint_as_float((unsigned)u) + __uint_as_float((unsigned)(u >> 32));
}

union U4 { float4 f; ull u[2]; };

// ---------------------------------------------------------------------------
// Grid barrier v3: single monotonic counter. Arrive: red.release.gpu (orders
// this block's prior .cg stores). Wait: ONE poller with ld.acquire.gpu.
// No __threadfence, no L1 flush (all cross-block data uses .cg ops).
// ---------------------------------------------------------------------------
__device__ __forceinline__ void grid_barrier(unsigned ep) {
    __syncthreads();
    if (threadIdx.x == 0) {
        asm volatile("red.release.gpu.global.add.u32 [%0], 1;"
                     :: "l"(&g_ctr) : "memory");
        const unsigned target = ep * NB;
        unsigned v;
        do {
            asm volatile("ld.acquire.gpu.global.u32 %0, [%1];"
                         : "=r"(v) : "l"(&g_ctr) : "memory");
        } while ((int)(v - target) < 0);
    }
    __syncthreads();
}

__global__ void reset_ctr() {
    if (threadIdx.x == 0) g_ctr = 0u;
}

// ---------------------------------------------------------------------------
// Weight transpose: dst[n][k] = src[srcOff + k][n]
// ---------------------------------------------------------------------------
__global__ void transpose_weights(const float* __restrict__ Wz,
                                  const float* __restrict__ Wr,
                                  const float* __restrict__ Wh,
                                  const float* __restrict__ Wp) {
    __shared__ float tile[32][33];
    const int z = blockIdx.z;
    const float* src; float* dst; int srcOff;
    if (z == 0)      { src = Wz; dst = g_wt_zr;               srcOff = 1024; }
    else if (z == 1) { src = Wr; dst = g_wt_zr + 1024 * 1024; srcOff = 1024; }
    else if (z == 2) { src = Wh; dst = g_wt_h;                srcOff = 1024; }
    else             { src = Wp; dst = g_wt_p;                srcOff = 0;    }
    const int kBase = blockIdx.x * 32;
    const int cBase = blockIdx.y * 32;
    tile[threadIdx.y][threadIdx.x] =
        src[(srcOff + kBase + threadIdx.y) * 1024 + cBase + threadIdx.x];
    __syncthreads();
    dst[(cBase + threadIdx.y) * 1024 + kBase + threadIdx.x] =
        tile[threadIdx.x][threadIdx.y];
}

__global__ void init_h(const float* __restrict__ h0) {
    int i = blockIdx.x * blockDim.x + threadIdx.x;
    if (i < BB * 1024) g_hbuf[0][i] = h0[i];
}

// ---------------------------------------------------------------------------
// Precompute GEMM (double-buffered 128x128x8, 256 thr, 8x8 microtiles)
// ---------------------------------------------------------------------------
__global__ void __launch_bounds__(256, 2) sgemm_pre(
    const float* __restrict__ X,
    const float* __restrict__ Wz, const float* __restrict__ Wr, const float* __restrict__ Wh,
    const float* __restrict__ bz, const float* __restrict__ br, const float* __restrict__ bh) {
    const int g = blockIdx.z;
    const float* Bw   = (g == 0) ? Wz : (g == 1) ? Wr : Wh;
    const float* bias = (g == 0) ? bz : (g == 1) ? br : bh;
    const int m0 = blockIdx.y * 128;
    const int n0 = blockIdx.x * 128;

    __shared__ float As[2][8 * 128];   // [k][m]
    __shared__ float Bs[2][8 * 128];   // [k][n]

    const int tid = threadIdx.x;
    const int tr = (tid / 16) * 8;
    const int tc = (tid % 16) * 8;

    const int arow = tid / 2;
    const int acol = (tid % 2) * 4;
    const int brow = tid / 32;
    const int bcol = (tid % 32) * 4;

    ull acc2[8][4];
#pragma unroll
    for (int i = 0; i < 8; i++)
#pragma unroll
        for (int j = 0; j < 4; j++) acc2[i][j] = 0ull;

    {
        float4 av = *reinterpret_cast<const float4*>(&X[(size_t)(m0 + arow) * 1024 + acol]);
        As[0][(acol + 0) * 128 + arow] = av.x;
        As[0][(acol + 1) * 128 + arow] = av.y;
        As[0][(acol + 2) * 128 + arow] = av.z;
        As[0][(acol + 3) * 128 + arow] = av.w;
        float4 bv = *reinterpret_cast<const float4*>(&Bw[(size_t)brow * 1024 + n0 + bcol]);
        *reinterpret_cast<float4*>(&Bs[0][brow * 128 + bcol]) = bv;
    }
    __syncthreads();

    int buf = 0;
#pragma unroll 1
    for (int k0 = 0; k0 < 1024; k0 += 8) {
        float4 av2, bv2;
        const bool hasNext = (k0 + 8 < 1024);
        if (hasNext) {
            av2 = *reinterpret_cast<const float4*>(&X[(size_t)(m0 + arow) * 1024 + k0 + 8 + acol]);
            bv2 = *reinterpret_cast<const float4*>(&Bw[(size_t)(k0 + 8 + brow) * 1024 + n0 + bcol]);
        }
#pragma unroll
        for (int k = 0; k < 8; k++) {
            float regM[8];
            U4 n0v, n1v;
            *reinterpret_cast<float4*>(&regM[0]) = *reinterpret_cast<const float4*>(&As[buf][k * 128 + tr]);
            *reinterpret_cast<float4*>(&regM[4]) = *reinterpret_cast<const float4*>(&As[buf][k * 128 + tr + 4]);
            n0v.f = *reinterpret_cast<const float4*>(&Bs[buf][k * 128 + tc]);
            n1v.f = *reinterpret_cast<const float4*>(&Bs[buf][k * 128 + tc + 4]);
#pragma unroll
            for (int i = 0; i < 8; i++) {
                unsigned mu = __float_as_uint(regM[i]);
                ull mm = (ull)mu | ((ull)mu << 32);
                ffma2(acc2[i][0], mm, n0v.u[0]);
                ffma2(acc2[i][1], mm, n0v.u[1]);
                ffma2(acc2[i][2], mm, n1v.u[0]);
                ffma2(acc2[i][3], mm, n1v.u[1]);
            }
        }
        if (hasNext) {
            const int nb = buf ^ 1;
            As[nb][(acol + 0) * 128 + arow] = av2.x;
            As[nb][(acol + 1) * 128 + arow] = av2.y;
            As[nb][(acol + 2) * 128 + arow] = av2.z;
            As[nb][(acol + 3) * 128 + arow] = av2.w;
            *reinterpret_cast<float4*>(&Bs[nb][brow * 128 + bcol]) = bv2;
        }
        __syncthreads();
        buf ^= 1;
    }

    float4 bv0 = *reinterpret_cast<const float4*>(&bias[n0 + tc]);
    float4 bv1 = *reinterpret_cast<const float4*>(&bias[n0 + tc + 4]);
#pragma unroll
    for (int i = 0; i < 8; i++) {
        size_t base = (size_t)(m0 + tr + i) * 3072 + (size_t)g * 1024 + n0 + tc;
        float4 o0 = make_float4(__uint_as_float((unsigned)acc2[i][0])         + bv0.x,
                                __uint_as_float((unsigned)(acc2[i][0] >> 32)) + bv0.y,
                                __uint_as_float((unsigned)acc2[i][1])         + bv0.z,
                                __uint_as_float((unsigned)(acc2[i][1] >> 32)) + bv0.w);
        float4 o1 = make_float4(__uint_as_float((unsigned)acc2[i][2])         + bv1.x,
                                __uint_as_float((unsigned)(acc2[i][2] >> 32)) + bv1.y,
                                __uint_as_float((unsigned)acc2[i][3])         + bv1.z,
                                __uint_as_float((unsigned)(acc2[i][3] >> 32)) + bv1.w);
        *reinterpret_cast<float4*>(&g_pre[base])     = o0;
        *reinterpret_cast<float4*>(&g_pre[base + 4]) = o1;
    }
}

// ---------------------------------------------------------------------------
// Recurrent GEMM: 512 threads. Thread computes NR rows x 1 col (col's W column
// is SMEM-resident, k-contiguous, passed as Wcol). A (64x1024) staged from
// gmem (.cg) to smem in K=128 double-buffered chunks, row-major stride 132.
// RSIG: A multiplied by sigmoided r (g_zr r-half) during staging.
// k-packed FFMA2 accumulators (no splats); hsum at the end.
// ---------------------------------------------------------------------------
#define KC 128
#define AST 132
#define ABUF (64 * AST)
#define WST 1028

template <int NR, bool RSIG>
__device__ __forceinline__ void rec_gemm(const float* __restrict__ A,
                                         const float* __restrict__ Rsig,
                                         const float* __restrict__ Wcol,
                                         float* __restrict__ As,
                                         int r0, float* __restrict__ outv, int tid) {
    ull acc[NR][2];
#pragma unroll
    for (int i = 0; i < NR; i++) { acc[i][0] = 0ull; acc[i][1] = 0ull; }

    // stage chunk 0: 64 rows x 128 k = 2048 float4 / 512 thr = 4 passes
#pragma unroll
    for (int p = 0; p < 4; p++) {
        int pos = p * 512 + tid;
        int row = pos >> 5, kq = (pos & 31) << 2;
        float4 v = __ldcg(reinterpret_cast<const float4*>(&A[row * 1024 + kq]));
        if (RSIG) {
            float4 s = __ldcg(reinterpret_cast<const float4*>(&Rsig[row * 2048 + 1024 + kq]));
            v.x *= s.x; v.y *= s.y; v.z *= s.z; v.w *= s.w;
        }
        *reinterpret_cast<float4*>(&As[row * AST + kq]) = v;
    }
    __syncthreads();

#pragma unroll 1
    for (int ch = 0; ch < 1024 / KC; ch++) {
        float4 nv[4];
        const bool hasNext = (ch < 1024 / KC - 1);
        if (hasNext) {
            const int kb = (ch + 1) << 7;
#pragma unroll
            for (int p = 0; p < 4; p++) {
                int pos = p * 512 + tid;
                int row = pos >> 5, kq = (pos & 31) << 2;
                float4 v = __ldcg(reinterpret_cast<const float4*>(&A[row * 1024 + kb + kq]));
                if (RSIG) {
                    float4 s = __ldcg(reinterpret_cast<const float4*>(&Rsig[row * 2048 + 1024 + kb + kq]));
                    v.x *= s.x; v.y *= s.y; v.z *= s.z; v.w *= s.w;
                }
                nv[p] = v;
            }
        }
        const float* cur = As + (ch & 1) * ABUF;
        const float* wp  = Wcol + (ch << 7);
        const float* ap  = cur + r0 * AST;
#pragma unroll
        for (int k4 = 0; k4 < KC; k4 += 4) {
            U4 w;
            w.f = *reinterpret_cast<const float4*>(wp + k4);
#pragma unroll
            for (int i = 0; i < NR; i++) {
                U4 a;
                a.f = *reinterpret_cast<const float4*>(ap + i * AST + k4);
                ffma2(acc[i][0], a.u[0], w.u[0]);
                ffma2(acc[i][1], a.u[1], w.u[1]);
            }
        }
        if (hasNext) {
            float* nxt = As + ((ch + 1) & 1) * ABUF;
#pragma unroll
            for (int p = 0; p < 4; p++) {
                int pos = p * 512 + tid;
                int row = pos >> 5, kq = (pos & 31) << 2;
                *reinterpret_cast<float4*>(&nxt[row * AST + kq]) = nv[p];
            }
        }
        __syncthreads();
    }
#pragma unroll
    for (int i = 0; i < NR; i++) outv[i] = hsum2(acc[i][0]) + hsum2(acc[i][1]);
}

// SMEM layout (floats): Ws1[16][1028] | Ws2[8][1028] | Ws3[8][1028] | As[2][64*132]
#define OFF_WS1 0
#define OFF_WS2 (16 * WST)
#define OFF_WS3 (24 * WST)
#define OFF_AS  (32 * WST)
#define SMEM_REC_FLOATS (OFF_AS + 2 * ABUF)
#define SMEM_REC_BYTES  (SMEM_REC_FLOATS * 4)

// ---------------------------------------------------------------------------
// Persistent recurrent kernel: 128 blocks x 512 threads, 512 steps.
// ---------------------------------------------------------------------------
__global__ void __launch_bounds__(THR, 1) gru_recurrent(const float* __restrict__ bp,
                                                        float* __restrict__ out) {
    extern __shared__ float smem[];
    float* Ws1 = smem + OFF_WS1;
    float* Ws2 = smem + OFF_WS2;
    float* Ws3 = smem + OFF_WS3;
    float* As  = smem + OFF_AS;

    const int tid = threadIdx.x;
    const int bid = blockIdx.x;

    // Load this block's weight columns into SMEM once.
    for (int idx = tid; idx < 16 * 256; idx += THR) {   // Ws1: 16 cols x 256 float4
        int i = idx >> 8, kq = (idx & 255) << 2;
        float4 v = *reinterpret_cast<const float4*>(&g_wt_zr[(size_t)(bid * 16 + i) * 1024 + kq]);
        *reinterpret_cast<float4*>(&Ws1[i * WST + kq]) = v;
    }
    for (int idx = tid; idx < 8 * 256; idx += THR) {
        int i = idx >> 8, kq = (idx & 255) << 2;
        float4 v = *reinterpret_cast<const float4*>(&g_wt_h[(size_t)(bid * 8 + i) * 1024 + kq]);
        *reinterpret_cast<float4*>(&Ws2[i * WST + kq]) = v;
        float4 w = *reinterpret_cast<const float4*>(&g_wt_p[(size_t)(bid * 8 + i) * 1024 + kq]);
        *reinterpret_cast<float4*>(&Ws3[i * WST + kq]) = w;
    }
    __syncthreads();

    // Thread maps
    const int cp1 = tid & 15;           // phase-1 col within block (0..15)
    const int rp1 = tid >> 4;           // phase-1 row group (0..31) -> rows 2rp1, 2rp1+1
    const int cp2 = tid & 7;            // phase-2/3 col within block (0..7)
    const int rp2 = tid >> 3;           // phase-2/3 row (0..63)

    const float bpv = bp[bid * 8 + cp2];
    unsigned ep = 0;
    int p = 0;   // h lives in g_hbuf[p] at step start

#pragma unroll 1
    for (int t = 0; t < TT; t++) {
        const float* h = g_hbuf[p];

        // ---- phase 1: zr = sigmoid(pre_zr + h @ Wzr_h) ----
        {
            const int cz = (bid << 4) + cp1;
            const int b0 = 2 * rp1, b1 = b0 + 1;
            // prefetch epilogue operands (streaming; latency hidden under GEMM)
            float p0 = __ldcs(&g_pre[(size_t)(b0 * TT + t) * 3072 + cz]);
            float p1 = __ldcs(&g_pre[(size_t)(b1 * TT + t) * 3072 + cz]);
            float s[2];
            rec_gemm<2, false>(h, nullptr, Ws1 + cp1 * WST, As, b0, s, tid);
            __stcg(&g_zr[b0 * 2048 + cz], sig_(s[0] + p0));
            __stcg(&g_zr[b1 * 2048 + cz], sig_(s[1] + p1));
        }
        grid_barrier(++ep);

        // ---- phase 2: cand + gate combine ----
        float* hnext = g_hbuf[p ^ 1];
        {
            const int c = (bid << 3) + cp2;
            float preh = __ldcs(&g_pre[(size_t)(rp2 * TT + t) * 3072 + 2048 + c]);
            float zv   = __ldcg(&g_zr[rp2 * 2048 + c]);       // already sigmoided
            float hold = __ldcg(&h[rp2 * 1024 + c]);
            float s[1];
            rec_gemm<1, true>(h, g_zr, Ws2 + cp2 * WST, As, rp2, s, tid);
            float hn = fmaf(zv, tanh_(s[0] + preh) - hold, hold);
            out[(size_t)(rp2 * TT + t) * 1024 + c] = hn;
            __stcg(&hnext[rp2 * 1024 + c], hn);
        }
        grid_barrier(++ep);

        // ---- phase 3: chunk-boundary projection ----
        const bool prop = ((t & 3) == 3) && (t != TT - 1);
        if (prop) {
            const int c = (bid << 3) + cp2;
            float s[1];
            rec_gemm<1, false>(hnext, nullptr, Ws3 + cp2 * WST, As, rp2, s, tid);
            __stcg(&g_hbuf[p][rp2 * 1024 + c], tanh_(s[0] + bpv));
            grid_barrier(++ep);
            // h stays in g_hbuf[p]
        } else {
            p ^= 1;
        }
    }
}

// ---------------------------------------------------------------------------
extern "C" void kernel_launch(void* const* d_in, const int* in_sizes, int n_in,
                              void* d_out, int out_size) {
    (void)in_sizes; (void)n_in; (void)out_size;
    const float* x  = (const float*)d_in[0];
    const float* h0 = (const float*)d_in[1];
    const float* Wz = (const float*)d_in[2];
    const float* bz = (const float*)d_in[3];
    const float* Wr = (const float*)d_in[4];
    const float* br = (const float*)d_in[5];
    const float* Wh = (const float*)d_in[6];
    const float* bh = (const float*)d_in[7];
    const float* Wp = (const float*)d_in[8];
    const float* bp = (const float*)d_in[9];
    float* out = (float*)d_out;

    static bool attr_set = false;
    if (!attr_set) {
        cudaFuncSetAttribute(gru_recurrent, cudaFuncAttributeMaxDynamicSharedMemorySize,
                             SMEM_REC_BYTES);
        attr_set = true;
    }

    transpose_weights<<<dim3(32, 32, 4), dim3(32, 32)>>>(Wz, Wr, Wh, Wp);
    init_h<<<64, 1024>>>(h0);
    reset_ctr<<<1, 32>>>();
    sgemm_pre<<<dim3(8, 256, 3), 256>>>(x, Wz, Wr, Wh, bz, br, bh);
    gru_recurrent<<<NB, THR, SMEM_REC_BYTES>>>(bp, out);
}

// round 9
// speedup vs baseline: 3.2184x; 1.0588x over previous
#include <cuda_runtime.h>

// ---------------------------------------------------------------------------
// ChunkParallelGRU: B=64, T=512, D=1024, H=1024, CHUNK=4
//
//   pre[g][m][n] = x[m] @ Wg_x + bg                (big GEMM, parallel)
//   per step t (sequential, persistent kernel):
//     P1: z = sig(pre_z + h @ Wz_h)          -> g_z    (blocks 0..63)
//         rh = sig(pre_r + h @ Wr_h) * h     -> g_rh   (blocks 64..127, fold)
//     P2: cand = tanh(pre_h + rh @ Wh_h);
//         h_new = h + z*(cand-h); out[t] = h_new
//     P3 (chunk boundary): h = tanh(h_new @ Wp + bp)
//
// v6 = v4 (round-6, known-good: counter barrier, __ldcg staging, single
//      launch) + rh-fold only (halves P2's L2 A-traffic).
// ---------------------------------------------------------------------------

#define BB 64
#define TT 512
#define BT (BB * TT)
#define NB 128          // persistent grid (<=148 SMs -> co-resident)
#define THR 512

typedef unsigned long long ull;

// Scratch (static device arrays; allocation-free)
__device__ float g_pre[(size_t)BT * 3072];      // [m][z|r|h]
__device__ float g_wt_zr[2048 * 1024];          // transposed h-parts of Wz|Wr: [n][k]
__device__ float g_wt_h[1024 * 1024];           // transposed h-part of Wh
__device__ float g_wt_p[1024 * 1024];           // transposed Wp
__device__ float g_hbuf[2][BB * 1024];          // double-buffered state
__device__ float g_z[BB * 1024];                // sigmoided z for current step
__device__ float g_rh[BB * 1024];               // sig(r_pre)*h for current step
__device__ unsigned g_ctr;                      // barrier arrival counter (monotonic)

__device__ __forceinline__ float sig_(float x) {
    return 1.0f / (1.0f + __expf(-x));
}
__device__ __forceinline__ float tanh_(float x) {
    x = fminf(15.0f, fmaxf(-15.0f, x));
    float e = __expf(-2.0f * x);
    return (1.0f - e) / (1.0f + e);
}

// packed fp32x2 FMA: frees issue slots (same MAC rate as FFMA)
__device__ __forceinline__ void ffma2(ull& d, ull a, ull b) {
    asm("fma.rn.f32x2 %0, %1, %2, %3;" : "=l"(d) : "l"(a), "l"(b), "l"(d));
}
__device__ __forceinline__ float hsum2(ull u) {
    return __uint_as_float((unsigned)u) + __uint_as_float((unsigned)(u >> 32));
}

union U4 { float4 f; ull u[2]; };

// ---------------------------------------------------------------------------
// Grid barrier (round-6, known good): single monotonic counter.
// Arrive: red.release.gpu (orders this block's prior .cg stores).
// Wait: ONE poller with ld.acquire.gpu. All cross-block data uses .cg ops.
// ---------------------------------------------------------------------------
__device__ __forceinline__ void grid_barrier(unsigned ep) {
    __syncthreads();
    if (threadIdx.x == 0) {
        asm volatile("red.release.gpu.global.add.u32 [%0], 1;"
                     :: "l"(&g_ctr) : "memory");
        const unsigned target = ep * NB;
        unsigned v;
        do {
            asm volatile("ld.acquire.gpu.global.u32 %0, [%1];"
                         : "=r"(v) : "l"(&g_ctr) : "memory");
        } while ((int)(v - target) < 0);
    }
    __syncthreads();
}

__global__ void reset_ctr() {
    if (threadIdx.x == 0) g_ctr = 0u;
}

// ---------------------------------------------------------------------------
// Weight transpose: dst[n][k] = src[srcOff + k][n]
// ---------------------------------------------------------------------------
__global__ void transpose_weights(const float* __restrict__ Wz,
                                  const float* __restrict__ Wr,
                                  const float* __restrict__ Wh,
                                  const float* __restrict__ Wp) {
    __shared__ float tile[32][33];
    const int z = blockIdx.z;
    const float* src; float* dst; int srcOff;
    if (z == 0)      { src = Wz; dst = g_wt_zr;               srcOff = 1024; }
    else if (z == 1) { src = Wr; dst = g_wt_zr + 1024 * 1024; srcOff = 1024; }
    else if (z == 2) { src = Wh; dst = g_wt_h;                srcOff = 1024; }
    else             { src = Wp; dst = g_wt_p;                srcOff = 0;    }
    const int kBase = blockIdx.x * 32;
    const int cBase = blockIdx.y * 32;
    tile[threadIdx.y][threadIdx.x] =
        src[(srcOff + kBase + threadIdx.y) * 1024 + cBase + threadIdx.x];
    __syncthreads();
    dst[(cBase + threadIdx.y) * 1024 + kBase + threadIdx.x] =
        tile[threadIdx.x][threadIdx.y];
}

__global__ void init_h(const float* __restrict__ h0) {
    int i = blockIdx.x * blockDim.x + threadIdx.x;
    if (i < BB * 1024) g_hbuf[0][i] = h0[i];
}

// ---------------------------------------------------------------------------
// Precompute GEMM (double-buffered 128x128x8, 256 thr, 8x8 microtiles)
// ---------------------------------------------------------------------------
__global__ void __launch_bounds__(256, 2) sgemm_pre(
    const float* __restrict__ X,
    const float* __restrict__ Wz, const float* __restrict__ Wr, const float* __restrict__ Wh,
    const float* __restrict__ bz, const float* __restrict__ br, const float* __restrict__ bh) {
    const int g = blockIdx.z;
    const float* Bw   = (g == 0) ? Wz : (g == 1) ? Wr : Wh;
    const float* bias = (g == 0) ? bz : (g == 1) ? br : bh;
    const int m0 = blockIdx.y * 128;
    const int n0 = blockIdx.x * 128;

    __shared__ float As[2][8 * 128];   // [k][m]
    __shared__ float Bs[2][8 * 128];   // [k][n]

    const int tid = threadIdx.x;
    const int tr = (tid / 16) * 8;
    const int tc = (tid % 16) * 8;

    const int arow = tid / 2;
    const int acol = (tid % 2) * 4;
    const int brow = tid / 32;
    const int bcol = (tid % 32) * 4;

    ull acc2[8][4];
#pragma unroll
    for (int i = 0; i < 8; i++)
#pragma unroll
        for (int j = 0; j < 4; j++) acc2[i][j] = 0ull;

    {
        float4 av = *reinterpret_cast<const float4*>(&X[(size_t)(m0 + arow) * 1024 + acol]);
        As[0][(acol + 0) * 128 + arow] = av.x;
        As[0][(acol + 1) * 128 + arow] = av.y;
        As[0][(acol + 2) * 128 + arow] = av.z;
        As[0][(acol + 3) * 128 + arow] = av.w;
        float4 bv = *reinterpret_cast<const float4*>(&Bw[(size_t)brow * 1024 + n0 + bcol]);
        *reinterpret_cast<float4*>(&Bs[0][brow * 128 + bcol]) = bv;
    }
    __syncthreads();

    int buf = 0;
#pragma unroll 1
    for (int k0 = 0; k0 < 1024; k0 += 8) {
        float4 av2, bv2;
        const bool hasNext = (k0 + 8 < 1024);
        if (hasNext) {
            av2 = *reinterpret_cast<const float4*>(&X[(size_t)(m0 + arow) * 1024 + k0 + 8 + acol]);
            bv2 = *reinterpret_cast<const float4*>(&Bw[(size_t)(k0 + 8 + brow) * 1024 + n0 + bcol]);
        }
#pragma unroll
        for (int k = 0; k < 8; k++) {
            float regM[8];
            U4 n0v, n1v;
            *reinterpret_cast<float4*>(&regM[0]) = *reinterpret_cast<const float4*>(&As[buf][k * 128 + tr]);
            *reinterpret_cast<float4*>(&regM[4]) = *reinterpret_cast<const float4*>(&As[buf][k * 128 + tr + 4]);
            n0v.f = *reinterpret_cast<const float4*>(&Bs[buf][k * 128 + tc]);
            n1v.f = *reinterpret_cast<const float4*>(&Bs[buf][k * 128 + tc + 4]);
#pragma unroll
            for (int i = 0; i < 8; i++) {
                unsigned mu = __float_as_uint(regM[i]);
                ull mm = (ull)mu | ((ull)mu << 32);
                ffma2(acc2[i][0], mm, n0v.u[0]);
                ffma2(acc2[i][1], mm, n0v.u[1]);
                ffma2(acc2[i][2], mm, n1v.u[0]);
                ffma2(acc2[i][3], mm, n1v.u[1]);
            }
        }
        if (hasNext) {
            const int nb = buf ^ 1;
            As[nb][(acol + 0) * 128 + arow] = av2.x;
            As[nb][(acol + 1) * 128 + arow] = av2.y;
            As[nb][(acol + 2) * 128 + arow] = av2.z;
            As[nb][(acol + 3) * 128 + arow] = av2.w;
            *reinterpret_cast<float4*>(&Bs[nb][brow * 128 + bcol]) = bv2;
        }
        __syncthreads();
        buf ^= 1;
    }

    float4 bv0 = *reinterpret_cast<const float4*>(&bias[n0 + tc]);
    float4 bv1 = *reinterpret_cast<const float4*>(&bias[n0 + tc + 4]);
#pragma unroll
    for (int i = 0; i < 8; i++) {
        size_t base = (size_t)(m0 + tr + i) * 3072 + (size_t)g * 1024 + n0 + tc;
        float4 o0 = make_float4(__uint_as_float((unsigned)acc2[i][0])         + bv0.x,
                                __uint_as_float((unsigned)(acc2[i][0] >> 32)) + bv0.y,
                                __uint_as_float((unsigned)acc2[i][1])         + bv0.z,
                                __uint_as_float((unsigned)(acc2[i][1] >> 32)) + bv0.w);
        float4 o1 = make_float4(__uint_as_float((unsigned)acc2[i][2])         + bv1.x,
                                __uint_as_float((unsigned)(acc2[i][2] >> 32)) + bv1.y,
                                __uint_as_float((unsigned)acc2[i][3])         + bv1.z,
                                __uint_as_float((unsigned)(acc2[i][3] >> 32)) + bv1.w);
        *reinterpret_cast<float4*>(&g_pre[base])     = o0;
        *reinterpret_cast<float4*>(&g_pre[base + 4]) = o1;
    }
}

// ---------------------------------------------------------------------------
// Recurrent GEMM: 512 threads. Thread computes NR rows x 1 col (W column is
// SMEM-resident, k-contiguous). A (64x1024) staged gmem(.cg)->smem in K=128
// double-buffered chunks (register prefetch), row-major stride 132.
// ---------------------------------------------------------------------------
#define KC 128
#define AST 132
#define ABUF (64 * AST)
#define WST 1028

template <int NR>
__device__ __forceinline__ void rec_gemm(const float* __restrict__ A,
                                         const float* __restrict__ Wcol,
                                         float* __restrict__ As,
                                         int r0, float* __restrict__ outv, int tid) {
    ull acc[NR][2];
#pragma unroll
    for (int i = 0; i < NR; i++) { acc[i][0] = 0ull; acc[i][1] = 0ull; }

    // stage chunk 0: 64 rows x 128 k = 2048 float4 / 512 thr = 4 each
#pragma unroll
    for (int p = 0; p < 4; p++) {
        int pos = p * 512 + tid;
        int row = pos >> 5, kq = (pos & 31) << 2;
        float4 v = __ldcg(reinterpret_cast<const float4*>(&A[row * 1024 + kq]));
        *reinterpret_cast<float4*>(&As[row * AST + kq]) = v;
    }
    __syncthreads();

#pragma unroll 1
    for (int ch = 0; ch < 1024 / KC; ch++) {
        float4 nv[4];
        const bool hasNext = (ch < 1024 / KC - 1);
        if (hasNext) {
            const int kb = (ch + 1) << 7;
#pragma unroll
            for (int p = 0; p < 4; p++) {
                int pos = p * 512 + tid;
                int row = pos >> 5, kq = (pos & 31) << 2;
                nv[p] = __ldcg(reinterpret_cast<const float4*>(&A[row * 1024 + kb + kq]));
            }
        }
        const float* cur = As + (ch & 1) * ABUF;
        const float* wp  = Wcol + (ch << 7);
        const float* ap  = cur + r0 * AST;
#pragma unroll
        for (int k4 = 0; k4 < KC; k4 += 4) {
            U4 w;
            w.f = *reinterpret_cast<const float4*>(wp + k4);
#pragma unroll
            for (int i = 0; i < NR; i++) {
                U4 a;
                a.f = *reinterpret_cast<const float4*>(ap + i * AST + k4);
                ffma2(acc[i][0], a.u[0], w.u[0]);
                ffma2(acc[i][1], a.u[1], w.u[1]);
            }
        }
        if (hasNext) {
            float* nxt = As + ((ch + 1) & 1) * ABUF;
#pragma unroll
            for (int p = 0; p < 4; p++) {
                int pos = p * 512 + tid;
                int row = pos >> 5, kq = (pos & 31) << 2;
                *reinterpret_cast<float4*>(&nxt[row * AST + kq]) = nv[p];
            }
        }
        __syncthreads();
    }
#pragma unroll
    for (int i = 0; i < NR; i++) outv[i] = hsum2(acc[i][0]) + hsum2(acc[i][1]);
}

// SMEM layout (floats): Ws1[16][1028] | Ws2[8][1028] | Ws3[8][1028] | As[2][64*132]
#define OFF_WS1 0
#define OFF_WS2 (16 * WST)
#define OFF_WS3 (24 * WST)
#define OFF_AS  (32 * WST)
#define SMEM_REC_FLOATS (OFF_AS + 2 * ABUF)
#define SMEM_REC_BYTES  (SMEM_REC_FLOATS * 4)

// ---------------------------------------------------------------------------
// Persistent recurrent kernel: 128 blocks x 512 threads, 512 steps.
// ---------------------------------------------------------------------------
__global__ void __launch_bounds__(THR, 1) gru_recurrent(const float* __restrict__ bp,
                                                        float* __restrict__ out) {
    extern __shared__ float smem[];
    float* Ws1 = smem + OFF_WS1;
    float* Ws2 = smem + OFF_WS2;
    float* Ws3 = smem + OFF_WS3;
    float* As  = smem + OFF_AS;

    const int tid = threadIdx.x;
    const int bid = blockIdx.x;

    // Load this block's weight columns into SMEM once.
    for (int idx = tid; idx < 16 * 256; idx += THR) {   // Ws1: 16 cols x 256 float4
        int i = idx >> 8, kq = (idx & 255) << 2;
        float4 v = *reinterpret_cast<const float4*>(&g_wt_zr[(size_t)(bid * 16 + i) * 1024 + kq]);
        *reinterpret_cast<float4*>(&Ws1[i * WST + kq]) = v;
    }
    for (int idx = tid; idx < 8 * 256; idx += THR) {
        int i = idx >> 8, kq = (idx & 255) << 2;
        float4 v = *reinterpret_cast<const float4*>(&g_wt_h[(size_t)(bid * 8 + i) * 1024 + kq]);
        *reinterpret_cast<float4*>(&Ws2[i * WST + kq]) = v;
        float4 w = *reinterpret_cast<const float4*>(&g_wt_p[(size_t)(bid * 8 + i) * 1024 + kq]);
        *reinterpret_cast<float4*>(&Ws3[i * WST + kq]) = w;
    }
    __syncthreads();

    // Thread maps
    const int cp1 = tid & 15;           // P1 col within block (0..15)
    const int rp1 = tid >> 4;           // P1 row group (0..31) -> rows 2rp1, 2rp1+1
    const int cp2 = tid & 7;            // P2/P3 col within block (0..7)
    const int rp2 = tid >> 3;           // P2/P3 row (0..63)
    const bool isR = (bid >= 64);       // P1 r-half block (uniform per block)

    const float bpv = bp[bid * 8 + cp2];
    unsigned ep = 0;
    int p = 0;   // h lives in g_hbuf[p] at step start

#pragma unroll 1
    for (int t = 0; t < TT; t++) {
        const float* h = g_hbuf[p];

        // ---- phase 1: z -> g_z (bid<64) ; sig(r_pre)*h -> g_rh (bid>=64) ----
        {
            const int cz = (bid << 4) + cp1;          // 0..2047
            const int ch = cz & 1023;                 // hidden index
            const int b0 = 2 * rp1, b1 = b0 + 1;
            float p0 = __ldcs(&g_pre[(size_t)(b0 * TT + t) * 3072 + cz]);
            float p1 = __ldcs(&g_pre[(size_t)(b1 * TT + t) * 3072 + cz]);
            float h0v = 0.f, h1v = 0.f;
            if (isR) {
                h0v = __ldcg(&h[b0 * 1024 + ch]);
                h1v = __ldcg(&h[b1 * 1024 + ch]);
            }
            float s[2];
            rec_gemm<2>(h, Ws1 + cp1 * WST, As, b0, s, tid);
            float v0 = sig_(s[0] + p0);
            float v1 = sig_(s[1] + p1);
            if (isR) {
                __stcg(&g_rh[b0 * 1024 + ch], v0 * h0v);
                __stcg(&g_rh[b1 * 1024 + ch], v1 * h1v);
            } else {
                __stcg(&g_z[b0 * 1024 + ch], v0);
                __stcg(&g_z[b1 * 1024 + ch], v1);
            }
        }
        grid_barrier(++ep);

        // ---- phase 2: cand + gate combine (A = g_rh, single array) ----
        float* hnext = g_hbuf[p ^ 1];
        {
            const int c = (bid << 3) + cp2;
            float preh = __ldcs(&g_pre[(size_t)(rp2 * TT + t) * 3072 + 2048 + c]);
            float zv   = __ldcg(&g_z[rp2 * 1024 + c]);
            float hold = __ldcg(&h[rp2 * 1024 + c]);
            float s1;
            rec_gemm<1>(g_rh, Ws2 + cp2 * WST, As, rp2, &s1, tid);
            float hn = fmaf(zv, tanh_(s1 + preh) - hold, hold);
            out[(size_t)(rp2 * TT + t) * 1024 + c] = hn;
            __stcg(&hnext[rp2 * 1024 + c], hn);
        }
        grid_barrier(++ep);

        // ---- phase 3: chunk-boundary projection ----
        const bool prop = ((t & 3) == 3) && (t != TT - 1);
        if (prop) {
            const int c = (bid << 3) + cp2;
            float s1;
            rec_gemm<1>(hnext, Ws3 + cp2 * WST, As, rp2, &s1, tid);
            __stcg(&g_hbuf[p][rp2 * 1024 + c], tanh_(s1 + bpv));
            grid_barrier(++ep);
            // h stays in g_hbuf[p]
        } else {
            p ^= 1;
        }
    }
}

// ---------------------------------------------------------------------------
extern "C" void kernel_launch(void* const* d_in, const int* in_sizes, int n_in,
                              void* d_out, int out_size) {
    (void)in_sizes; (void)n_in; (void)out_size;
    const float* x  = (const float*)d_in[0];
    const float* h0 = (const float*)d_in[1];
    const float* Wz = (const float*)d_in[2];
    const float* bz = (const float*)d_in[3];
    const float* Wr = (const float*)d_in[4];
    const float* br = (const float*)d_in[5];
    const float* Wh = (const float*)d_in[6];
    const float* bh = (const float*)d_in[7];
    const float* Wp = (const float*)d_in[8];
    const float* bp = (const float*)d_in[9];
    float* out = (float*)d_out;

    static bool attr_set = false;
    if (!attr_set) {
        cudaFuncSetAttribute(gru_recurrent, cudaFuncAttributeMaxDynamicSharedMemorySize,
                             SMEM_REC_BYTES);
        attr_set = true;
    }

    transpose_weights<<<dim3(32, 32, 4), dim3(32, 32)>>>(Wz, Wr, Wh, Wp);
    init_h<<<64, 1024>>>(h0);
    reset_ctr<<<1, 32>>>();
    sgemm_pre<<<dim3(8, 256, 3), 256>>>(x, Wz, Wr, Wh, bz, br, bh);
    gru_recurrent<<<NB, THR, SMEM_REC_BYTES>>>(bp, out);
}

// round 10
// speedup vs baseline: 5.0999x; 1.5846x over previous
#include <cuda_runtime.h>
#include <cuda_bf16.h>
#include <cstdint>

// ---------------------------------------------------------------------------
// ChunkParallelGRU: B=64, T=512, D=1024, H=1024, CHUNK=4
//
//   pre[g][m][n] = x[m] @ Wg_x + bg                (big GEMM, parallel)
//   per step t (sequential, persistent kernel):
//     P1: z = sig(pre_z + h @ Wz_h)          -> g_z    (blocks 0..63)
//         rh = sig(pre_r + h @ Wr_h) * h     -> g_rh   (blocks 64..127)
//     P2: cand = tanh(pre_h + rh @ Wh_h);
//         h_new = h + z*(cand-h); out[t] = h_new
//     P3 (chunk boundary): h = tanh(h_new @ Wp + bp)
//
// v7 = v6 skeleton (counter barrier, .cg dataflow, single launch) with the
//      recurrent GEMMs on mma.sync.m16n8k16 bf16 3-term split:
//      acc += Ahi*Whi + Ahi*Wlo + Alo*Whi  (fp32 accumulate, ~2^-17/product).
//      Weights pre-split once; activations split during smem staging.
// ---------------------------------------------------------------------------

#define BB 64
#define TT 512
#define BT (BB * TT)
#define NB 128          // persistent grid (<=148 SMs -> co-resident)
#define THR 512

typedef unsigned long long ull;

// Scratch (static device arrays; allocation-free)
__device__ float g_pre[(size_t)BT * 3072];      // [m][z|r|h]
__device__ float g_wt_zr[2048 * 1024];          // transposed h-parts of Wz|Wr: [n][k]
__device__ float g_wt_h[1024 * 1024];           // transposed h-part of Wh
__device__ float g_wt_p[1024 * 1024];           // transposed Wp
__device__ __nv_bfloat16 g_whi[(size_t)4096 * 1024];  // bf16 hi of [zr|h|p] transposed
__device__ __nv_bfloat16 g_wlo[(size_t)4096 * 1024];  // bf16 lo
__device__ float g_hbuf[2][BB * 1024];          // double-buffered state
__device__ float g_z[BB * 1024];                // sigmoided z for current step
__device__ float g_rh[BB * 1024];               // sig(r_pre)*h for current step
__device__ unsigned g_ctr;                      // barrier arrival counter (monotonic)

__device__ __forceinline__ float sig_(float x) {
    return 1.0f / (1.0f + __expf(-x));
}
__device__ __forceinline__ float tanh_(float x) {
    x = fminf(15.0f, fmaxf(-15.0f, x));
    float e = __expf(-2.0f * x);
    return (1.0f - e) / (1.0f + e);
}

// packed fp32x2 FMA (sgemm_pre only)
__device__ __forceinline__ void ffma2(ull& d, ull a, ull b) {
    asm("fma.rn.f32x2 %0, %1, %2, %3;" : "=l"(d) : "l"(a), "l"(b), "l"(d));
}
union U4 { float4 f; ull u[2]; };

// bf16 MMA: D(16x8,f32) += A(16x16,bf16,row) * B(16x8,bf16,col)
__device__ __forceinline__ void mma_bf16(float* d, const unsigned* a, const unsigned* b) {
    asm volatile(
        "mma.sync.aligned.m16n8k16.row.col.f32.bf16.bf16.f32 "
        "{%0,%1,%2,%3}, {%4,%5,%6,%7}, {%8,%9}, {%0,%1,%2,%3};\n"
        : "+f"(d[0]), "+f"(d[1]), "+f"(d[2]), "+f"(d[3])
        : "r"(a[0]), "r"(a[1]), "r"(a[2]), "r"(a[3]), "r"(b[0]), "r"(b[1]));
}

// ---------------------------------------------------------------------------
// Grid barrier (round-6, known good).
// ---------------------------------------------------------------------------
__device__ __forceinline__ void grid_barrier(unsigned ep) {
    __syncthreads();
    if (threadIdx.x == 0) {
        asm volatile("red.release.gpu.global.add.u32 [%0], 1;"
                     :: "l"(&g_ctr) : "memory");
        const unsigned target = ep * NB;
        unsigned v;
        do {
            asm volatile("ld.acquire.gpu.global.u32 %0, [%1];"
                         : "=r"(v) : "l"(&g_ctr) : "memory");
        } while ((int)(v - target) < 0);
    }
    __syncthreads();
}

__global__ void reset_ctr() {
    if (threadIdx.x == 0) g_ctr = 0u;
}

// ---------------------------------------------------------------------------
// Weight transpose: dst[n][k] = src[srcOff + k][n]
// ---------------------------------------------------------------------------
__global__ void transpose_weights(const float* __restrict__ Wz,
                                  const float* __restrict__ Wr,
                                  const float* __restrict__ Wh,
                                  const float* __restrict__ Wp) {
    __shared__ float tile[32][33];
    const int z = blockIdx.z;
    const float* src; float* dst; int srcOff;
    if (z == 0)      { src = Wz; dst = g_wt_zr;               srcOff = 1024; }
    else if (z == 1) { src = Wr; dst = g_wt_zr + 1024 * 1024; srcOff = 1024; }
    else if (z == 2) { src = Wh; dst = g_wt_h;                srcOff = 1024; }
    else             { src = Wp; dst = g_wt_p;                srcOff = 0;    }
    const int kBase = blockIdx.x * 32;
    const int cBase = blockIdx.y * 32;
    tile[threadIdx.y][threadIdx.x] =
        src[(srcOff + kBase + threadIdx.y) * 1024 + cBase + threadIdx.x];
    __syncthreads();
    dst[(cBase + threadIdx.y) * 1024 + kBase + threadIdx.x] =
        tile[threadIdx.x][threadIdx.y];
}

// Split transposed weights into bf16 hi/lo. Combined rows: [0,2048)=zr,
// [2048,3072)=h, [3072,4096)=p.
__global__ void split_weights() {
    size_t i = (size_t)blockIdx.x * blockDim.x + threadIdx.x;
    if (i >= (size_t)4096 * 1024) return;
    size_t row = i >> 10;
    float v;
    if (row < 2048)      v = g_wt_zr[i];
    else if (row < 3072) v = g_wt_h[i - (size_t)2048 * 1024];
    else                 v = g_wt_p[i - (size_t)3072 * 1024];
    __nv_bfloat16 hi = __float2bfloat16_rn(v);
    g_whi[i] = hi;
    g_wlo[i] = __float2bfloat16_rn(v - __bfloat162float(hi));
}

__global__ void init_h(const float* __restrict__ h0) {
    int i = blockIdx.x * blockDim.x + threadIdx.x;
    if (i < BB * 1024) g_hbuf[0][i] = h0[i];
}

// ---------------------------------------------------------------------------
// Precompute GEMM (unchanged, round-6)
// ---------------------------------------------------------------------------
__global__ void __launch_bounds__(256, 2) sgemm_pre(
    const float* __restrict__ X,
    const float* __restrict__ Wz, const float* __restrict__ Wr, const float* __restrict__ Wh,
    const float* __restrict__ bz, const float* __restrict__ br, const float* __restrict__ bh) {
    const int g = blockIdx.z;
    const float* Bw   = (g == 0) ? Wz : (g == 1) ? Wr : Wh;
    const float* bias = (g == 0) ? bz : (g == 1) ? br : bh;
    const int m0 = blockIdx.y * 128;
    const int n0 = blockIdx.x * 128;

    __shared__ float As[2][8 * 128];
    __shared__ float Bs[2][8 * 128];

    const int tid = threadIdx.x;
    const int tr = (tid / 16) * 8;
    const int tc = (tid % 16) * 8;
    const int arow = tid / 2;
    const int acol = (tid % 2) * 4;
    const int brow = tid / 32;
    const int bcol = (tid % 32) * 4;

    ull acc2[8][4];
#pragma unroll
    for (int i = 0; i < 8; i++)
#pragma unroll
        for (int j = 0; j < 4; j++) acc2[i][j] = 0ull;

    {
        float4 av = *reinterpret_cast<const float4*>(&X[(size_t)(m0 + arow) * 1024 + acol]);
        As[0][(acol + 0) * 128 + arow] = av.x;
        As[0][(acol + 1) * 128 + arow] = av.y;
        As[0][(acol + 2) * 128 + arow] = av.z;
        As[0][(acol + 3) * 128 + arow] = av.w;
        float4 bv = *reinterpret_cast<const float4*>(&Bw[(size_t)brow * 1024 + n0 + bcol]);
        *reinterpret_cast<float4*>(&Bs[0][brow * 128 + bcol]) = bv;
    }
    __syncthreads();

    int buf = 0;
#pragma unroll 1
    for (int k0 = 0; k0 < 1024; k0 += 8) {
        float4 av2, bv2;
        const bool hasNext = (k0 + 8 < 1024);
        if (hasNext) {
            av2 = *reinterpret_cast<const float4*>(&X[(size_t)(m0 + arow) * 1024 + k0 + 8 + acol]);
            bv2 = *reinterpret_cast<const float4*>(&Bw[(size_t)(k0 + 8 + brow) * 1024 + n0 + bcol]);
        }
#pragma unroll
        for (int k = 0; k < 8; k++) {
            float regM[8];
            U4 n0v, n1v;
            *reinterpret_cast<float4*>(&regM[0]) = *reinterpret_cast<const float4*>(&As[buf][k * 128 + tr]);
            *reinterpret_cast<float4*>(&regM[4]) = *reinterpret_cast<const float4*>(&As[buf][k * 128 + tr + 4]);
            n0v.f = *reinterpret_cast<const float4*>(&Bs[buf][k * 128 + tc]);
            n1v.f = *reinterpret_cast<const float4*>(&Bs[buf][k * 128 + tc + 4]);
#pragma unroll
            for (int i = 0; i < 8; i++) {
                unsigned mu = __float_as_uint(regM[i]);
                ull mm = (ull)mu | ((ull)mu << 32);
                ffma2(acc2[i][0], mm, n0v.u[0]);
                ffma2(acc2[i][1], mm, n0v.u[1]);
                ffma2(acc2[i][2], mm, n1v.u[0]);
                ffma2(acc2[i][3], mm, n1v.u[1]);
            }
        }
        if (hasNext) {
            const int nb = buf ^ 1;
            As[nb][(acol + 0) * 128 + arow] = av2.x;
            As[nb][(acol + 1) * 128 + arow] = av2.y;
            As[nb][(acol + 2) * 128 + arow] = av2.z;
            As[nb][(acol + 3) * 128 + arow] = av2.w;
            *reinterpret_cast<float4*>(&Bs[nb][brow * 128 + bcol]) = bv2;
        }
        __syncthreads();
        buf ^= 1;
    }

    float4 bv0 = *reinterpret_cast<const float4*>(&bias[n0 + tc]);
    float4 bv1 = *reinterpret_cast<const float4*>(&bias[n0 + tc + 4]);
#pragma unroll
    for (int i = 0; i < 8; i++) {
        size_t base = (size_t)(m0 + tr + i) * 3072 + (size_t)g * 1024 + n0 + tc;
        float4 o0 = make_float4(__uint_as_float((unsigned)acc2[i][0])         + bv0.x,
                                __uint_as_float((unsigned)(acc2[i][0] >> 32)) + bv0.y,
                                __uint_as_float((unsigned)acc2[i][1])         + bv0.z,
                                __uint_as_float((unsigned)(acc2[i][1] >> 32)) + bv0.w);
        float4 o1 = make_float4(__uint_as_float((unsigned)acc2[i][2])         + bv1.x,
                                __uint_as_float((unsigned)(acc2[i][2] >> 32)) + bv1.y,
                                __uint_as_float((unsigned)acc2[i][3])         + bv1.z,
                                __uint_as_float((unsigned)(acc2[i][3] >> 32)) + bv1.w);
        *reinterpret_cast<float4*>(&g_pre[base])     = o0;
        *reinterpret_cast<float4*>(&g_pre[base + 4]) = o1;
    }
}

// ---------------------------------------------------------------------------
// SMEM layout (bytes). A stride 264 bf16 (528 B -> 132 words == 4 mod 32),
// W stride 1032 bf16 (2064 B -> 516 words == 4 mod 32): frag LDS conflict-free.
// ---------------------------------------------------------------------------
#define AST2 264
#define WST2 1032
#define SM_WHI   0                        // bf16[32*1032] = 66048 B
#define SM_WLO   66048
#define SM_AHI   132096                   // bf16[64*264] = 33792 B
#define SM_ALO   165888
#define SM_RED   199680                   // float[1536] = 6144 B
#define SM_TOTAL 205824

// ---------------------------------------------------------------------------
// MMA tile: C(64 x NT*8) = A(64x1024 fp32 global, .cg) @ W(smem bf16 hi/lo).
// 16 warps: mi = w>>2 (4 m-tiles of 16 rows); NT==2: ni=(w>>1)&1, ks=w&1
// (k-halves of each 256-chunk); NT==1: ni=0, ks=w&3. A staged per 256-k chunk
// with fp32->bf16 hi/lo split. ks>0 partials reduced via smem; result d[4]
// valid for ks==0 warps: d0=(r,c) d1=(r,c+1) d2=(r+8,c) d3=(r+8,c+1) with
// r = mi*16 + (lane>>2), c = ni*8 + 2*(lane&3).
// ---------------------------------------------------------------------------
template <int NT, int KSEG>
__device__ __forceinline__ void mma_tile(const float* __restrict__ Agf,
                                         const __nv_bfloat16* __restrict__ WhiS,
                                         const __nv_bfloat16* __restrict__ WloS,
                                         int colBase,
                                         __nv_bfloat16* __restrict__ AhiS,
                                         __nv_bfloat16* __restrict__ AloS,
                                         float* __restrict__ red,
                                         float* __restrict__ d, int tid) {
    const int w = tid >> 5, lane = tid & 31;
    const int g = lane >> 2, t = lane & 3;
    const int mi = w >> 2;
    const int ni = (NT == 2) ? ((w >> 1) & 1) : 0;
    const int ks = w & (KSEG - 1);
    const int SEGK = 256 / KSEG;

    d[0] = 0.f; d[1] = 0.f; d[2] = 0.f; d[3] = 0.f;

#pragma unroll 1
    for (int ch = 0; ch < 4; ch++) {
        __syncthreads();   // previous chunk fully consumed before restage
        // stage + split: 64 rows x 256 k fp32 -> bf16 hi/lo
#pragma unroll
        for (int p = 0; p < 8; p++) {
            int pos = p * 512 + tid;
            int row = pos >> 6, kq = (pos & 63) << 2;
            float4 v = __ldcg(reinterpret_cast<const float4*>(&Agf[row * 1024 + (ch << 8) + kq]));
            __nv_bfloat16 hx = __float2bfloat16_rn(v.x);
            __nv_bfloat16 hy = __float2bfloat16_rn(v.y);
            __nv_bfloat16 hz = __float2bfloat16_rn(v.z);
            __nv_bfloat16 hw = __float2bfloat16_rn(v.w);
            __nv_bfloat162 hp0; hp0.x = hx; hp0.y = hy;
            __nv_bfloat162 hp1; hp1.x = hz; hp1.y = hw;
            __nv_bfloat162 lp0;
            lp0.x = __float2bfloat16_rn(v.x - __bfloat162float(hx));
            lp0.y = __float2bfloat16_rn(v.y - __bfloat162float(hy));
            __nv_bfloat162 lp1;
            lp1.x = __float2bfloat16_rn(v.z - __bfloat162float(hz));
            lp1.y = __float2bfloat16_rn(v.w - __bfloat162float(hw));
            int base = row * AST2 + kq;
            *reinterpret_cast<__nv_bfloat162*>(&AhiS[base])     = hp0;
            *reinterpret_cast<__nv_bfloat162*>(&AhiS[base + 2]) = hp1;
            *reinterpret_cast<__nv_bfloat162*>(&AloS[base])     = lp0;
            *reinterpret_cast<__nv_bfloat162*>(&AloS[base + 2]) = lp1;
        }
        __syncthreads();

        const int ar = (mi * 16 + g) * AST2 + ks * SEGK + 2 * t;
        const int wr = (colBase + ni * 8 + g) * WST2 + (ch << 8) + ks * SEGK + 2 * t;
#pragma unroll
        for (int j = 0; j < SEGK / 16; j++) {
            const int ka = ar + j * 16;
            const int kb = wr + j * 16;
            unsigned ahi[4], alo[4], bhi[2], blo[2];
            ahi[0] = *reinterpret_cast<const unsigned*>(&AhiS[ka]);
            ahi[1] = *reinterpret_cast<const unsigned*>(&AhiS[ka + 8 * AST2]);
            ahi[2] = *reinterpret_cast<const unsigned*>(&AhiS[ka + 8]);
            ahi[3] = *reinterpret_cast<const unsigned*>(&AhiS[ka + 8 * AST2 + 8]);
            alo[0] = *reinterpret_cast<const unsigned*>(&AloS[ka]);
            alo[1] = *reinterpret_cast<const unsigned*>(&AloS[ka + 8 * AST2]);
            alo[2] = *reinterpret_cast<const unsigned*>(&AloS[ka + 8]);
            alo[3] = *reinterpret_cast<const unsigned*>(&AloS[ka + 8 * AST2 + 8]);
            bhi[0] = *reinterpret_cast<const unsigned*>(&WhiS[kb]);
            bhi[1] = *reinterpret_cast<const unsigned*>(&WhiS[kb + 8]);
            blo[0] = *reinterpret_cast<const unsigned*>(&WloS[kb]);
            blo[1] = *reinterpret_cast<const unsigned*>(&WloS[kb + 8]);
            mma_bf16(d, ahi, bhi);
            mma_bf16(d, ahi, blo);
            mma_bf16(d, alo, bhi);
        }
    }

    // reduce k-segments
    __syncthreads();
    if (ks != 0) {
        float* dst = red + (((mi * NT + ni) * (KSEG - 1) + (ks - 1)) * 32 + lane) * 4;
        dst[0] = d[0]; dst[1] = d[1]; dst[2] = d[2]; dst[3] = d[3];
    }
    __syncthreads();
    if (ks == 0) {
#pragma unroll
        for (int s = 0; s < KSEG - 1; s++) {
            const float* src = red + (((mi * NT + ni) * (KSEG - 1) + s) * 32 + lane) * 4;
            d[0] += src[0]; d[1] += src[1]; d[2] += src[2]; d[3] += src[3];
        }
    }
}

// ---------------------------------------------------------------------------
// Persistent recurrent kernel: 128 blocks x 512 threads, 512 steps.
// ---------------------------------------------------------------------------
__global__ void __launch_bounds__(THR, 1) gru_recurrent(const float* __restrict__ bp,
                                                        float* __restrict__ out) {
    extern __shared__ char smem[];
    __nv_bfloat16* WhiS = reinterpret_cast<__nv_bfloat16*>(smem + SM_WHI);
    __nv_bfloat16* WloS = reinterpret_cast<__nv_bfloat16*>(smem + SM_WLO);
    __nv_bfloat16* AhiS = reinterpret_cast<__nv_bfloat16*>(smem + SM_AHI);
    __nv_bfloat16* AloS = reinterpret_cast<__nv_bfloat16*>(smem + SM_ALO);
    float*         red  = reinterpret_cast<float*>(smem + SM_RED);

    const int tid = threadIdx.x;
    const int bid = blockIdx.x;
    const int w = tid >> 5, lane = tid & 31;
    const int g = lane >> 2, t = lane & 3;

    // Load this block's 32 weight columns (hi+lo) into SMEM once.
    // cols 0-15: zr cols bid*16+i ; 16-23: h cols bid*8+(i-16) ; 24-31: p cols.
    for (int idx = tid; idx < 32 * 128; idx += THR) {
        int i = idx >> 7, ko = (idx & 127) << 3;
        int gc = (i < 16) ? (bid * 16 + i)
               : (i < 24) ? (2048 + bid * 8 + (i - 16))
                          : (3072 + bid * 8 + (i - 24));
        *reinterpret_cast<uint4*>(&WhiS[i * WST2 + ko]) =
            *reinterpret_cast<const uint4*>(&g_whi[(size_t)gc * 1024 + ko]);
        *reinterpret_cast<uint4*>(&WloS[i * WST2 + ko]) =
            *reinterpret_cast<const uint4*>(&g_wlo[(size_t)gc * 1024 + ko]);
    }
    __syncthreads();

    const bool isR = (bid >= 64);
    unsigned ep = 0;
    int p = 0;   // h lives in g_hbuf[p] at step start

#pragma unroll 1
    for (int tt = 0; tt < TT; tt++) {
        const float* h = g_hbuf[p];

        // ---- phase 1: z (bid<64) ; sig(r_pre)*h (bid>=64) ----
        {
            float d[4];
            mma_tile<2, 2>(h, WhiS, WloS, 0, AhiS, AloS, red, d, tid);
            if ((w & 1) == 0) {
                const int mi = w >> 2, ni = (w >> 1) & 1;
                const int cz = (bid << 4) + ni * 8 + 2 * t;   // and cz+1
                const int r0 = mi * 16 + g, r1 = r0 + 8;
                float p00 = __ldcs(&g_pre[(size_t)(r0 * TT + tt) * 3072 + cz]);
                float p01 = __ldcs(&g_pre[(size_t)(r0 * TT + tt) * 3072 + cz + 1]);
                float p10 = __ldcs(&g_pre[(size_t)(r1 * TT + tt) * 3072 + cz]);
                float p11 = __ldcs(&g_pre[(size_t)(r1 * TT + tt) * 3072 + cz + 1]);
                float v00 = sig_(d[0] + p00);
                float v01 = sig_(d[1] + p01);
                float v10 = sig_(d[2] + p10);
                float v11 = sig_(d[3] + p11);
                if (isR) {
                    const int cn = cz - 1024;
                    float h00 = __ldcg(&h[r0 * 1024 + cn]);
                    float h01 = __ldcg(&h[r0 * 1024 + cn + 1]);
                    float h10 = __ldcg(&h[r1 * 1024 + cn]);
                    float h11 = __ldcg(&h[r1 * 1024 + cn + 1]);
                    __stcg(&g_rh[r0 * 1024 + cn],     v00 * h00);
                    __stcg(&g_rh[r0 * 1024 + cn + 1], v01 * h01);
                    __stcg(&g_rh[r1 * 1024 + cn],     v10 * h10);
                    __stcg(&g_rh[r1 * 1024 + cn + 1], v11 * h11);
                } else {
                    __stcg(&g_z[r0 * 1024 + cz],     v00);
                    __stcg(&g_z[r0 * 1024 + cz + 1], v01);
                    __stcg(&g_z[r1 * 1024 + cz],     v10);
                    __stcg(&g_z[r1 * 1024 + cz + 1], v11);
                }
            }
        }
        grid_barrier(++ep);

        // ---- phase 2: cand + gate combine ----
        float* hnext = g_hbuf[p ^ 1];
        {
            float d[4];
            mma_tile<1, 4>(g_rh, WhiS, WloS, 16, AhiS, AloS, red, d, tid);
            if ((w & 3) == 0) {
                const int mi = w >> 2;
                const int c0 = (bid << 3) + 2 * t;
                const int r0 = mi * 16 + g, r1 = r0 + 8;
#pragma unroll
                for (int e = 0; e < 4; e++) {
                    const int r = (e < 2) ? r0 : r1;
                    const int c = c0 + (e & 1);
                    float preh = __ldcs(&g_pre[(size_t)(r * TT + tt) * 3072 + 2048 + c]);
                    float zv   = __ldcg(&g_z[r * 1024 + c]);
                    float hold = __ldcg(&h[r * 1024 + c]);
                    float hn = fmaf(zv, tanh_(d[e] + preh) - hold, hold);
                    out[(size_t)(r * TT + tt) * 1024 + c] = hn;
                    __stcg(&hnext[r * 1024 + c], hn);
                }
            }
        }
        grid_barrier(++ep);

        // ---- phase 3: chunk-boundary projection ----
        const bool prop = ((tt & 3) == 3) && (tt != TT - 1);
        if (prop) {
            float d[4];
            mma_tile<1, 4>(hnext, WhiS, WloS, 24, AhiS, AloS, red, d, tid);
            if ((w & 3) == 0) {
                const int mi = w >> 2;
                const int c0 = (bid << 3) + 2 * t;
                const int r0 = mi * 16 + g, r1 = r0 + 8;
                float bp0 = bp[c0], bp1 = bp[c0 + 1];
#pragma unroll
                for (int e = 0; e < 4; e++) {
                    const int r = (e < 2) ? r0 : r1;
                    const int c = c0 + (e & 1);
                    float bv = (e & 1) ? bp1 : bp0;
                    __stcg(&g_hbuf[p][r * 1024 + c], tanh_(d[e] + bv));
                }
            }
            grid_barrier(++ep);
            // h stays in g_hbuf[p]
        } else {
            p ^= 1;
        }
    }
}

// ---------------------------------------------------------------------------
extern "C" void kernel_launch(void* const* d_in, const int* in_sizes, int n_in,
                              void* d_out, int out_size) {
    (void)in_sizes; (void)n_in; (void)out_size;
    const float* x  = (const float*)d_in[0];
    const float* h0 = (const float*)d_in[1];
    const float* Wz = (const float*)d_in[2];
    const float* bz = (const float*)d_in[3];
    const float* Wr = (const float*)d_in[4];
    const float* br = (const float*)d_in[5];
    const float* Wh = (const float*)d_in[6];
    const float* bh = (const float*)d_in[7];
    const float* Wp = (const float*)d_in[8];
    const float* bp = (const float*)d_in[9];
    float* out = (float*)d_out;

    static bool attr_set = false;
    if (!attr_set) {
        cudaFuncSetAttribute(gru_recurrent, cudaFuncAttributeMaxDynamicSharedMemorySize,
                             SM_TOTAL);
        attr_set = true;
    }

    transpose_weights<<<dim3(32, 32, 4), dim3(32, 32)>>>(Wz, Wr, Wh, Wp);
    split_weights<<<8192, 512>>>();
    init_h<<<64, 1024>>>(h0);
    reset_ctr<<<1, 32>>>();
    sgemm_pre<<<dim3(8, 256, 3), 256>>>(x, Wz, Wr, Wh, bz, br, bh);
    gru_recurrent<<<NB, THR, SM_TOTAL>>>(bp, out);
}

// round 11
// speedup vs baseline: 6.1804x; 1.2119x over previous
#include <cuda_runtime.h>
#include <cuda_bf16.h>
#include <cstdint>

// ---------------------------------------------------------------------------
// ChunkParallelGRU: B=64, T=512, D=1024, H=1024, CHUNK=4
//
//   pre[g][m][n] = x[m] @ Wg_x + bg                (bf16 3-term MMA GEMM)
//   per step t (sequential, persistent kernel):
//     P1: z = sig(pre_z + h @ Wz_h)          -> g_z    (blocks 0..63)
//         rh = sig(pre_r + h @ Wr_h) * h     -> rh hi/lo (blocks 64..127)
//     P2: cand = tanh(pre_h + rh @ Wh_h);
//         h_new = h + z*(cand-h); out[t] = h_new
//     P3 (chunk boundary): h = tanh(h_new @ Wp + bp)
//
// v8 = v7 skeleton + (a) producer-side bf16 hi/lo for h/rh/hnext (consumers
//      stage with pure uint4 copies, no cvt), (b) sgemm_pre on bf16 MMA.
// ---------------------------------------------------------------------------

#define BB 64
#define TT 512
#define BT (BB * 512)
#define NB 128          // persistent grid (<=148 SMs -> co-resident)
#define THR 512

// Scratch (static device arrays; allocation-free)
__device__ float g_pre[(size_t)BT * 3072];            // [m][z|r|h]
__device__ float g_wt_all[(size_t)7168 * 1024];       // transposed fp32 weights
__device__ __nv_bfloat16 g_whi[(size_t)7168 * 1024];  // bf16 hi: [zr_h|h_h|p|z_x|r_x|h_x]
__device__ __nv_bfloat16 g_wlo[(size_t)7168 * 1024];  // bf16 lo
__device__ __nv_bfloat16 g_xhi[(size_t)BT * 1024];    // bf16 hi of x
__device__ __nv_bfloat16 g_xlo[(size_t)BT * 1024];
__device__ float g_hbuf[2][BB * 1024];                // fp32 state (epilogue reads)
__device__ __nv_bfloat16 g_hhi[2][BB * 1024];         // bf16 hi/lo state (MMA A)
__device__ __nv_bfloat16 g_hlo[2][BB * 1024];
__device__ __nv_bfloat16 g_rhhi[BB * 1024];           // bf16 hi/lo of sig(r)*h
__device__ __nv_bfloat16 g_rhlo[BB * 1024];
__device__ float g_z[BB * 1024];                      // sigmoided z
__device__ unsigned g_ctr;                            // barrier counter (monotonic)

__device__ __forceinline__ float sig_(float x) {
    return 1.0f / (1.0f + __expf(-x));
}
__device__ __forceinline__ float tanh_(float x) {
    x = fminf(15.0f, fmaxf(-15.0f, x));
    float e = __expf(-2.0f * x);
    return (1.0f - e) / (1.0f + e);
}

// bf16 MMA: D(16x8,f32) += A(16x16,bf16,row) * B(16x8,bf16,col)
__device__ __forceinline__ void mma_bf16(float* d, const unsigned* a, const unsigned* b) {
    asm volatile(
        "mma.sync.aligned.m16n8k16.row.col.f32.bf16.bf16.f32 "
        "{%0,%1,%2,%3}, {%4,%5,%6,%7}, {%8,%9}, {%0,%1,%2,%3};\n"
        : "+f"(d[0]), "+f"(d[1]), "+f"(d[2]), "+f"(d[3])
        : "r"(a[0]), "r"(a[1]), "r"(a[2]), "r"(a[3]), "r"(b[0]), "r"(b[1]));
}

// split pair (a,b) -> packed bf16x2 hi and lo words
__device__ __forceinline__ void split2(float a, float b, unsigned& hip, unsigned& lop) {
    __nv_bfloat16 ah = __float2bfloat16_rn(a);
    __nv_bfloat16 bh = __float2bfloat16_rn(b);
    __nv_bfloat16 al = __float2bfloat16_rn(a - __bfloat162float(ah));
    __nv_bfloat16 bl = __float2bfloat16_rn(b - __bfloat162float(bh));
    hip = (unsigned)__bfloat16_as_ushort(ah) | ((unsigned)__bfloat16_as_ushort(bh) << 16);
    lop = (unsigned)__bfloat16_as_ushort(al) | ((unsigned)__bfloat16_as_ushort(bl) << 16);
}

// cp.async 16B via L2 (bypasses L1)
__device__ __forceinline__ void cpa16(uint32_t s, const void* g) {
    asm volatile("cp.async.cg.shared.global [%0], [%1], 16;" :: "r"(s), "l"(g) : "memory");
}
#define CP_COMMIT() asm volatile("cp.async.commit_group;" ::: "memory")

// ---------------------------------------------------------------------------
// Grid barrier (round-6, known good).
// ---------------------------------------------------------------------------
__device__ __forceinline__ void grid_barrier(unsigned ep) {
    __syncthreads();
    if (threadIdx.x == 0) {
        asm volatile("red.release.gpu.global.add.u32 [%0], 1;"
                     :: "l"(&g_ctr) : "memory");
        const unsigned target = ep * NB;
        unsigned v;
        do {
            asm volatile("ld.acquire.gpu.global.u32 %0, [%1];"
                         : "=r"(v) : "l"(&g_ctr) : "memory");
        } while ((int)(v - target) < 0);
    }
    __syncthreads();
}

__global__ void reset_ctr() {
    if (threadIdx.x == 0) g_ctr = 0u;
}

// ---------------------------------------------------------------------------
// Weight transpose into unified array: g_wt_all[z*1024 + n][k] = src[off+k][n]
//  z0..z2: Wz/Wr/Wh h-parts, z3: Wp, z4..z6: Wz/Wr/Wh x-parts.
// ---------------------------------------------------------------------------
__global__ void transpose_weights(const float* __restrict__ Wz,
                                  const float* __restrict__ Wr,
                                  const float* __restrict__ Wh,
                                  const float* __restrict__ Wp) {
    __shared__ float tile[32][33];
    const int z = blockIdx.z;
    const float* src;
    int srcOff;
    switch (z) {
        case 0: src = Wz; srcOff = 1024; break;
        case 1: src = Wr; srcOff = 1024; break;
        case 2: src = Wh; srcOff = 1024; break;
        case 3: src = Wp; srcOff = 0;    break;
        case 4: src = Wz; srcOff = 0;    break;
        case 5: src = Wr; srcOff = 0;    break;
        default: src = Wh; srcOff = 0;   break;
    }
    float* dst = g_wt_all + (size_t)z * 1024 * 1024;
    const int kBase = blockIdx.x * 32;
    const int cBase = blockIdx.y * 32;
    tile[threadIdx.y][threadIdx.x] =
        src[(size_t)(srcOff + kBase + threadIdx.y) * 1024 + cBase + threadIdx.x];
    __syncthreads();
    dst[(size_t)(cBase + threadIdx.y) * 1024 + kBase + threadIdx.x] =
        tile[threadIdx.x][threadIdx.y];
}

__global__ void split_weights() {
    size_t i = (size_t)blockIdx.x * blockDim.x + threadIdx.x;
    if (i >= (size_t)7168 * 1024) return;
    float v = g_wt_all[i];
    __nv_bfloat16 hi = __float2bfloat16_rn(v);
    g_whi[i] = hi;
    g_wlo[i] = __float2bfloat16_rn(v - __bfloat162float(hi));
}

__global__ void split_x(const float* __restrict__ x) {
    size_t i = (size_t)blockIdx.x * blockDim.x + threadIdx.x;
    if (i >= (size_t)BT * 1024) return;
    float v = x[i];
    __nv_bfloat16 hi = __float2bfloat16_rn(v);
    g_xhi[i] = hi;
    g_xlo[i] = __float2bfloat16_rn(v - __bfloat162float(hi));
}

__global__ void init_h(const float* __restrict__ h0) {
    int i = blockIdx.x * blockDim.x + threadIdx.x;
    if (i < BB * 1024) {
        float v = h0[i];
        g_hbuf[0][i] = v;
        __nv_bfloat16 hi = __float2bfloat16_rn(v);
        g_hhi[0][i] = hi;
        g_hlo[0][i] = __float2bfloat16_rn(v - __bfloat162float(hi));
    }
}

// ---------------------------------------------------------------------------
// Precompute GEMM on bf16 MMA: g_pre[m][gate*1024+n] = X @ Wg_x + bg.
// Block tile 128x128, K-chunks of 32, cp.async double buffered.
// 8 warps: warp tile 32 rows x 64 cols (4 m-warps x 2 n-warps),
// per warp 2 m-frags x 8 n-frags of m16n8k16, 3-term split.
// ---------------------------------------------------------------------------
#define SG_AST 40                         // bf16 row stride (conflict-free)
#define SG_A   (128 * SG_AST)             // one array (5120 bf16)
#define SG_BUFE (4 * SG_A)                // buffer: Ahi|Alo|Bhi|Blo
#define SG_SMEM_BYTES (2 * SG_BUFE * 2)   // 81920

__global__ void __launch_bounds__(256, 1) sgemm_pre_mma(
    const float* __restrict__ bz, const float* __restrict__ br,
    const float* __restrict__ bh) {
    extern __shared__ __nv_bfloat16 sm[];
    const int gate = blockIdx.z;
    const int m0 = blockIdx.y * 128;
    const int n0 = blockIdx.x * 128;
    const float* bias = (gate == 0) ? bz : (gate == 1) ? br : bh;
    const size_t wrow = (size_t)(4096 + gate * 1024 + n0) * 1024;

    const int tid = threadIdx.x;
    const int w = tid >> 5, lane = tid & 31, g4 = lane >> 2, t = lane & 3;
    const int wm = (w & 3) * 32, wn = (w >> 2) * 64;
    const uint32_t smb = (uint32_t)__cvta_generic_to_shared(sm);

    float acc[2][8][4];
#pragma unroll
    for (int i = 0; i < 2; i++)
#pragma unroll
        for (int j = 0; j < 8; j++)
#pragma unroll
            for (int e = 0; e < 4; e++) acc[i][j][e] = 0.0f;

    // initial stage (chunk 0)
#pragma unroll
    for (int q = 0; q < 2; q++) {
        int pos = q * 256 + tid;
        int row = pos >> 2, ku = (pos & 3) * 8;
        uint32_t soff = (uint32_t)(row * SG_AST + ku) * 2;
        cpa16(smb + 0 * SG_A * 2 + soff, &g_xhi[(size_t)(m0 + row) * 1024 + ku]);
        cpa16(smb + 1 * SG_A * 2 + soff, &g_xlo[(size_t)(m0 + row) * 1024 + ku]);
        cpa16(smb + 2 * SG_A * 2 + soff, &g_whi[wrow + (size_t)row * 1024 + ku]);
        cpa16(smb + 3 * SG_A * 2 + soff, &g_wlo[wrow + (size_t)row * 1024 + ku]);
    }
    CP_COMMIT();

    int buf = 0;
#pragma unroll 1
    for (int ch = 0; ch < 32; ch++) {
        const bool hasNext = (ch < 31);
        if (hasNext) {
            const int k0 = (ch + 1) * 32;
            const uint32_t b0 = smb + (uint32_t)((buf ^ 1) * SG_BUFE) * 2;
#pragma unroll
            for (int q = 0; q < 2; q++) {
                int pos = q * 256 + tid;
                int row = pos >> 2, ku = (pos & 3) * 8;
                uint32_t soff = (uint32_t)(row * SG_AST + ku) * 2;
                cpa16(b0 + 0 * SG_A * 2 + soff, &g_xhi[(size_t)(m0 + row) * 1024 + k0 + ku]);
                cpa16(b0 + 1 * SG_A * 2 + soff, &g_xlo[(size_t)(m0 + row) * 1024 + k0 + ku]);
                cpa16(b0 + 2 * SG_A * 2 + soff, &g_whi[wrow + (size_t)row * 1024 + k0 + ku]);
                cpa16(b0 + 3 * SG_A * 2 + soff, &g_wlo[wrow + (size_t)row * 1024 + k0 + ku]);
            }
            CP_COMMIT();
            asm volatile("cp.async.wait_group 1;" ::: "memory");
        } else {
            asm volatile("cp.async.wait_group 0;" ::: "memory");
        }
        __syncthreads();

        const __nv_bfloat16* bb = sm + buf * SG_BUFE;
        const __nv_bfloat16* AH = bb;
        const __nv_bfloat16* AL = bb + SG_A;
        const __nv_bfloat16* BH = bb + 2 * SG_A;
        const __nv_bfloat16* BL = bb + 3 * SG_A;
#pragma unroll
        for (int kf = 0; kf < 2; kf++) {
            const int koff = kf * 16 + 2 * t;
            unsigned ahi[2][4], alo[2][4];
#pragma unroll
            for (int mi = 0; mi < 2; mi++) {
                int ra = (wm + mi * 16 + g4) * SG_AST + koff;
                ahi[mi][0] = *reinterpret_cast<const unsigned*>(&AH[ra]);
                ahi[mi][1] = *reinterpret_cast<const unsigned*>(&AH[ra + 8 * SG_AST]);
                ahi[mi][2] = *reinterpret_cast<const unsigned*>(&AH[ra + 8]);
                ahi[mi][3] = *reinterpret_cast<const unsigned*>(&AH[ra + 8 * SG_AST + 8]);
                alo[mi][0] = *reinterpret_cast<const unsigned*>(&AL[ra]);
                alo[mi][1] = *reinterpret_cast<const unsigned*>(&AL[ra + 8 * SG_AST]);
                alo[mi][2] = *reinterpret_cast<const unsigned*>(&AL[ra + 8]);
                alo[mi][3] = *reinterpret_cast<const unsigned*>(&AL[ra + 8 * SG_AST + 8]);
            }
#pragma unroll
            for (int nj = 0; nj < 8; nj++) {
                int rb = (wn + nj * 8 + g4) * SG_AST + koff;
                unsigned bhi[2], blo[2];
                bhi[0] = *reinterpret_cast<const unsigned*>(&BH[rb]);
                bhi[1] = *reinterpret_cast<const unsigned*>(&BH[rb + 8]);
                blo[0] = *reinterpret_cast<const unsigned*>(&BL[rb]);
                blo[1] = *reinterpret_cast<const unsigned*>(&BL[rb + 8]);
#pragma unroll
                for (int mi = 0; mi < 2; mi++) {
                    mma_bf16(acc[mi][nj], ahi[mi], bhi);
                    mma_bf16(acc[mi][nj], ahi[mi], blo);
                    mma_bf16(acc[mi][nj], alo[mi], bhi);
                }
            }
        }
        __syncthreads();
        buf ^= 1;
    }

    // epilogue: add bias, store fp32
#pragma unroll
    for (int nj = 0; nj < 8; nj++) {
        int c = n0 + wn + nj * 8 + 2 * t;
        float b0v = bias[c], b1v = bias[c + 1];
#pragma unroll
        for (int mi = 0; mi < 2; mi++) {
            int r = m0 + wm + mi * 16 + g4;
            float2 o0 = make_float2(acc[mi][nj][0] + b0v, acc[mi][nj][1] + b1v);
            float2 o1 = make_float2(acc[mi][nj][2] + b0v, acc[mi][nj][3] + b1v);
            *reinterpret_cast<float2*>(&g_pre[(size_t)r * 3072 + gate * 1024 + c]) = o0;
            *reinterpret_cast<float2*>(&g_pre[(size_t)(r + 8) * 3072 + gate * 1024 + c]) = o1;
        }
    }
}

// ---------------------------------------------------------------------------
// Recurrent SMEM layout (bytes): W hi/lo (stride 1032), A hi/lo (stride 264).
// ---------------------------------------------------------------------------
#define AST2 264
#define WST2 1032
#define SM_WHI   0
#define SM_WLO   66048
#define SM_AHI   132096
#define SM_ALO   165888
#define SM_RED   199680
#define SM_TOTAL 205824

// ---------------------------------------------------------------------------
// MMA tile: C(64 x NT*8) = A(64x1024, pre-split bf16 hi/lo in global) @ W.
// A staged with pure uint4 copies (no conversion). Fragment math identical
// to the round-10-proven version.
// ---------------------------------------------------------------------------
template <int NT, int KSEG>
__device__ __forceinline__ void mma_tile(const __nv_bfloat16* __restrict__ AhiG,
                                         const __nv_bfloat16* __restrict__ AloG,
                                         const __nv_bfloat16* __restrict__ WhiS,
                                         const __nv_bfloat16* __restrict__ WloS,
                                         int colBase,
                                         __nv_bfloat16* __restrict__ AhiS,
                                         __nv_bfloat16* __restrict__ AloS,
                                         float* __restrict__ red,
                                         float* __restrict__ d, int tid) {
    const int w = tid >> 5, lane = tid & 31;
    const int g = lane >> 2, t = lane & 3;
    const int mi = w >> 2;
    const int ni = (NT == 2) ? ((w >> 1) & 1) : 0;
    const int ks = w & (KSEG - 1);
    const int SEGK = 256 / KSEG;

    d[0] = 0.f; d[1] = 0.f; d[2] = 0.f; d[3] = 0.f;

#pragma unroll 1
    for (int ch = 0; ch < 4; ch++) {
        __syncthreads();   // previous chunk fully consumed before restage
        // stage: 64 rows x 256 k bf16, hi+lo, pure copies
#pragma unroll
        for (int p = 0; p < 4; p++) {
            int pos = p * 512 + tid;
            int row = pos >> 5, ku = (pos & 31) << 3;
            *reinterpret_cast<uint4*>(&AhiS[row * AST2 + ku]) =
                __ldcg(reinterpret_cast<const uint4*>(&AhiG[row * 1024 + (ch << 8) + ku]));
            *reinterpret_cast<uint4*>(&AloS[row * AST2 + ku]) =
                __ldcg(reinterpret_cast<const uint4*>(&AloG[row * 1024 + (ch << 8) + ku]));
        }
        __syncthreads();

        const int ar = (mi * 16 + g) * AST2 + ks * SEGK + 2 * t;
        const int wr = (colBase + ni * 8 + g) * WST2 + (ch << 8) + ks * SEGK + 2 * t;
#pragma unroll
        for (int j = 0; j < SEGK / 16; j++) {
            const int ka = ar + j * 16;
            const int kb = wr + j * 16;
            unsigned ahi[4], alo[4], bhi[2], blo[2];
            ahi[0] = *reinterpret_cast<const unsigned*>(&AhiS[ka]);
            ahi[1] = *reinterpret_cast<const unsigned*>(&AhiS[ka + 8 * AST2]);
            ahi[2] = *reinterpret_cast<const unsigned*>(&AhiS[ka + 8]);
            ahi[3] = *reinterpret_cast<const unsigned*>(&AhiS[ka + 8 * AST2 + 8]);
            alo[0] = *reinterpret_cast<const unsigned*>(&AloS[ka]);
            alo[1] = *reinterpret_cast<const unsigned*>(&AloS[ka + 8 * AST2]);
            alo[2] = *reinterpret_cast<const unsigned*>(&AloS[ka + 8]);
            alo[3] = *reinterpret_cast<const unsigned*>(&AloS[ka + 8 * AST2 + 8]);
            bhi[0] = *reinterpret_cast<const unsigned*>(&WhiS[kb]);
            bhi[1] = *reinterpret_cast<const unsigned*>(&WhiS[kb + 8]);
            blo[0] = *reinterpret_cast<const unsigned*>(&WloS[kb]);
            blo[1] = *reinterpret_cast<const unsigned*>(&WloS[kb + 8]);
            mma_bf16(d, ahi, bhi);
            mma_bf16(d, ahi, blo);
            mma_bf16(d, alo, bhi);
        }
    }

    // reduce k-segments
    __syncthreads();
    if (ks != 0) {
        float* dst = red + (((mi * NT + ni) * (KSEG - 1) + (ks - 1)) * 32 + lane) * 4;
        dst[0] = d[0]; dst[1] = d[1]; dst[2] = d[2]; dst[3] = d[3];
    }
    __syncthreads();
    if (ks == 0) {
#pragma unroll
        for (int s = 0; s < KSEG - 1; s++) {
            const float* src = red + (((mi * NT + ni) * (KSEG - 1) + s) * 32 + lane) * 4;
            d[0] += src[0]; d[1] += src[1]; d[2] += src[2]; d[3] += src[3];
        }
    }
}

// ---------------------------------------------------------------------------
// Persistent recurrent kernel: 128 blocks x 512 threads, 512 steps.
// ---------------------------------------------------------------------------
__global__ void __launch_bounds__(THR, 1) gru_recurrent(const float* __restrict__ bp,
                                                        float* __restrict__ out) {
    extern __shared__ char smem[];
    __nv_bfloat16* WhiS = reinterpret_cast<__nv_bfloat16*>(smem + SM_WHI);
    __nv_bfloat16* WloS = reinterpret_cast<__nv_bfloat16*>(smem + SM_WLO);
    __nv_bfloat16* AhiS = reinterpret_cast<__nv_bfloat16*>(smem + SM_AHI);
    __nv_bfloat16* AloS = reinterpret_cast<__nv_bfloat16*>(smem + SM_ALO);
    float*         red  = reinterpret_cast<float*>(smem + SM_RED);

    const int tid = threadIdx.x;
    const int bid = blockIdx.x;
    const int w = tid >> 5, lane = tid & 31;
    const int g = lane >> 2, t = lane & 3;

    // Load this block's 32 weight columns (hi+lo) into SMEM once.
    for (int idx = tid; idx < 32 * 128; idx += THR) {
        int i = idx >> 7, ko = (idx & 127) << 3;
        int gc = (i < 16) ? (bid * 16 + i)
               : (i < 24) ? (2048 + bid * 8 + (i - 16))
                          : (3072 + bid * 8 + (i - 24));
        *reinterpret_cast<uint4*>(&WhiS[i * WST2 + ko]) =
            *reinterpret_cast<const uint4*>(&g_whi[(size_t)gc * 1024 + ko]);
        *reinterpret_cast<uint4*>(&WloS[i * WST2 + ko]) =
            *reinterpret_cast<const uint4*>(&g_wlo[(size_t)gc * 1024 + ko]);
    }
    __syncthreads();

    const bool isR = (bid >= 64);
    unsigned ep = 0;
    int p = 0;   // h lives in buffers [p] at step start

#pragma unroll 1
    for (int tt = 0; tt < TT; tt++) {
        const float* h = g_hbuf[p];

        // ---- phase 1: z (bid<64) ; sig(r_pre)*h -> rh hi/lo (bid>=64) ----
        {
            float d[4];
            mma_tile<2, 2>(g_hhi[p], g_hlo[p], WhiS, WloS, 0, AhiS, AloS, red, d, tid);
            if ((w & 1) == 0) {
                const int mi = w >> 2, ni = (w >> 1) & 1;
                const int cz = (bid << 4) + ni * 8 + 2 * t;   // and cz+1
                const int r0 = mi * 16 + g, r1 = r0 + 8;
                float p00 = __ldcs(&g_pre[(size_t)(r0 * TT + tt) * 3072 + cz]);
                float p01 = __ldcs(&g_pre[(size_t)(r0 * TT + tt) * 3072 + cz + 1]);
                float p10 = __ldcs(&g_pre[(size_t)(r1 * TT + tt) * 3072 + cz]);
                float p11 = __ldcs(&g_pre[(size_t)(r1 * TT + tt) * 3072 + cz + 1]);
                float v00 = sig_(d[0] + p00);
                float v01 = sig_(d[1] + p01);
                float v10 = sig_(d[2] + p10);
                float v11 = sig_(d[3] + p11);
                if (isR) {
                    const int cn = cz - 1024;
                    float q00 = v00 * __ldcg(&h[r0 * 1024 + cn]);
                    float q01 = v01 * __ldcg(&h[r0 * 1024 + cn + 1]);
                    float q10 = v10 * __ldcg(&h[r1 * 1024 + cn]);
                    float q11 = v11 * __ldcg(&h[r1 * 1024 + cn + 1]);
                    unsigned hp, lp;
                    split2(q00, q01, hp, lp);
                    __stcg(reinterpret_cast<unsigned*>(&g_rhhi[r0 * 1024 + cn]), hp);
                    __stcg(reinterpret_cast<unsigned*>(&g_rhlo[r0 * 1024 + cn]), lp);
                    split2(q10, q11, hp, lp);
                    __stcg(reinterpret_cast<unsigned*>(&g_rhhi[r1 * 1024 + cn]), hp);
                    __stcg(reinterpret_cast<unsigned*>(&g_rhlo[r1 * 1024 + cn]), lp);
                } else {
                    __stcg(&g_z[r0 * 1024 + cz],     v00);
                    __stcg(&g_z[r0 * 1024 + cz + 1], v01);
                    __stcg(&g_z[r1 * 1024 + cz],     v10);
                    __stcg(&g_z[r1 * 1024 + cz + 1], v11);
                }
            }
        }
        grid_barrier(++ep);

        // ---- phase 2: cand + gate combine ----
        const int pn = p ^ 1;
        {
            float d[4];
            mma_tile<1, 4>(g_rhhi, g_rhlo, WhiS, WloS, 16, AhiS, AloS, red, d, tid);
            if ((w & 3) == 0) {
                const int mi = w >> 2;
                const int c0 = (bid << 3) + 2 * t;
                const int r0 = mi * 16 + g, r1 = r0 + 8;
                float ph00 = __ldcs(&g_pre[(size_t)(r0 * TT + tt) * 3072 + 2048 + c0]);
                float ph01 = __ldcs(&g_pre[(size_t)(r0 * TT + tt) * 3072 + 2048 + c0 + 1]);
                float ph10 = __ldcs(&g_pre[(size_t)(r1 * TT + tt) * 3072 + 2048 + c0]);
                float ph11 = __ldcs(&g_pre[(size_t)(r1 * TT + tt) * 3072 + 2048 + c0 + 1]);
                float z00 = __ldcg(&g_z[r0 * 1024 + c0]);
                float z01 = __ldcg(&g_z[r0 * 1024 + c0 + 1]);
                float z10 = __ldcg(&g_z[r1 * 1024 + c0]);
                float z11 = __ldcg(&g_z[r1 * 1024 + c0 + 1]);
                float h00 = __ldcg(&h[r0 * 1024 + c0]);
                float h01 = __ldcg(&h[r0 * 1024 + c0 + 1]);
                float h10 = __ldcg(&h[r1 * 1024 + c0]);
                float h11 = __ldcg(&h[r1 * 1024 + c0 + 1]);
                float hn00 = fmaf(z00, tanh_(d[0] + ph00) - h00, h00);
                float hn01 = fmaf(z01, tanh_(d[1] + ph01) - h01, h01);
                float hn10 = fmaf(z10, tanh_(d[2] + ph10) - h10, h10);
                float hn11 = fmaf(z11, tanh_(d[3] + ph11) - h11, h11);
                out[(size_t)(r0 * TT + tt) * 1024 + c0]     = hn00;
                out[(size_t)(r0 * TT + tt) * 1024 + c0 + 1] = hn01;
                out[(size_t)(r1 * TT + tt) * 1024 + c0]     = hn10;
                out[(size_t)(r1 * TT + tt) * 1024 + c0 + 1] = hn11;
                __stcg(&g_hbuf[pn][r0 * 1024 + c0],     hn00);
                __stcg(&g_hbuf[pn][r0 * 1024 + c0 + 1], hn01);
                __stcg(&g_hbuf[pn][r1 * 1024 + c0],     hn10);
                __stcg(&g_hbuf[pn][r1 * 1024 + c0 + 1], hn11);
                unsigned hp, lp;
                split2(hn00, hn01, hp, lp);
                __stcg(reinterpret_cast<unsigned*>(&g_hhi[pn][r0 * 1024 + c0]), hp);
                __stcg(reinterpret_cast<unsigned*>(&g_hlo[pn][r0 * 1024 + c0]), lp);
                split2(hn10, hn11, hp, lp);
                __stcg(reinterpret_cast<unsigned*>(&g_hhi[pn][r1 * 1024 + c0]), hp);
                __stcg(reinterpret_cast<unsigned*>(&g_hlo[pn][r1 * 1024 + c0]), lp);
            }
        }
        grid_barrier(++ep);

        // ---- phase 3: chunk-boundary projection ----
        const bool prop = ((tt & 3) == 3) && (tt != TT - 1);
        if (prop) {
            float d[4];
            mma_tile<1, 4>(g_hhi[pn], g_hlo[pn], WhiS, WloS, 24, AhiS, AloS, red, d, tid);
            if ((w & 3) == 0) {
                const int mi = w >> 2;
                const int c0 = (bid << 3) + 2 * t;
                const int r0 = mi * 16 + g, r1 = r0 + 8;
                float bp0 = bp[c0], bp1 = bp[c0 + 1];
                float v00 = tanh_(d[0] + bp0);
                float v01 = tanh_(d[1] + bp1);
                float v10 = tanh_(d[2] + bp0);
                float v11 = tanh_(d[3] + bp1);
                __stcg(&g_hbuf[p][r0 * 1024 + c0],     v00);
                __stcg(&g_hbuf[p][r0 * 1024 + c0 + 1], v01);
                __stcg(&g_hbuf[p][r1 * 1024 + c0],     v10);
                __stcg(&g_hbuf[p][r1 * 1024 + c0 + 1], v11);
                unsigned hp, lp;
                split2(v00, v01, hp, lp);
                __stcg(reinterpret_cast<unsigned*>(&g_hhi[p][r0 * 1024 + c0]), hp);
                __stcg(reinterpret_cast<unsigned*>(&g_hlo[p][r0 * 1024 + c0]), lp);
                split2(v10, v11, hp, lp);
                __stcg(reinterpret_cast<unsigned*>(&g_hhi[p][r1 * 1024 + c0]), hp);
                __stcg(reinterpret_cast<unsigned*>(&g_hlo[p][r1 * 1024 + c0]), lp);
            }
            grid_barrier(++ep);
            // h stays in buffers [p]
        } else {
            p ^= 1;
        }
    }
}

// ---------------------------------------------------------------------------
extern "C" void kernel_launch(void* const* d_in, const int* in_sizes, int n_in,
                              void* d_out, int out_size) {
    (void)in_sizes; (void)n_in; (void)out_size;
    const float* x  = (const float*)d_in[0];
    const float* h0 = (const float*)d_in[1];
    const float* Wz = (const float*)d_in[2];
    const float* bz = (const float*)d_in[3];
    const float* Wr = (const float*)d_in[4];
    const float* br = (const float*)d_in[5];
    const float* Wh = (const float*)d_in[6];
    const float* bh = (const float*)d_in[7];
    const float* Wp = (const float*)d_in[8];
    const float* bp = (const float*)d_in[9];
    float* out = (float*)d_out;

    static bool attr_set = false;
    if (!attr_set) {
        cudaFuncSetAttribute(gru_recurrent, cudaFuncAttributeMaxDynamicSharedMemorySize,
                             SM_TOTAL);
        cudaFuncSetAttribute(sgemm_pre_mma, cudaFuncAttributeMaxDynamicSharedMemorySize,
                             SG_SMEM_BYTES);
        attr_set = true;
    }

    transpose_weights<<<dim3(32, 32, 7), dim3(32, 32)>>>(Wz, Wr, Wh, Wp);
    split_weights<<<14336, 512>>>();
    split_x<<<65536, 512>>>(x);
    init_h<<<64, 1024>>>(h0);
    reset_ctr<<<1, 32>>>();
    sgemm_pre_mma<<<dim3(8, 256, 3), 256, SG_SMEM_BYTES>>>(bz, br, bh);
    gru_recurrent<<<NB, THR, SM_TOTAL>>>(bp, out);
}

// round 12
// speedup vs baseline: 6.6573x; 1.0771x over previous
#include <cuda_runtime.h>
#include <cuda_bf16.h>
#include <cstdint>

// ---------------------------------------------------------------------------
// ChunkParallelGRU: B=64, T=512, D=1024, H=1024, CHUNK=4
//
//   pre[g][m][n] = x[m] @ Wg_x + bg                (bf16 3-term MMA GEMM)
//   per step t (sequential, persistent kernel):
//     P1: z = sig(pre_z + h @ Wz_h)          -> g_z    (blocks 0..63)
//         rh = sig(pre_r + h @ Wr_h) * h     -> rh hi/lo (blocks 64..127)
//     P2: cand = tanh(pre_h + rh @ Wh_h);
//         h_new = h + z*(cand-h); out[t] = h_new
//     P3 (chunk boundary): h = tanh(h_new @ Wp + bp)
//
// v9 = v8 + cp.async double-buffered A staging in mma_tile (stage/math
//      overlap; K-chunks 256->128 so 2 buffers fit in smem).
// ---------------------------------------------------------------------------

#define BB 64
#define TT 512
#define BT (BB * 512)
#define NB 128          // persistent grid (<=148 SMs -> co-resident)
#define THR 512

// Scratch (static device arrays; allocation-free)
__device__ float g_pre[(size_t)BT * 3072];            // [m][z|r|h]
__device__ float g_wt_all[(size_t)7168 * 1024];       // transposed fp32 weights
__device__ __nv_bfloat16 g_whi[(size_t)7168 * 1024];  // bf16 hi: [zr_h|h_h|p|z_x|r_x|h_x]
__device__ __nv_bfloat16 g_wlo[(size_t)7168 * 1024];  // bf16 lo
__device__ __nv_bfloat16 g_xhi[(size_t)BT * 1024];    // bf16 hi of x
__device__ __nv_bfloat16 g_xlo[(size_t)BT * 1024];
__device__ float g_hbuf[2][BB * 1024];                // fp32 state (epilogue reads)
__device__ __nv_bfloat16 g_hhi[2][BB * 1024];         // bf16 hi/lo state (MMA A)
__device__ __nv_bfloat16 g_hlo[2][BB * 1024];
__device__ __nv_bfloat16 g_rhhi[BB * 1024];           // bf16 hi/lo of sig(r)*h
__device__ __nv_bfloat16 g_rhlo[BB * 1024];
__device__ float g_z[BB * 1024];                      // sigmoided z
__device__ unsigned g_ctr;                            // barrier counter (monotonic)

__device__ __forceinline__ float sig_(float x) {
    return 1.0f / (1.0f + __expf(-x));
}
__device__ __forceinline__ float tanh_(float x) {
    x = fminf(15.0f, fmaxf(-15.0f, x));
    float e = __expf(-2.0f * x);
    return (1.0f - e) / (1.0f + e);
}

// bf16 MMA: D(16x8,f32) += A(16x16,bf16,row) * B(16x8,bf16,col)
__device__ __forceinline__ void mma_bf16(float* d, const unsigned* a, const unsigned* b) {
    asm volatile(
        "mma.sync.aligned.m16n8k16.row.col.f32.bf16.bf16.f32 "
        "{%0,%1,%2,%3}, {%4,%5,%6,%7}, {%8,%9}, {%0,%1,%2,%3};\n"
        : "+f"(d[0]), "+f"(d[1]), "+f"(d[2]), "+f"(d[3])
        : "r"(a[0]), "r"(a[1]), "r"(a[2]), "r"(a[3]), "r"(b[0]), "r"(b[1]));
}

// split pair (a,b) -> packed bf16x2 hi and lo words
__device__ __forceinline__ void split2(float a, float b, unsigned& hip, unsigned& lop) {
    __nv_bfloat16 ah = __float2bfloat16_rn(a);
    __nv_bfloat16 bh = __float2bfloat16_rn(b);
    __nv_bfloat16 al = __float2bfloat16_rn(a - __bfloat162float(ah));
    __nv_bfloat16 bl = __float2bfloat16_rn(b - __bfloat162float(bh));
    hip = (unsigned)__bfloat16_as_ushort(ah) | ((unsigned)__bfloat16_as_ushort(bh) << 16);
    lop = (unsigned)__bfloat16_as_ushort(al) | ((unsigned)__bfloat16_as_ushort(bl) << 16);
}

// cp.async 16B via L2 (bypasses L1)
__device__ __forceinline__ void cpa16(uint32_t s, const void* g) {
    asm volatile("cp.async.cg.shared.global [%0], [%1], 16;" :: "r"(s), "l"(g) : "memory");
}
#define CP_COMMIT() asm volatile("cp.async.commit_group;" ::: "memory")

// ---------------------------------------------------------------------------
// Grid barrier (round-6, known good).
// ---------------------------------------------------------------------------
__device__ __forceinline__ void grid_barrier(unsigned ep) {
    __syncthreads();
    if (threadIdx.x == 0) {
        asm volatile("red.release.gpu.global.add.u32 [%0], 1;"
                     :: "l"(&g_ctr) : "memory");
        const unsigned target = ep * NB;
        unsigned v;
        do {
            asm volatile("ld.acquire.gpu.global.u32 %0, [%1];"
                         : "=r"(v) : "l"(&g_ctr) : "memory");
        } while ((int)(v - target) < 0);
    }
    __syncthreads();
}

// ---------------------------------------------------------------------------
// Weight transpose into unified array: g_wt_all[z*1024 + n][k] = src[off+k][n]
//  z0..z2: Wz/Wr/Wh h-parts, z3: Wp, z4..z6: Wz/Wr/Wh x-parts.
// ---------------------------------------------------------------------------
__global__ void transpose_weights(const float* __restrict__ Wz,
                                  const float* __restrict__ Wr,
                                  const float* __restrict__ Wh,
                                  const float* __restrict__ Wp) {
    __shared__ float tile[32][33];
    const int z = blockIdx.z;
    const float* src;
    int srcOff;
    switch (z) {
        case 0: src = Wz; srcOff = 1024; break;
        case 1: src = Wr; srcOff = 1024; break;
        case 2: src = Wh; srcOff = 1024; break;
        case 3: src = Wp; srcOff = 0;    break;
        case 4: src = Wz; srcOff = 0;    break;
        case 5: src = Wr; srcOff = 0;    break;
        default: src = Wh; srcOff = 0;   break;
    }
    float* dst = g_wt_all + (size_t)z * 1024 * 1024;
    const int kBase = blockIdx.x * 32;
    const int cBase = blockIdx.y * 32;
    tile[threadIdx.y][threadIdx.x] =
        src[(size_t)(srcOff + kBase + threadIdx.y) * 1024 + cBase + threadIdx.x];
    __syncthreads();
    dst[(size_t)(cBase + threadIdx.y) * 1024 + kBase + threadIdx.x] =
        tile[threadIdx.x][threadIdx.y];
}

__global__ void split_weights() {
    size_t i = (size_t)blockIdx.x * blockDim.x + threadIdx.x;
    if (i >= (size_t)7168 * 1024) return;
    float v = g_wt_all[i];
    __nv_bfloat16 hi = __float2bfloat16_rn(v);
    g_whi[i] = hi;
    g_wlo[i] = __float2bfloat16_rn(v - __bfloat162float(hi));
}

__global__ void split_x(const float* __restrict__ x) {
    size_t i = (size_t)blockIdx.x * blockDim.x + threadIdx.x;
    if (i >= (size_t)BT * 1024) return;
    float v = x[i];
    __nv_bfloat16 hi = __float2bfloat16_rn(v);
    g_xhi[i] = hi;
    g_xlo[i] = __float2bfloat16_rn(v - __bfloat162float(hi));
}

__global__ void init_h(const float* __restrict__ h0) {
    int i = blockIdx.x * blockDim.x + threadIdx.x;
    if (i == 0) g_ctr = 0u;   // barrier reset (runs before gru_recurrent)
    if (i < BB * 1024) {
        float v = h0[i];
        g_hbuf[0][i] = v;
        __nv_bfloat16 hi = __float2bfloat16_rn(v);
        g_hhi[0][i] = hi;
        g_hlo[0][i] = __float2bfloat16_rn(v - __bfloat162float(hi));
    }
}

// ---------------------------------------------------------------------------
// Precompute GEMM on bf16 MMA (unchanged, round-11 proven).
// ---------------------------------------------------------------------------
#define SG_AST 40
#define SG_A   (128 * SG_AST)
#define SG_BUFE (4 * SG_A)
#define SG_SMEM_BYTES (2 * SG_BUFE * 2)

__global__ void __launch_bounds__(256, 1) sgemm_pre_mma(
    const float* __restrict__ bz, const float* __restrict__ br,
    const float* __restrict__ bh) {
    extern __shared__ __nv_bfloat16 sm[];
    const int gate = blockIdx.z;
    const int m0 = blockIdx.y * 128;
    const int n0 = blockIdx.x * 128;
    const float* bias = (gate == 0) ? bz : (gate == 1) ? br : bh;
    const size_t wrow = (size_t)(4096 + gate * 1024 + n0) * 1024;

    const int tid = threadIdx.x;
    const int w = tid >> 5, lane = tid & 31, g4 = lane >> 2, t = lane & 3;
    const int wm = (w & 3) * 32, wn = (w >> 2) * 64;
    const uint32_t smb = (uint32_t)__cvta_generic_to_shared(sm);

    float acc[2][8][4];
#pragma unroll
    for (int i = 0; i < 2; i++)
#pragma unroll
        for (int j = 0; j < 8; j++)
#pragma unroll
            for (int e = 0; e < 4; e++) acc[i][j][e] = 0.0f;

#pragma unroll
    for (int q = 0; q < 2; q++) {
        int pos = q * 256 + tid;
        int row = pos >> 2, ku = (pos & 3) * 8;
        uint32_t soff = (uint32_t)(row * SG_AST + ku) * 2;
        cpa16(smb + 0 * SG_A * 2 + soff, &g_xhi[(size_t)(m0 + row) * 1024 + ku]);
        cpa16(smb + 1 * SG_A * 2 + soff, &g_xlo[(size_t)(m0 + row) * 1024 + ku]);
        cpa16(smb + 2 * SG_A * 2 + soff, &g_whi[wrow + (size_t)row * 1024 + ku]);
        cpa16(smb + 3 * SG_A * 2 + soff, &g_wlo[wrow + (size_t)row * 1024 + ku]);
    }
    CP_COMMIT();

    int buf = 0;
#pragma unroll 1
    for (int ch = 0; ch < 32; ch++) {
        const bool hasNext = (ch < 31);
        if (hasNext) {
            const int k0 = (ch + 1) * 32;
            const uint32_t b0 = smb + (uint32_t)((buf ^ 1) * SG_BUFE) * 2;
#pragma unroll
            for (int q = 0; q < 2; q++) {
                int pos = q * 256 + tid;
                int row = pos >> 2, ku = (pos & 3) * 8;
                uint32_t soff = (uint32_t)(row * SG_AST + ku) * 2;
                cpa16(b0 + 0 * SG_A * 2 + soff, &g_xhi[(size_t)(m0 + row) * 1024 + k0 + ku]);
                cpa16(b0 + 1 * SG_A * 2 + soff, &g_xlo[(size_t)(m0 + row) * 1024 + k0 + ku]);
                cpa16(b0 + 2 * SG_A * 2 + soff, &g_whi[wrow + (size_t)row * 1024 + k0 + ku]);
                cpa16(b0 + 3 * SG_A * 2 + soff, &g_wlo[wrow + (size_t)row * 1024 + k0 + ku]);
            }
            CP_COMMIT();
            asm volatile("cp.async.wait_group 1;" ::: "memory");
        } else {
            asm volatile("cp.async.wait_group 0;" ::: "memory");
        }
        __syncthreads();

        const __nv_bfloat16* bb = sm + buf * SG_BUFE;
        const __nv_bfloat16* AH = bb;
        const __nv_bfloat16* AL = bb + SG_A;
        const __nv_bfloat16* BH = bb + 2 * SG_A;
        const __nv_bfloat16* BL = bb + 3 * SG_A;
#pragma unroll
        for (int kf = 0; kf < 2; kf++) {
            const int koff = kf * 16 + 2 * t;
            unsigned ahi[2][4], alo[2][4];
#pragma unroll
            for (int mi = 0; mi < 2; mi++) {
                int ra = (wm + mi * 16 + g4) * SG_AST + koff;
                ahi[mi][0] = *reinterpret_cast<const unsigned*>(&AH[ra]);
                ahi[mi][1] = *reinterpret_cast<const unsigned*>(&AH[ra + 8 * SG_AST]);
                ahi[mi][2] = *reinterpret_cast<const unsigned*>(&AH[ra + 8]);
                ahi[mi][3] = *reinterpret_cast<const unsigned*>(&AH[ra + 8 * SG_AST + 8]);
                alo[mi][0] = *reinterpret_cast<const unsigned*>(&AL[ra]);
                alo[mi][1] = *reinterpret_cast<const unsigned*>(&AL[ra + 8 * SG_AST]);
                alo[mi][2] = *reinterpret_cast<const unsigned*>(&AL[ra + 8]);
                alo[mi][3] = *reinterpret_cast<const unsigned*>(&AL[ra + 8 * SG_AST + 8]);
            }
#pragma unroll
            for (int nj = 0; nj < 8; nj++) {
                int rb = (wn + nj * 8 + g4) * SG_AST + koff;
                unsigned bhi[2], blo[2];
                bhi[0] = *reinterpret_cast<const unsigned*>(&BH[rb]);
                bhi[1] = *reinterpret_cast<const unsigned*>(&BH[rb + 8]);
                blo[0] = *reinterpret_cast<const unsigned*>(&BL[rb]);
                blo[1] = *reinterpret_cast<const unsigned*>(&BL[rb + 8]);
#pragma unroll
                for (int mi = 0; mi < 2; mi++) {
                    mma_bf16(acc[mi][nj], ahi[mi], bhi);
                    mma_bf16(acc[mi][nj], ahi[mi], blo);
                    mma_bf16(acc[mi][nj], alo[mi], bhi);
                }
            }
        }
        __syncthreads();
        buf ^= 1;
    }

#pragma unroll
    for (int nj = 0; nj < 8; nj++) {
        int c = n0 + wn + nj * 8 + 2 * t;
        float b0v = bias[c], b1v = bias[c + 1];
#pragma unroll
        for (int mi = 0; mi < 2; mi++) {
            int r = m0 + wm + mi * 16 + g4;
            float2 o0 = make_float2(acc[mi][nj][0] + b0v, acc[mi][nj][1] + b1v);
            float2 o1 = make_float2(acc[mi][nj][2] + b0v, acc[mi][nj][3] + b1v);
            *reinterpret_cast<float2*>(&g_pre[(size_t)r * 3072 + gate * 1024 + c]) = o0;
            *reinterpret_cast<float2*>(&g_pre[(size_t)(r + 8) * 3072 + gate * 1024 + c]) = o1;
        }
    }
}

// ---------------------------------------------------------------------------
// Recurrent SMEM layout (bytes). A staged in K=128 chunks, double buffered:
//   AST2=136 bf16 row stride (272 B = 68 words == 4 mod 32, conflict-free,
//   same residue as the proven 264 layout).
// ---------------------------------------------------------------------------
#define AST2 136
#define ACH  (64 * AST2)                  // one chunk buffer (bf16 elems)
#define WST2 1032
#define SM_WHI   0                        // 32*1032*2      = 66048
#define SM_WLO   66048                    //                = 66048
#define SM_AHI   132096                   // 2*ACH*2        = 34816
#define SM_ALO   166912                   //                = 34816
#define SM_RED   201728                   // float[1536]    = 6144
#define SM_TOTAL 207872

// ---------------------------------------------------------------------------
// MMA tile: C(64 x NT*8) = A(64x1024 bf16 hi/lo global) @ W(smem).
// cp.async double-buffered K=128 chunks (pattern proven in sgemm_pre_mma).
// Result d[4] valid for ks==0 warps; layout as round-10/11.
// ---------------------------------------------------------------------------
template <int NT, int KSEG>
__device__ __forceinline__ void mma_tile(const __nv_bfloat16* __restrict__ AhiG,
                                         const __nv_bfloat16* __restrict__ AloG,
                                         const __nv_bfloat16* __restrict__ WhiS,
                                         const __nv_bfloat16* __restrict__ WloS,
                                         int colBase,
                                         __nv_bfloat16* __restrict__ AhiS,
                                         __nv_bfloat16* __restrict__ AloS,
                                         float* __restrict__ red,
                                         float* __restrict__ d, int tid) {
    const int w = tid >> 5, lane = tid & 31;
    const int g = lane >> 2, t = lane & 3;
    const int mi = w >> 2;
    const int ni = (NT == 2) ? ((w >> 1) & 1) : 0;
    const int ks = w & (KSEG - 1);
    const int SEGK = 128 / KSEG;
    const uint32_t ahi_b = (uint32_t)__cvta_generic_to_shared(AhiS);
    const uint32_t alo_b = (uint32_t)__cvta_generic_to_shared(AloS);

    d[0] = 0.f; d[1] = 0.f; d[2] = 0.f; d[3] = 0.f;

    // prologue: chunk 0 -> buf 0 (64 rows x 128 k x 2B = 1024 x 16B; 2/thread)
#pragma unroll
    for (int p = 0; p < 2; p++) {
        int pos = p * 512 + tid;
        int row = pos >> 4, ku = (pos & 15) << 3;
        uint32_t soff = (uint32_t)(row * AST2 + ku) * 2;
        cpa16(ahi_b + soff, &AhiG[row * 1024 + ku]);
        cpa16(alo_b + soff, &AloG[row * 1024 + ku]);
    }
    CP_COMMIT();

    int buf = 0;
#pragma unroll 1
    for (int ch = 0; ch < 8; ch++) {
        if (ch < 7) {
            const int kb = (ch + 1) << 7;
            const uint32_t hb = ahi_b + (uint32_t)((buf ^ 1) * ACH) * 2;
            const uint32_t lb = alo_b + (uint32_t)((buf ^ 1) * ACH) * 2;
#pragma unroll
            for (int p = 0; p < 2; p++) {
                int pos = p * 512 + tid;
                int row = pos >> 4, ku = (pos & 15) << 3;
                uint32_t soff = (uint32_t)(row * AST2 + ku) * 2;
                cpa16(hb + soff, &AhiG[row * 1024 + kb + ku]);
                cpa16(lb + soff, &AloG[row * 1024 + kb + ku]);
            }
            CP_COMMIT();
            asm volatile("cp.async.wait_group 1;" ::: "memory");
        } else {
            asm volatile("cp.async.wait_group 0;" ::: "memory");
        }
        __syncthreads();

        const __nv_bfloat16* AH = AhiS + buf * ACH;
        const __nv_bfloat16* AL = AloS + buf * ACH;
        const int ar = (mi * 16 + g) * AST2 + ks * SEGK + 2 * t;
        const int wr = (colBase + ni * 8 + g) * WST2 + (ch << 7) + ks * SEGK + 2 * t;
#pragma unroll
        for (int j = 0; j < SEGK / 16; j++) {
            const int ka = ar + j * 16;
            const int kb2 = wr + j * 16;
            unsigned ahi[4], alo[4], bhi[2], blo[2];
            ahi[0] = *reinterpret_cast<const unsigned*>(&AH[ka]);
            ahi[1] = *reinterpret_cast<const unsigned*>(&AH[ka + 8 * AST2]);
            ahi[2] = *reinterpret_cast<const unsigned*>(&AH[ka + 8]);
            ahi[3] = *reinterpret_cast<const unsigned*>(&AH[ka + 8 * AST2 + 8]);
            alo[0] = *reinterpret_cast<const unsigned*>(&AL[ka]);
            alo[1] = *reinterpret_cast<const unsigned*>(&AL[ka + 8 * AST2]);
            alo[2] = *reinterpret_cast<const unsigned*>(&AL[ka + 8]);
            alo[3] = *reinterpret_cast<const unsigned*>(&AL[ka + 8 * AST2 + 8]);
            bhi[0] = *reinterpret_cast<const unsigned*>(&WhiS[kb2]);
            bhi[1] = *reinterpret_cast<const unsigned*>(&WhiS[kb2 + 8]);
            blo[0] = *reinterpret_cast<const unsigned*>(&WloS[kb2]);
            blo[1] = *reinterpret_cast<const unsigned*>(&WloS[kb2 + 8]);
            mma_bf16(d, ahi, bhi);
            mma_bf16(d, ahi, blo);
            mma_bf16(d, alo, bhi);
        }
        __syncthreads();
        buf ^= 1;
    }

    // reduce k-segments (loop ended with a syncthreads)
    if (ks != 0) {
        float* dst = red + (((mi * NT + ni) * (KSEG - 1) + (ks - 1)) * 32 + lane) * 4;
        dst[0] = d[0]; dst[1] = d[1]; dst[2] = d[2]; dst[3] = d[3];
    }
    __syncthreads();
    if (ks == 0) {
#pragma unroll
        for (int s = 0; s < KSEG - 1; s++) {
            const float* src = red + (((mi * NT + ni) * (KSEG - 1) + s) * 32 + lane) * 4;
            d[0] += src[0]; d[1] += src[1]; d[2] += src[2]; d[3] += src[3];
        }
    }
}

// ---------------------------------------------------------------------------
// Persistent recurrent kernel: 128 blocks x 512 threads, 512 steps.
// ---------------------------------------------------------------------------
__global__ void __launch_bounds__(THR, 1) gru_recurrent(const float* __restrict__ bp,
                                                        float* __restrict__ out) {
    extern __shared__ char smem[];
    __nv_bfloat16* WhiS = reinterpret_cast<__nv_bfloat16*>(smem + SM_WHI);
    __nv_bfloat16* WloS = reinterpret_cast<__nv_bfloat16*>(smem + SM_WLO);
    __nv_bfloat16* AhiS = reinterpret_cast<__nv_bfloat16*>(smem + SM_AHI);
    __nv_bfloat16* AloS = reinterpret_cast<__nv_bfloat16*>(smem + SM_ALO);
    float*         red  = reinterpret_cast<float*>(smem + SM_RED);

    const int tid = threadIdx.x;
    const int bid = blockIdx.x;
    const int w = tid >> 5, lane = tid & 31;
    const int g = lane >> 2, t = lane & 3;

    // Load this block's 32 weight columns (hi+lo) into SMEM once.
    for (int idx = tid; idx < 32 * 128; idx += THR) {
        int i = idx >> 7, ko = (idx & 127) << 3;
        int gc = (i < 16) ? (bid * 16 + i)
               : (i < 24) ? (2048 + bid * 8 + (i - 16))
                          : (3072 + bid * 8 + (i - 24));
        *reinterpret_cast<uint4*>(&WhiS[i * WST2 + ko]) =
            *reinterpret_cast<const uint4*>(&g_whi[(size_t)gc * 1024 + ko]);
        *reinterpret_cast<uint4*>(&WloS[i * WST2 + ko]) =
            *reinterpret_cast<const uint4*>(&g_wlo[(size_t)gc * 1024 + ko]);
    }
    __syncthreads();

    const bool isR = (bid >= 64);
    unsigned ep = 0;
    int p = 0;   // h lives in buffers [p] at step start

#pragma unroll 1
    for (int tt = 0; tt < TT; tt++) {
        const float* h = g_hbuf[p];

        // ---- phase 1: z (bid<64) ; sig(r_pre)*h -> rh hi/lo (bid>=64) ----
        {
            float d[4];
            mma_tile<2, 2>(g_hhi[p], g_hlo[p], WhiS, WloS, 0, AhiS, AloS, red, d, tid);
            if ((w & 1) == 0) {
                const int mi = w >> 2, ni = (w >> 1) & 1;
                const int cz = (bid << 4) + ni * 8 + 2 * t;   // and cz+1
                const int r0 = mi * 16 + g, r1 = r0 + 8;
                float p00 = __ldcs(&g_pre[(size_t)(r0 * TT + tt) * 3072 + cz]);
                float p01 = __ldcs(&g_pre[(size_t)(r0 * TT + tt) * 3072 + cz + 1]);
                float p10 = __ldcs(&g_pre[(size_t)(r1 * TT + tt) * 3072 + cz]);
                float p11 = __ldcs(&g_pre[(size_t)(r1 * TT + tt) * 3072 + cz + 1]);
                float v00 = sig_(d[0] + p00);
                float v01 = sig_(d[1] + p01);
                float v10 = sig_(d[2] + p10);
                float v11 = sig_(d[3] + p11);
                if (isR) {
                    const int cn = cz - 1024;
                    float q00 = v00 * __ldcg(&h[r0 * 1024 + cn]);
                    float q01 = v01 * __ldcg(&h[r0 * 1024 + cn + 1]);
                    float q10 = v10 * __ldcg(&h[r1 * 1024 + cn]);
                    float q11 = v11 * __ldcg(&h[r1 * 1024 + cn + 1]);
                    unsigned hp, lp;
                    split2(q00, q01, hp, lp);
                    __stcg(reinterpret_cast<unsigned*>(&g_rhhi[r0 * 1024 + cn]), hp);
                    __stcg(reinterpret_cast<unsigned*>(&g_rhlo[r0 * 1024 + cn]), lp);
                    split2(q10, q11, hp, lp);
                    __stcg(reinterpret_cast<unsigned*>(&g_rhhi[r1 * 1024 + cn]), hp);
                    __stcg(reinterpret_cast<unsigned*>(&g_rhlo[r1 * 1024 + cn]), lp);
                } else {
                    __stcg(&g_z[r0 * 1024 + cz],     v00);
                    __stcg(&g_z[r0 * 1024 + cz + 1], v01);
                    __stcg(&g_z[r1 * 1024 + cz],     v10);
                    __stcg(&g_z[r1 * 1024 + cz + 1], v11);
                }
            }
        }
        grid_barrier(++ep);

        // ---- phase 2: cand + gate combine ----
        const int pn = p ^ 1;
        {
            float d[4];
            mma_tile<1, 4>(g_rhhi, g_rhlo, WhiS, WloS, 16, AhiS, AloS, red, d, tid);
            if ((w & 3) == 0) {
                const int mi = w >> 2;
                const int c0 = (bid << 3) + 2 * t;
                const int r0 = mi * 16 + g, r1 = r0 + 8;
                float ph00 = __ldcs(&g_pre[(size_t)(r0 * TT + tt) * 3072 + 2048 + c0]);
                float ph01 = __ldcs(&g_pre[(size_t)(r0 * TT + tt) * 3072 + 2048 + c0 + 1]);
                float ph10 = __ldcs(&g_pre[(size_t)(r1 * TT + tt) * 3072 + 2048 + c0]);
                float ph11 = __ldcs(&g_pre[(size_t)(r1 * TT + tt) * 3072 + 2048 + c0 + 1]);
                float z00 = __ldcg(&g_z[r0 * 1024 + c0]);
                float z01 = __ldcg(&g_z[r0 * 1024 + c0 + 1]);
                float z10 = __ldcg(&g_z[r1 * 1024 + c0]);
                float z11 = __ldcg(&g_z[r1 * 1024 + c0 + 1]);
                float h00 = __ldcg(&h[r0 * 1024 + c0]);
                float h01 = __ldcg(&h[r0 * 1024 + c0 + 1]);
                float h10 = __ldcg(&h[r1 * 1024 + c0]);
                float h11 = __ldcg(&h[r1 * 1024 + c0 + 1]);
                float hn00 = fmaf(z00, tanh_(d[0] + ph00) - h00, h00);
                float hn01 = fmaf(z01, tanh_(d[1] + ph01) - h01, h01);
                float hn10 = fmaf(z10, tanh_(d[2] + ph10) - h10, h10);
                float hn11 = fmaf(z11, tanh_(d[3] + ph11) - h11, h11);
                out[(size_t)(r0 * TT + tt) * 1024 + c0]     = hn00;
                out[(size_t)(r0 * TT + tt) * 1024 + c0 + 1] = hn01;
                out[(size_t)(r1 * TT + tt) * 1024 + c0]     = hn10;
                out[(size_t)(r1 * TT + tt) * 1024 + c0 + 1] = hn11;
                __stcg(&g_hbuf[pn][r0 * 1024 + c0],     hn00);
                __stcg(&g_hbuf[pn][r0 * 1024 + c0 + 1], hn01);
                __stcg(&g_hbuf[pn][r1 * 1024 + c0],     hn10);
                __stcg(&g_hbuf[pn][r1 * 1024 + c0 + 1], hn11);
                unsigned hp, lp;
                split2(hn00, hn01, hp, lp);
                __stcg(reinterpret_cast<unsigned*>(&g_hhi[pn][r0 * 1024 + c0]), hp);
                __stcg(reinterpret_cast<unsigned*>(&g_hlo[pn][r0 * 1024 + c0]), lp);
                split2(hn10, hn11, hp, lp);
                __stcg(reinterpret_cast<unsigned*>(&g_hhi[pn][r1 * 1024 + c0]), hp);
                __stcg(reinterpret_cast<unsigned*>(&g_hlo[pn][r1 * 1024 + c0]), lp);
            }
        }
        grid_barrier(++ep);

        // ---- phase 3: chunk-boundary projection ----
        const bool prop = ((tt & 3) == 3) && (tt != TT - 1);
        if (prop) {
            float d[4];
            mma_tile<1, 4>(g_hhi[pn], g_hlo[pn], WhiS, WloS, 24, AhiS, AloS, red, d, tid);
            if ((w & 3) == 0) {
                const int mi = w >> 2;
                const int c0 = (bid << 3) + 2 * t;
                const int r0 = mi * 16 + g, r1 = r0 + 8;
                float bp0 = bp[c0], bp1 = bp[c0 + 1];
                float v00 = tanh_(d[0] + bp0);
                float v01 = tanh_(d[1] + bp1);
                float v10 = tanh_(d[2] + bp0);
                float v11 = tanh_(d[3] + bp1);
                __stcg(&g_hbuf[p][r0 * 1024 + c0],     v00);
                __stcg(&g_hbuf[p][r0 * 1024 + c0 + 1], v01);
                __stcg(&g_hbuf[p][r1 * 1024 + c0],     v10);
                __stcg(&g_hbuf[p][r1 * 1024 + c0 + 1], v11);
                unsigned hp, lp;
                split2(v00, v01, hp, lp);
                __stcg(reinterpret_cast<unsigned*>(&g_hhi[p][r0 * 1024 + c0]), hp);
                __stcg(reinterpret_cast<unsigned*>(&g_hlo[p][r0 * 1024 + c0]), lp);
                split2(v10, v11, hp, lp);
                __stcg(reinterpret_cast<unsigned*>(&g_hhi[p][r1 * 1024 + c0]), hp);
                __stcg(reinterpret_cast<unsigned*>(&g_hlo[p][r1 * 1024 + c0]), lp);
            }
            grid_barrier(++ep);
            // h stays in buffers [p]
        } else {
            p ^= 1;
        }
    }
}

// ---------------------------------------------------------------------------
extern "C" void kernel_launch(void* const* d_in, const int* in_sizes, int n_in,
                              void* d_out, int out_size) {
    (void)in_sizes; (void)n_in; (void)out_size;
    const float* x  = (const float*)d_in[0];
    const float* h0 = (const float*)d_in[1];
    const float* Wz = (const float*)d_in[2];
    const float* bz = (const float*)d_in[3];
    const float* Wr = (const float*)d_in[4];
    const float* br = (const float*)d_in[5];
    const float* Wh = (const float*)d_in[6];
    const float* bh = (const float*)d_in[7];
    const float* Wp = (const float*)d_in[8];
    const float* bp = (const float*)d_in[9];
    float* out = (float*)d_out;

    static bool attr_set = false;
    if (!attr_set) {
        cudaFuncSetAttribute(gru_recurrent, cudaFuncAttributeMaxDynamicSharedMemorySize,
                             SM_TOTAL);
        cudaFuncSetAttribute(sgemm_pre_mma, cudaFuncAttributeMaxDynamicSharedMemorySize,
                             SG_SMEM_BYTES);
        attr_set = true;
    }

    transpose_weights<<<dim3(32, 32, 7), dim3(32, 32)>>>(Wz, Wr, Wh, Wp);
    split_weights<<<14336, 512>>>();
    split_x<<<65536, 512>>>(x);
    init_h<<<64, 1024>>>(h0);
    sgemm_pre_mma<<<dim3(8, 256, 3), 256, SG_SMEM_BYTES>>>(bz, br, bh);
    gru_recurrent<<<NB, THR, SM_TOTAL>>>(bp, out);
}

// round 13
// speedup vs baseline: 6.9012x; 1.0366x over previous
#include <cuda_runtime.h>
#include <cuda_bf16.h>
#include <cstdint>

// ---------------------------------------------------------------------------
// ChunkParallelGRU: B=64, T=512, D=1024, H=1024, CHUNK=4
//
//   pre[g][m][n] = x[m] @ Wg_x + bg                (bf16 3-term MMA GEMM)
//   per step t (sequential, persistent kernel):
//     P1: z = sig(pre_z + h @ Wz_h)          -> g_z    (blocks 0..63)
//         rh = sig(pre_r + h @ Wr_h) * h     -> rh hi/lo (blocks 64..127)
//     P2: cand = tanh(pre_h + rh @ Wh_h);
//         h_new = h + z*(cand-h); out[t] = h_new
//     P3 (chunk boundary): h = tanh(h_new @ Wp + bp)
//
// v10 = v9 + (a) 3 independent MMA accumulator chains in mma_tile (breaks
//       the single HMMA dependency chain; tensor pipe goes throughput-bound),
//       (b) epilogue operand prefetch before the GEMM.
// ---------------------------------------------------------------------------

#define BB 64
#define TT 512
#define BT (BB * 512)
#define NB 128          // persistent grid (<=148 SMs -> co-resident)
#define THR 512

// Scratch (static device arrays; allocation-free)
__device__ float g_pre[(size_t)BT * 3072];            // [m][z|r|h]
__device__ float g_wt_all[(size_t)7168 * 1024];       // transposed fp32 weights
__device__ __nv_bfloat16 g_whi[(size_t)7168 * 1024];  // bf16 hi: [zr_h|h_h|p|z_x|r_x|h_x]
__device__ __nv_bfloat16 g_wlo[(size_t)7168 * 1024];  // bf16 lo
__device__ __nv_bfloat16 g_xhi[(size_t)BT * 1024];    // bf16 hi of x
__device__ __nv_bfloat16 g_xlo[(size_t)BT * 1024];
__device__ float g_hbuf[2][BB * 1024];                // fp32 state (epilogue reads)
__device__ __nv_bfloat16 g_hhi[2][BB * 1024];         // bf16 hi/lo state (MMA A)
__device__ __nv_bfloat16 g_hlo[2][BB * 1024];
__device__ __nv_bfloat16 g_rhhi[BB * 1024];           // bf16 hi/lo of sig(r)*h
__device__ __nv_bfloat16 g_rhlo[BB * 1024];
__device__ float g_z[BB * 1024];                      // sigmoided z
__device__ unsigned g_ctr;                            // barrier counter (monotonic)

__device__ __forceinline__ float sig_(float x) {
    return 1.0f / (1.0f + __expf(-x));
}
__device__ __forceinline__ float tanh_(float x) {
    x = fminf(15.0f, fmaxf(-15.0f, x));
    float e = __expf(-2.0f * x);
    return (1.0f - e) / (1.0f + e);
}

// bf16 MMA: D(16x8,f32) += A(16x16,bf16,row) * B(16x8,bf16,col)
__device__ __forceinline__ void mma_bf16(float* d, const unsigned* a, const unsigned* b) {
    asm volatile(
        "mma.sync.aligned.m16n8k16.row.col.f32.bf16.bf16.f32 "
        "{%0,%1,%2,%3}, {%4,%5,%6,%7}, {%8,%9}, {%0,%1,%2,%3};\n"
        : "+f"(d[0]), "+f"(d[1]), "+f"(d[2]), "+f"(d[3])
        : "r"(a[0]), "r"(a[1]), "r"(a[2]), "r"(a[3]), "r"(b[0]), "r"(b[1]));
}

// split pair (a,b) -> packed bf16x2 hi and lo words
__device__ __forceinline__ void split2(float a, float b, unsigned& hip, unsigned& lop) {
    __nv_bfloat16 ah = __float2bfloat16_rn(a);
    __nv_bfloat16 bh = __float2bfloat16_rn(b);
    __nv_bfloat16 al = __float2bfloat16_rn(a - __bfloat162float(ah));
    __nv_bfloat16 bl = __float2bfloat16_rn(b - __bfloat162float(bh));
    hip = (unsigned)__bfloat16_as_ushort(ah) | ((unsigned)__bfloat16_as_ushort(bh) << 16);
    lop = (unsigned)__bfloat16_as_ushort(al) | ((unsigned)__bfloat16_as_ushort(bl) << 16);
}

// cp.async 16B via L2 (bypasses L1)
__device__ __forceinline__ void cpa16(uint32_t s, const void* g) {
    asm volatile("cp.async.cg.shared.global [%0], [%1], 16;" :: "r"(s), "l"(g) : "memory");
}
#define CP_COMMIT() asm volatile("cp.async.commit_group;" ::: "memory")

// ---------------------------------------------------------------------------
// Grid barrier (round-6, known good).
// ---------------------------------------------------------------------------
__device__ __forceinline__ void grid_barrier(unsigned ep) {
    __syncthreads();
    if (threadIdx.x == 0) {
        asm volatile("red.release.gpu.global.add.u32 [%0], 1;"
                     :: "l"(&g_ctr) : "memory");
        const unsigned target = ep * NB;
        unsigned v;
        do {
            asm volatile("ld.acquire.gpu.global.u32 %0, [%1];"
                         : "=r"(v) : "l"(&g_ctr) : "memory");
        } while ((int)(v - target) < 0);
    }
    __syncthreads();
}

// ---------------------------------------------------------------------------
// Weight transpose into unified array: g_wt_all[z*1024 + n][k] = src[off+k][n]
// ---------------------------------------------------------------------------
__global__ void transpose_weights(const float* __restrict__ Wz,
                                  const float* __restrict__ Wr,
                                  const float* __restrict__ Wh,
                                  const float* __restrict__ Wp) {
    __shared__ float tile[32][33];
    const int z = blockIdx.z;
    const float* src;
    int srcOff;
    switch (z) {
        case 0: src = Wz; srcOff = 1024; break;
        case 1: src = Wr; srcOff = 1024; break;
        case 2: src = Wh; srcOff = 1024; break;
        case 3: src = Wp; srcOff = 0;    break;
        case 4: src = Wz; srcOff = 0;    break;
        case 5: src = Wr; srcOff = 0;    break;
        default: src = Wh; srcOff = 0;   break;
    }
    float* dst = g_wt_all + (size_t)z * 1024 * 1024;
    const int kBase = blockIdx.x * 32;
    const int cBase = blockIdx.y * 32;
    tile[threadIdx.y][threadIdx.x] =
        src[(size_t)(srcOff + kBase + threadIdx.y) * 1024 + cBase + threadIdx.x];
    __syncthreads();
    dst[(size_t)(cBase + threadIdx.y) * 1024 + kBase + threadIdx.x] =
        tile[threadIdx.x][threadIdx.y];
}

__global__ void split_weights() {
    size_t i = (size_t)blockIdx.x * blockDim.x + threadIdx.x;
    if (i >= (size_t)7168 * 1024) return;
    float v = g_wt_all[i];
    __nv_bfloat16 hi = __float2bfloat16_rn(v);
    g_whi[i] = hi;
    g_wlo[i] = __float2bfloat16_rn(v - __bfloat162float(hi));
}

__global__ void split_x(const float* __restrict__ x) {
    size_t i = (size_t)blockIdx.x * blockDim.x + threadIdx.x;
    if (i >= (size_t)BT * 1024) return;
    float v = x[i];
    __nv_bfloat16 hi = __float2bfloat16_rn(v);
    g_xhi[i] = hi;
    g_xlo[i] = __float2bfloat16_rn(v - __bfloat162float(hi));
}

__global__ void init_h(const float* __restrict__ h0) {
    int i = blockIdx.x * blockDim.x + threadIdx.x;
    if (i == 0) g_ctr = 0u;   // barrier reset (runs before gru_recurrent)
    if (i < BB * 1024) {
        float v = h0[i];
        g_hbuf[0][i] = v;
        __nv_bfloat16 hi = __float2bfloat16_rn(v);
        g_hhi[0][i] = hi;
        g_hlo[0][i] = __float2bfloat16_rn(v - __bfloat162float(hi));
    }
}

// ---------------------------------------------------------------------------
// Precompute GEMM on bf16 MMA (unchanged, round-11 proven; already has 16
// independent accumulator chains).
// ---------------------------------------------------------------------------
#define SG_AST 40
#define SG_A   (128 * SG_AST)
#define SG_BUFE (4 * SG_A)
#define SG_SMEM_BYTES (2 * SG_BUFE * 2)

__global__ void __launch_bounds__(256, 1) sgemm_pre_mma(
    const float* __restrict__ bz, const float* __restrict__ br,
    const float* __restrict__ bh) {
    extern __shared__ __nv_bfloat16 sm[];
    const int gate = blockIdx.z;
    const int m0 = blockIdx.y * 128;
    const int n0 = blockIdx.x * 128;
    const float* bias = (gate == 0) ? bz : (gate == 1) ? br : bh;
    const size_t wrow = (size_t)(4096 + gate * 1024 + n0) * 1024;

    const int tid = threadIdx.x;
    const int w = tid >> 5, lane = tid & 31, g4 = lane >> 2, t = lane & 3;
    const int wm = (w & 3) * 32, wn = (w >> 2) * 64;
    const uint32_t smb = (uint32_t)__cvta_generic_to_shared(sm);

    float acc[2][8][4];
#pragma unroll
    for (int i = 0; i < 2; i++)
#pragma unroll
        for (int j = 0; j < 8; j++)
#pragma unroll
            for (int e = 0; e < 4; e++) acc[i][j][e] = 0.0f;

#pragma unroll
    for (int q = 0; q < 2; q++) {
        int pos = q * 256 + tid;
        int row = pos >> 2, ku = (pos & 3) * 8;
        uint32_t soff = (uint32_t)(row * SG_AST + ku) * 2;
        cpa16(smb + 0 * SG_A * 2 + soff, &g_xhi[(size_t)(m0 + row) * 1024 + ku]);
        cpa16(smb + 1 * SG_A * 2 + soff, &g_xlo[(size_t)(m0 + row) * 1024 + ku]);
        cpa16(smb + 2 * SG_A * 2 + soff, &g_whi[wrow + (size_t)row * 1024 + ku]);
        cpa16(smb + 3 * SG_A * 2 + soff, &g_wlo[wrow + (size_t)row * 1024 + ku]);
    }
    CP_COMMIT();

    int buf = 0;
#pragma unroll 1
    for (int ch = 0; ch < 32; ch++) {
        const bool hasNext = (ch < 31);
        if (hasNext) {
            const int k0 = (ch + 1) * 32;
            const uint32_t b0 = smb + (uint32_t)((buf ^ 1) * SG_BUFE) * 2;
#pragma unroll
            for (int q = 0; q < 2; q++) {
                int pos = q * 256 + tid;
                int row = pos >> 2, ku = (pos & 3) * 8;
                uint32_t soff = (uint32_t)(row * SG_AST + ku) * 2;
                cpa16(b0 + 0 * SG_A * 2 + soff, &g_xhi[(size_t)(m0 + row) * 1024 + k0 + ku]);
                cpa16(b0 + 1 * SG_A * 2 + soff, &g_xlo[(size_t)(m0 + row) * 1024 + k0 + ku]);
                cpa16(b0 + 2 * SG_A * 2 + soff, &g_whi[wrow + (size_t)row * 1024 + k0 + ku]);
                cpa16(b0 + 3 * SG_A * 2 + soff, &g_wlo[wrow + (size_t)row * 1024 + k0 + ku]);
            }
            CP_COMMIT();
            asm volatile("cp.async.wait_group 1;" ::: "memory");
        } else {
            asm volatile("cp.async.wait_group 0;" ::: "memory");
        }
        __syncthreads();

        const __nv_bfloat16* bb = sm + buf * SG_BUFE;
        const __nv_bfloat16* AH = bb;
        const __nv_bfloat16* AL = bb + SG_A;
        const __nv_bfloat16* BH = bb + 2 * SG_A;
        const __nv_bfloat16* BL = bb + 3 * SG_A;
#pragma unroll
        for (int kf = 0; kf < 2; kf++) {
            const int koff = kf * 16 + 2 * t;
            unsigned ahi[2][4], alo[2][4];
#pragma unroll
            for (int mi = 0; mi < 2; mi++) {
                int ra = (wm + mi * 16 + g4) * SG_AST + koff;
                ahi[mi][0] = *reinterpret_cast<const unsigned*>(&AH[ra]);
                ahi[mi][1] = *reinterpret_cast<const unsigned*>(&AH[ra + 8 * SG_AST]);
                ahi[mi][2] = *reinterpret_cast<const unsigned*>(&AH[ra + 8]);
                ahi[mi][3] = *reinterpret_cast<const unsigned*>(&AH[ra + 8 * SG_AST + 8]);
                alo[mi][0] = *reinterpret_cast<const unsigned*>(&AL[ra]);
                alo[mi][1] = *reinterpret_cast<const unsigned*>(&AL[ra + 8 * SG_AST]);
                alo[mi][2] = *reinterpret_cast<const unsigned*>(&AL[ra + 8]);
                alo[mi][3] = *reinterpret_cast<const unsigned*>(&AL[ra + 8 * SG_AST + 8]);
            }
#pragma unroll
            for (int nj = 0; nj < 8; nj++) {
                int rb = (wn + nj * 8 + g4) * SG_AST + koff;
                unsigned bhi[2], blo[2];
                bhi[0] = *reinterpret_cast<const unsigned*>(&BH[rb]);
                bhi[1] = *reinterpret_cast<const unsigned*>(&BH[rb + 8]);
                blo[0] = *reinterpret_cast<const unsigned*>(&BL[rb]);
                blo[1] = *reinterpret_cast<const unsigned*>(&BL[rb + 8]);
#pragma unroll
                for (int mi = 0; mi < 2; mi++) {
                    mma_bf16(acc[mi][nj], ahi[mi], bhi);
                    mma_bf16(acc[mi][nj], ahi[mi], blo);
                    mma_bf16(acc[mi][nj], alo[mi], bhi);
                }
            }
        }
        __syncthreads();
        buf ^= 1;
    }

#pragma unroll
    for (int nj = 0; nj < 8; nj++) {
        int c = n0 + wn + nj * 8 + 2 * t;
        float b0v = bias[c], b1v = bias[c + 1];
#pragma unroll
        for (int mi = 0; mi < 2; mi++) {
            int r = m0 + wm + mi * 16 + g4;
            float2 o0 = make_float2(acc[mi][nj][0] + b0v, acc[mi][nj][1] + b1v);
            float2 o1 = make_float2(acc[mi][nj][2] + b0v, acc[mi][nj][3] + b1v);
            *reinterpret_cast<float2*>(&g_pre[(size_t)r * 3072 + gate * 1024 + c]) = o0;
            *reinterpret_cast<float2*>(&g_pre[(size_t)(r + 8) * 3072 + gate * 1024 + c]) = o1;
        }
    }
}

// ---------------------------------------------------------------------------
// Recurrent SMEM layout (unchanged from round 12).
// ---------------------------------------------------------------------------
#define AST2 136
#define ACH  (64 * AST2)
#define WST2 1032
#define SM_WHI   0
#define SM_WLO   66048
#define SM_AHI   132096
#define SM_ALO   166912
#define SM_RED   201728
#define SM_TOTAL 207872

// ---------------------------------------------------------------------------
// MMA tile with 3 independent accumulator chains (da/db/dc per split term).
// ---------------------------------------------------------------------------
template <int NT, int KSEG>
__device__ __forceinline__ void mma_tile(const __nv_bfloat16* __restrict__ AhiG,
                                         const __nv_bfloat16* __restrict__ AloG,
                                         const __nv_bfloat16* __restrict__ WhiS,
                                         const __nv_bfloat16* __restrict__ WloS,
                                         int colBase,
                                         __nv_bfloat16* __restrict__ AhiS,
                                         __nv_bfloat16* __restrict__ AloS,
                                         float* __restrict__ red,
                                         float* __restrict__ d, int tid) {
    const int w = tid >> 5, lane = tid & 31;
    const int g = lane >> 2, t = lane & 3;
    const int mi = w >> 2;
    const int ni = (NT == 2) ? ((w >> 1) & 1) : 0;
    const int ks = w & (KSEG - 1);
    const int SEGK = 128 / KSEG;
    const uint32_t ahi_b = (uint32_t)__cvta_generic_to_shared(AhiS);
    const uint32_t alo_b = (uint32_t)__cvta_generic_to_shared(AloS);

    float da[4] = {0.f, 0.f, 0.f, 0.f};
    float db[4] = {0.f, 0.f, 0.f, 0.f};
    float dc[4] = {0.f, 0.f, 0.f, 0.f};

    // prologue: chunk 0 -> buf 0
#pragma unroll
    for (int p = 0; p < 2; p++) {
        int pos = p * 512 + tid;
        int row = pos >> 4, ku = (pos & 15) << 3;
        uint32_t soff = (uint32_t)(row * AST2 + ku) * 2;
        cpa16(ahi_b + soff, &AhiG[row * 1024 + ku]);
        cpa16(alo_b + soff, &AloG[row * 1024 + ku]);
    }
    CP_COMMIT();

    int buf = 0;
#pragma unroll 1
    for (int ch = 0; ch < 8; ch++) {
        if (ch < 7) {
            const int kb = (ch + 1) << 7;
            const uint32_t hb = ahi_b + (uint32_t)((buf ^ 1) * ACH) * 2;
            const uint32_t lb = alo_b + (uint32_t)((buf ^ 1) * ACH) * 2;
#pragma unroll
            for (int p = 0; p < 2; p++) {
                int pos = p * 512 + tid;
                int row = pos >> 4, ku = (pos & 15) << 3;
                uint32_t soff = (uint32_t)(row * AST2 + ku) * 2;
                cpa16(hb + soff, &AhiG[row * 1024 + kb + ku]);
                cpa16(lb + soff, &AloG[row * 1024 + kb + ku]);
            }
            CP_COMMIT();
            asm volatile("cp.async.wait_group 1;" ::: "memory");
        } else {
            asm volatile("cp.async.wait_group 0;" ::: "memory");
        }
        __syncthreads();

        const __nv_bfloat16* AH = AhiS + buf * ACH;
        const __nv_bfloat16* AL = AloS + buf * ACH;
        const int ar = (mi * 16 + g) * AST2 + ks * SEGK + 2 * t;
        const int wr = (colBase + ni * 8 + g) * WST2 + (ch << 7) + ks * SEGK + 2 * t;
#pragma unroll
        for (int j = 0; j < SEGK / 16; j++) {
            const int ka = ar + j * 16;
            const int kb2 = wr + j * 16;
            unsigned ahi[4], alo[4], bhi[2], blo[2];
            ahi[0] = *reinterpret_cast<const unsigned*>(&AH[ka]);
            ahi[1] = *reinterpret_cast<const unsigned*>(&AH[ka + 8 * AST2]);
            ahi[2] = *reinterpret_cast<const unsigned*>(&AH[ka + 8]);
            ahi[3] = *reinterpret_cast<const unsigned*>(&AH[ka + 8 * AST2 + 8]);
            alo[0] = *reinterpret_cast<const unsigned*>(&AL[ka]);
            alo[1] = *reinterpret_cast<const unsigned*>(&AL[ka + 8 * AST2]);
            alo[2] = *reinterpret_cast<const unsigned*>(&AL[ka + 8]);
            alo[3] = *reinterpret_cast<const unsigned*>(&AL[ka + 8 * AST2 + 8]);
            bhi[0] = *reinterpret_cast<const unsigned*>(&WhiS[kb2]);
            bhi[1] = *reinterpret_cast<const unsigned*>(&WhiS[kb2 + 8]);
            blo[0] = *reinterpret_cast<const unsigned*>(&WloS[kb2]);
            blo[1] = *reinterpret_cast<const unsigned*>(&WloS[kb2 + 8]);
            mma_bf16(da, ahi, bhi);   // 3 independent chains
            mma_bf16(db, ahi, blo);
            mma_bf16(dc, alo, bhi);
        }
        __syncthreads();
        buf ^= 1;
    }

#pragma unroll
    for (int e = 0; e < 4; e++) d[e] = da[e] + (db[e] + dc[e]);

    // reduce k-segments (loop ended with a syncthreads)
    if (ks != 0) {
        float* dst = red + (((mi * NT + ni) * (KSEG - 1) + (ks - 1)) * 32 + lane) * 4;
        dst[0] = d[0]; dst[1] = d[1]; dst[2] = d[2]; dst[3] = d[3];
    }
    __syncthreads();
    if (ks == 0) {
#pragma unroll
        for (int s = 0; s < KSEG - 1; s++) {
            const float* src = red + (((mi * NT + ni) * (KSEG - 1) + s) * 32 + lane) * 4;
            d[0] += src[0]; d[1] += src[1]; d[2] += src[2]; d[3] += src[3];
        }
    }
}

// ---------------------------------------------------------------------------
// Persistent recurrent kernel: 128 blocks x 512 threads, 512 steps.
// Epilogue operands prefetched before each mma_tile (they're phase-invariant).
// ---------------------------------------------------------------------------
__global__ void __launch_bounds__(THR, 1) gru_recurrent(const float* __restrict__ bp,
                                                        float* __restrict__ out) {
    extern __shared__ char smem[];
    __nv_bfloat16* WhiS = reinterpret_cast<__nv_bfloat16*>(smem + SM_WHI);
    __nv_bfloat16* WloS = reinterpret_cast<__nv_bfloat16*>(smem + SM_WLO);
    __nv_bfloat16* AhiS = reinterpret_cast<__nv_bfloat16*>(smem + SM_AHI);
    __nv_bfloat16* AloS = reinterpret_cast<__nv_bfloat16*>(smem + SM_ALO);
    float*         red  = reinterpret_cast<float*>(smem + SM_RED);

    const int tid = threadIdx.x;
    const int bid = blockIdx.x;
    const int w = tid >> 5, lane = tid & 31;
    const int g = lane >> 2, t = lane & 3;

    // Load this block's 32 weight columns (hi+lo) into SMEM once.
    for (int idx = tid; idx < 32 * 128; idx += THR) {
        int i = idx >> 7, ko = (idx & 127) << 3;
        int gc = (i < 16) ? (bid * 16 + i)
               : (i < 24) ? (2048 + bid * 8 + (i - 16))
                          : (3072 + bid * 8 + (i - 24));
        *reinterpret_cast<uint4*>(&WhiS[i * WST2 + ko]) =
            *reinterpret_cast<const uint4*>(&g_whi[(size_t)gc * 1024 + ko]);
        *reinterpret_cast<uint4*>(&WloS[i * WST2 + ko]) =
            *reinterpret_cast<const uint4*>(&g_wlo[(size_t)gc * 1024 + ko]);
    }
    __syncthreads();

    const bool isR = (bid >= 64);
    unsigned ep = 0;
    int p = 0;   // h lives in buffers [p] at step start

#pragma unroll 1
    for (int tt = 0; tt < TT; tt++) {
        const float* h = g_hbuf[p];

        // ---- phase 1: z (bid<64) ; sig(r_pre)*h -> rh hi/lo (bid>=64) ----
        {
            const int mi = w >> 2, ni = (w >> 1) & 1;
            const int cz = (bid << 4) + ni * 8 + 2 * t;
            const int r0 = mi * 16 + g, r1 = r0 + 8;
            float p00 = 0.f, p01 = 0.f, p10 = 0.f, p11 = 0.f;
            float h00 = 0.f, h01 = 0.f, h10 = 0.f, h11 = 0.f;
            if ((w & 1) == 0) {   // prefetch epilogue operands before the GEMM
                p00 = __ldcs(&g_pre[(size_t)(r0 * TT + tt) * 3072 + cz]);
                p01 = __ldcs(&g_pre[(size_t)(r0 * TT + tt) * 3072 + cz + 1]);
                p10 = __ldcs(&g_pre[(size_t)(r1 * TT + tt) * 3072 + cz]);
                p11 = __ldcs(&g_pre[(size_t)(r1 * TT + tt) * 3072 + cz + 1]);
                if (isR) {
                    const int cn = cz - 1024;
                    h00 = __ldcg(&h[r0 * 1024 + cn]);
                    h01 = __ldcg(&h[r0 * 1024 + cn + 1]);
                    h10 = __ldcg(&h[r1 * 1024 + cn]);
                    h11 = __ldcg(&h[r1 * 1024 + cn + 1]);
                }
            }
            float d[4];
            mma_tile<2, 2>(g_hhi[p], g_hlo[p], WhiS, WloS, 0, AhiS, AloS, red, d, tid);
            if ((w & 1) == 0) {
                float v00 = sig_(d[0] + p00);
                float v01 = sig_(d[1] + p01);
                float v10 = sig_(d[2] + p10);
                float v11 = sig_(d[3] + p11);
                if (isR) {
                    const int cn = cz - 1024;
                    unsigned hp, lp;
                    split2(v00 * h00, v01 * h01, hp, lp);
                    __stcg(reinterpret_cast<unsigned*>(&g_rhhi[r0 * 1024 + cn]), hp);
                    __stcg(reinterpret_cast<unsigned*>(&g_rhlo[r0 * 1024 + cn]), lp);
                    split2(v10 * h10, v11 * h11, hp, lp);
                    __stcg(reinterpret_cast<unsigned*>(&g_rhhi[r1 * 1024 + cn]), hp);
                    __stcg(reinterpret_cast<unsigned*>(&g_rhlo[r1 * 1024 + cn]), lp);
                } else {
                    __stcg(&g_z[r0 * 1024 + cz],     v00);
                    __stcg(&g_z[r0 * 1024 + cz + 1], v01);
                    __stcg(&g_z[r1 * 1024 + cz],     v10);
                    __stcg(&g_z[r1 * 1024 + cz + 1], v11);
                }
            }
        }
        grid_barrier(++ep);

        // ---- phase 2: cand + gate combine ----
        const int pn = p ^ 1;
        {
            const int mi = w >> 2;
            const int c0 = (bid << 3) + 2 * t;
            const int r0 = mi * 16 + g, r1 = r0 + 8;
            float ph00 = 0.f, ph01 = 0.f, ph10 = 0.f, ph11 = 0.f;
            float z00 = 0.f, z01 = 0.f, z10 = 0.f, z11 = 0.f;
            float h00 = 0.f, h01 = 0.f, h10 = 0.f, h11 = 0.f;
            if ((w & 3) == 0) {   // prefetch epilogue operands before the GEMM
                ph00 = __ldcs(&g_pre[(size_t)(r0 * TT + tt) * 3072 + 2048 + c0]);
                ph01 = __ldcs(&g_pre[(size_t)(r0 * TT + tt) * 3072 + 2048 + c0 + 1]);
                ph10 = __ldcs(&g_pre[(size_t)(r1 * TT + tt) * 3072 + 2048 + c0]);
                ph11 = __ldcs(&g_pre[(size_t)(r1 * TT + tt) * 3072 + 2048 + c0 + 1]);
                z00 = __ldcg(&g_z[r0 * 1024 + c0]);
                z01 = __ldcg(&g_z[r0 * 1024 + c0 + 1]);
                z10 = __ldcg(&g_z[r1 * 1024 + c0]);
                z11 = __ldcg(&g_z[r1 * 1024 + c0 + 1]);
                h00 = __ldcg(&h[r0 * 1024 + c0]);
                h01 = __ldcg(&h[r0 * 1024 + c0 + 1]);
                h10 = __ldcg(&h[r1 * 1024 + c0]);
                h11 = __ldcg(&h[r1 * 1024 + c0 + 1]);
            }
            float d[4];
            mma_tile<1, 4>(g_rhhi, g_rhlo, WhiS, WloS, 16, AhiS, AloS, red, d, tid);
            if ((w & 3) == 0) {
                float hn00 = fmaf(z00, tanh_(d[0] + ph00) - h00, h00);
                float hn01 = fmaf(z01, tanh_(d[1] + ph01) - h01, h01);
                float hn10 = fmaf(z10, tanh_(d[2] + ph10) - h10, h10);
                float hn11 = fmaf(z11, tanh_(d[3] + ph11) - h11, h11);
                out[(size_t)(r0 * TT + tt) * 1024 + c0]     = hn00;
                out[(size_t)(r0 * TT + tt) * 1024 + c0 + 1] = hn01;
                out[(size_t)(r1 * TT + tt) * 1024 + c0]     = hn10;
                out[(size_t)(r1 * TT + tt) * 1024 + c0 + 1] = hn11;
                __stcg(&g_hbuf[pn][r0 * 1024 + c0],     hn00);
                __stcg(&g_hbuf[pn][r0 * 1024 + c0 + 1], hn01);
                __stcg(&g_hbuf[pn][r1 * 1024 + c0],     hn10);
                __stcg(&g_hbuf[pn][r1 * 1024 + c0 + 1], hn11);
                unsigned hp, lp;
                split2(hn00, hn01, hp, lp);
                __stcg(reinterpret_cast<unsigned*>(&g_hhi[pn][r0 * 1024 + c0]), hp);
                __stcg(reinterpret_cast<unsigned*>(&g_hlo[pn][r0 * 1024 + c0]), lp);
                split2(hn10, hn11, hp, lp);
                __stcg(reinterpret_cast<unsigned*>(&g_hhi[pn][r1 * 1024 + c0]), hp);
                __stcg(reinterpret_cast<unsigned*>(&g_hlo[pn][r1 * 1024 + c0]), lp);
            }
        }
        grid_barrier(++ep);

        // ---- phase 3: chunk-boundary projection ----
        const bool prop = ((tt & 3) == 3) && (tt != TT - 1);
        if (prop) {
            float d[4];
            mma_tile<1, 4>(g_hhi[pn], g_hlo[pn], WhiS, WloS, 24, AhiS, AloS, red, d, tid);
            if ((w & 3) == 0) {
                const int mi = w >> 2;
                const int c0 = (bid << 3) + 2 * t;
                const int r0 = mi * 16 + g, r1 = r0 + 8;
                float bp0 = bp[c0], bp1 = bp[c0 + 1];
                float v00 = tanh_(d[0] + bp0);
                float v01 = tanh_(d[1] + bp1);
                float v10 = tanh_(d[2] + bp0);
                float v11 = tanh_(d[3] + bp1);
                __stcg(&g_hbuf[p][r0 * 1024 + c0],     v00);
                __stcg(&g_hbuf[p][r0 * 1024 + c0 + 1], v01);
                __stcg(&g_hbuf[p][r1 * 1024 + c0],     v10);
                __stcg(&g_hbuf[p][r1 * 1024 + c0 + 1], v11);
                unsigned hp, lp;
                split2(v00, v01, hp, lp);
                __stcg(reinterpret_cast<unsigned*>(&g_hhi[p][r0 * 1024 + c0]), hp);
                __stcg(reinterpret_cast<unsigned*>(&g_hlo[p][r0 * 1024 + c0]), lp);
                split2(v10, v11, hp, lp);
                __stcg(reinterpret_cast<unsigned*>(&g_hhi[p][r1 * 1024 + c0]), hp);
                __stcg(reinterpret_cast<unsigned*>(&g_hlo[p][r1 * 1024 + c0]), lp);
            }
            grid_barrier(++ep);
            // h stays in buffers [p]
        } else {
            p ^= 1;
        }
    }
}

// ---------------------------------------------------------------------------
extern "C" void kernel_launch(void* const* d_in, const int* in_sizes, int n_in,
                              void* d_out, int out_size) {
    (void)in_sizes; (void)n_in; (void)out_size;
    const float* x  = (const float*)d_in[0];
    const float* h0 = (const float*)d_in[1];
    const float* Wz = (const float*)d_in[2];
    const float* bz = (const float*)d_in[3];
    const float* Wr = (const float*)d_in[4];
    const float* br = (const float*)d_in[5];
    const float* Wh = (const float*)d_in[6];
    const float* bh = (const float*)d_in[7];
    const float* Wp = (const float*)d_in[8];
    const float* bp = (const float*)d_in[9];
    float* out = (float*)d_out;

    static bool attr_set = false;
    if (!attr_set) {
        cudaFuncSetAttribute(gru_recurrent, cudaFuncAttributeMaxDynamicSharedMemorySize,
                             SM_TOTAL);
        cudaFuncSetAttribute(sgemm_pre_mma, cudaFuncAttributeMaxDynamicSharedMemorySize,
                             SG_SMEM_BYTES);
        attr_set = true;
    }

    transpose_weights<<<dim3(32, 32, 7), dim3(32, 32)>>>(Wz, Wr, Wh, Wp);
    split_weights<<<14336, 512>>>();
    split_x<<<65536, 512>>>(x);
    init_h<<<64, 1024>>>(h0);
    sgemm_pre_mma<<<dim3(8, 256, 3), 256, SG_SMEM_BYTES>>>(bz, br, bh);
    gru_recurrent<<<NB, THR, SM_TOTAL>>>(bp, out);
}

// round 14
// speedup vs baseline: 9.0186x; 1.3068x over previous
#include <cuda_runtime.h>
#include <cuda_bf16.h>
#include <cuda_fp16.h>
#include <cstdint>

// ---------------------------------------------------------------------------
// ChunkParallelGRU: B=64, T=512, D=1024, H=1024, CHUNK=4
//
//   pre[g][m][n] = x[m] @ Wg_x + bg                (bf16 3-term MMA GEMM)
//   per step t (sequential, persistent kernel):
//     P1: z = sig(pre_z + h @ Wz_h)          -> g_z    (blocks 0..63)
//         rh = sig(pre_r + h @ Wr_h) * h     -> rh fp16 (blocks 64..127)
//     P2: cand = tanh(pre_h + rh @ Wh_h);
//         h_new = h + z*(cand-h); out[t] = h_new
//     P3 (chunk boundary): h = tanh(h_new @ Wp + bp)
//
// v11 = v10 with recurrent GEMMs on fp16: A single fp16 array (2B/elem,
//       HALF the L2 broadcast traffic), W fp16 hi/lo, 2 MMA terms.
//       K-chunks 128->256 (4 chunks/phase). sgemm_pre stays bf16 3-term.
// ---------------------------------------------------------------------------

#define BB 64
#define TT 512
#define BT (BB * 512)
#define NB 128          // persistent grid (<=148 SMs -> co-resident)
#define THR 512

// Scratch (static device arrays; allocation-free)
__device__ float g_pre[(size_t)BT * 3072];            // [m][z|r|h]
__device__ float g_wt_all[(size_t)7168 * 1024];       // transposed fp32 weights
__device__ __nv_bfloat16 g_whi[(size_t)7168 * 1024];  // bf16 hi (x-parts used by sgemm)
__device__ __nv_bfloat16 g_wlo[(size_t)7168 * 1024];  // bf16 lo
__device__ __half g_w16h[(size_t)4096 * 1024];        // fp16 hi of h-part weights [zr|h|p]
__device__ __half g_w16l[(size_t)4096 * 1024];        // fp16 lo
__device__ __nv_bfloat16 g_xhi[(size_t)BT * 1024];    // bf16 hi of x
__device__ __nv_bfloat16 g_xlo[(size_t)BT * 1024];
__device__ float g_hbuf[2][BB * 1024];                // fp32 state (epilogue reads)
__device__ __half g_h16[2][BB * 1024];                // fp16 state (MMA A)
__device__ __half g_rh16[BB * 1024];                  // fp16 sig(r)*h
__device__ float g_z[BB * 1024];                      // sigmoided z
__device__ unsigned g_ctr;                            // barrier counter (monotonic)

__device__ __forceinline__ float sig_(float x) {
    return 1.0f / (1.0f + __expf(-x));
}
__device__ __forceinline__ float tanh_(float x) {
    x = fminf(15.0f, fmaxf(-15.0f, x));
    float e = __expf(-2.0f * x);
    return (1.0f - e) / (1.0f + e);
}

// bf16 MMA (sgemm_pre): D(16x8,f32) += A(16x16)*B(16x8)
__device__ __forceinline__ void mma_bf16(float* d, const unsigned* a, const unsigned* b) {
    asm volatile(
        "mma.sync.aligned.m16n8k16.row.col.f32.bf16.bf16.f32 "
        "{%0,%1,%2,%3}, {%4,%5,%6,%7}, {%8,%9}, {%0,%1,%2,%3};\n"
        : "+f"(d[0]), "+f"(d[1]), "+f"(d[2]), "+f"(d[3])
        : "r"(a[0]), "r"(a[1]), "r"(a[2]), "r"(a[3]), "r"(b[0]), "r"(b[1]));
}

// fp16 MMA (recurrent): D(16x8,f32) += A(16x16,f16)*B(16x8,f16)
__device__ __forceinline__ void mma_f16(float* d, const unsigned* a, const unsigned* b) {
    asm volatile(
        "mma.sync.aligned.m16n8k16.row.col.f32.f16.f16.f32 "
        "{%0,%1,%2,%3}, {%4,%5,%6,%7}, {%8,%9}, {%0,%1,%2,%3};\n"
        : "+f"(d[0]), "+f"(d[1]), "+f"(d[2]), "+f"(d[3])
        : "r"(a[0]), "r"(a[1]), "r"(a[2]), "r"(a[3]), "r"(b[0]), "r"(b[1]));
}

// pack two floats to fp16x2 word (low = a, high = b)
__device__ __forceinline__ unsigned packh2(float a, float b) {
    __half2 p = __floats2half2_rn(a, b);
    return *reinterpret_cast<unsigned*>(&p);
}

// cp.async 16B via L2 (bypasses L1)
__device__ __forceinline__ void cpa16(uint32_t s, const void* g) {
    asm volatile("cp.async.cg.shared.global [%0], [%1], 16;" :: "r"(s), "l"(g) : "memory");
}
#define CP_COMMIT() asm volatile("cp.async.commit_group;" ::: "memory")

// ---------------------------------------------------------------------------
// Grid barrier (round-6, known good).
// ---------------------------------------------------------------------------
__device__ __forceinline__ void grid_barrier(unsigned ep) {
    __syncthreads();
    if (threadIdx.x == 0) {
        asm volatile("red.release.gpu.global.add.u32 [%0], 1;"
                     :: "l"(&g_ctr) : "memory");
        const unsigned target = ep * NB;
        unsigned v;
        do {
            asm volatile("ld.acquire.gpu.global.u32 %0, [%1];"
                         : "=r"(v) : "l"(&g_ctr) : "memory");
        } while ((int)(v - target) < 0);
    }
    __syncthreads();
}

// ---------------------------------------------------------------------------
// Weight transpose into unified array: g_wt_all[z*1024 + n][k] = src[off+k][n]
// ---------------------------------------------------------------------------
__global__ void transpose_weights(const float* __restrict__ Wz,
                                  const float* __restrict__ Wr,
                                  const float* __restrict__ Wh,
                                  const float* __restrict__ Wp) {
    __shared__ float tile[32][33];
    const int z = blockIdx.z;
    const float* src;
    int srcOff;
    switch (z) {
        case 0: src = Wz; srcOff = 1024; break;
        case 1: src = Wr; srcOff = 1024; break;
        case 2: src = Wh; srcOff = 1024; break;
        case 3: src = Wp; srcOff = 0;    break;
        case 4: src = Wz; srcOff = 0;    break;
        case 5: src = Wr; srcOff = 0;    break;
        default: src = Wh; srcOff = 0;   break;
    }
    float* dst = g_wt_all + (size_t)z * 1024 * 1024;
    const int kBase = blockIdx.x * 32;
    const int cBase = blockIdx.y * 32;
    tile[threadIdx.y][threadIdx.x] =
        src[(size_t)(srcOff + kBase + threadIdx.y) * 1024 + cBase + threadIdx.x];
    __syncthreads();
    dst[(size_t)(cBase + threadIdx.y) * 1024 + kBase + threadIdx.x] =
        tile[threadIdx.x][threadIdx.y];
}

__global__ void split_weights() {
    size_t i = (size_t)blockIdx.x * blockDim.x + threadIdx.x;
    if (i >= (size_t)7168 * 1024) return;
    float v = g_wt_all[i];
    __nv_bfloat16 hi = __float2bfloat16_rn(v);
    g_whi[i] = hi;
    g_wlo[i] = __float2bfloat16_rn(v - __bfloat162float(hi));
    if (i < (size_t)4096 * 1024) {        // fp16 split of h-part weights
        __half h16 = __float2half_rn(v);
        g_w16h[i] = h16;
        g_w16l[i] = __float2half_rn(v - __half2float(h16));
    }
}

__global__ void split_x(const float* __restrict__ x) {
    size_t i = (size_t)blockIdx.x * blockDim.x + threadIdx.x;
    if (i >= (size_t)BT * 1024) return;
    float v = x[i];
    __nv_bfloat16 hi = __float2bfloat16_rn(v);
    g_xhi[i] = hi;
    g_xlo[i] = __float2bfloat16_rn(v - __bfloat162float(hi));
}

__global__ void init_h(const float* __restrict__ h0) {
    int i = blockIdx.x * blockDim.x + threadIdx.x;
    if (i == 0) g_ctr = 0u;
    if (i < BB * 1024) {
        float v = h0[i];
        g_hbuf[0][i] = v;
        g_h16[0][i] = __float2half_rn(v);
    }
}

// ---------------------------------------------------------------------------
// Precompute GEMM on bf16 MMA (unchanged, round-11 proven).
// ---------------------------------------------------------------------------
#define SG_AST 40
#define SG_A   (128 * SG_AST)
#define SG_BUFE (4 * SG_A)
#define SG_SMEM_BYTES (2 * SG_BUFE * 2)

__global__ void __launch_bounds__(256, 1) sgemm_pre_mma(
    const float* __restrict__ bz, const float* __restrict__ br,
    const float* __restrict__ bh) {
    extern __shared__ __nv_bfloat16 sm[];
    const int gate = blockIdx.z;
    const int m0 = blockIdx.y * 128;
    const int n0 = blockIdx.x * 128;
    const float* bias = (gate == 0) ? bz : (gate == 1) ? br : bh;
    const size_t wrow = (size_t)(4096 + gate * 1024 + n0) * 1024;

    const int tid = threadIdx.x;
    const int w = tid >> 5, lane = tid & 31, g4 = lane >> 2, t = lane & 3;
    const int wm = (w & 3) * 32, wn = (w >> 2) * 64;
    const uint32_t smb = (uint32_t)__cvta_generic_to_shared(sm);

    float acc[2][8][4];
#pragma unroll
    for (int i = 0; i < 2; i++)
#pragma unroll
        for (int j = 0; j < 8; j++)
#pragma unroll
            for (int e = 0; e < 4; e++) acc[i][j][e] = 0.0f;

#pragma unroll
    for (int q = 0; q < 2; q++) {
        int pos = q * 256 + tid;
        int row = pos >> 2, ku = (pos & 3) * 8;
        uint32_t soff = (uint32_t)(row * SG_AST + ku) * 2;
        cpa16(smb + 0 * SG_A * 2 + soff, &g_xhi[(size_t)(m0 + row) * 1024 + ku]);
        cpa16(smb + 1 * SG_A * 2 + soff, &g_xlo[(size_t)(m0 + row) * 1024 + ku]);
        cpa16(smb + 2 * SG_A * 2 + soff, &g_whi[wrow + (size_t)row * 1024 + ku]);
        cpa16(smb + 3 * SG_A * 2 + soff, &g_wlo[wrow + (size_t)row * 1024 + ku]);
    }
    CP_COMMIT();

    int buf = 0;
#pragma unroll 1
    for (int ch = 0; ch < 32; ch++) {
        const bool hasNext = (ch < 31);
        if (hasNext) {
            const int k0 = (ch + 1) * 32;
            const uint32_t b0 = smb + (uint32_t)((buf ^ 1) * SG_BUFE) * 2;
#pragma unroll
            for (int q = 0; q < 2; q++) {
                int pos = q * 256 + tid;
                int row = pos >> 2, ku = (pos & 3) * 8;
                uint32_t soff = (uint32_t)(row * SG_AST + ku) * 2;
                cpa16(b0 + 0 * SG_A * 2 + soff, &g_xhi[(size_t)(m0 + row) * 1024 + k0 + ku]);
                cpa16(b0 + 1 * SG_A * 2 + soff, &g_xlo[(size_t)(m0 + row) * 1024 + k0 + ku]);
                cpa16(b0 + 2 * SG_A * 2 + soff, &g_whi[wrow + (size_t)row * 1024 + k0 + ku]);
                cpa16(b0 + 3 * SG_A * 2 + soff, &g_wlo[wrow + (size_t)row * 1024 + k0 + ku]);
            }
            CP_COMMIT();
            asm volatile("cp.async.wait_group 1;" ::: "memory");
        } else {
            asm volatile("cp.async.wait_group 0;" ::: "memory");
        }
        __syncthreads();

        const __nv_bfloat16* bb = sm + buf * SG_BUFE;
        const __nv_bfloat16* AH = bb;
        const __nv_bfloat16* AL = bb + SG_A;
        const __nv_bfloat16* BH = bb + 2 * SG_A;
        const __nv_bfloat16* BL = bb + 3 * SG_A;
#pragma unroll
        for (int kf = 0; kf < 2; kf++) {
            const int koff = kf * 16 + 2 * t;
            unsigned ahi[2][4], alo[2][4];
#pragma unroll
            for (int mi = 0; mi < 2; mi++) {
                int ra = (wm + mi * 16 + g4) * SG_AST + koff;
                ahi[mi][0] = *reinterpret_cast<const unsigned*>(&AH[ra]);
                ahi[mi][1] = *reinterpret_cast<const unsigned*>(&AH[ra + 8 * SG_AST]);
                ahi[mi][2] = *reinterpret_cast<const unsigned*>(&AH[ra + 8]);
                ahi[mi][3] = *reinterpret_cast<const unsigned*>(&AH[ra + 8 * SG_AST + 8]);
                alo[mi][0] = *reinterpret_cast<const unsigned*>(&AL[ra]);
                alo[mi][1] = *reinterpret_cast<const unsigned*>(&AL[ra + 8 * SG_AST]);
                alo[mi][2] = *reinterpret_cast<const unsigned*>(&AL[ra + 8]);
                alo[mi][3] = *reinterpret_cast<const unsigned*>(&AL[ra + 8 * SG_AST + 8]);
            }
#pragma unroll
            for (int nj = 0; nj < 8; nj++) {
                int rb = (wn + nj * 8 + g4) * SG_AST + koff;
                unsigned bhi[2], blo[2];
                bhi[0] = *reinterpret_cast<const unsigned*>(&BH[rb]);
                bhi[1] = *reinterpret_cast<const unsigned*>(&BH[rb + 8]);
                blo[0] = *reinterpret_cast<const unsigned*>(&BL[rb]);
                blo[1] = *reinterpret_cast<const unsigned*>(&BL[rb + 8]);
#pragma unroll
                for (int mi = 0; mi < 2; mi++) {
                    mma_bf16(acc[mi][nj], ahi[mi], bhi);
                    mma_bf16(acc[mi][nj], ahi[mi], blo);
                    mma_bf16(acc[mi][nj], alo[mi], bhi);
                }
            }
        }
        __syncthreads();
        buf ^= 1;
    }

#pragma unroll
    for (int nj = 0; nj < 8; nj++) {
        int c = n0 + wn + nj * 8 + 2 * t;
        float b0v = bias[c], b1v = bias[c + 1];
#pragma unroll
        for (int mi = 0; mi < 2; mi++) {
            int r = m0 + wm + mi * 16 + g4;
            float2 o0 = make_float2(acc[mi][nj][0] + b0v, acc[mi][nj][1] + b1v);
            float2 o1 = make_float2(acc[mi][nj][2] + b0v, acc[mi][nj][3] + b1v);
            *reinterpret_cast<float2*>(&g_pre[(size_t)r * 3072 + gate * 1024 + c]) = o0;
            *reinterpret_cast<float2*>(&g_pre[(size_t)(r + 8) * 3072 + gate * 1024 + c]) = o1;
        }
    }
}

// ---------------------------------------------------------------------------
// Recurrent SMEM layout. A = one fp16 array, K=256 chunks, double buffered.
//   AST2=264 fp16 row stride (528 B = 132 words == 4 mod 32: conflict-free).
// ---------------------------------------------------------------------------
#define AST2 264
#define ACH  (64 * AST2)
#define WST2 1032
#define SM_W16H  0                        // 32*1032*2 = 66048
#define SM_W16L  66048                    //           = 66048
#define SM_A     132096                   // 2*ACH*2   = 67584
#define SM_RED   199680                   // float[1536] = 6144
#define SM_TOTAL 205824

// ---------------------------------------------------------------------------
// fp16 MMA tile: C(64 x NT*8) = A16(64x1024 global fp16) @ W(fp16 hi/lo smem).
// 2 independent accumulator chains. cp.async double-buffered K=256 chunks.
// ---------------------------------------------------------------------------
template <int NT, int KSEG>
__device__ __forceinline__ void mma_tile16(const __half* __restrict__ AG,
                                           const __half* __restrict__ WhS,
                                           const __half* __restrict__ WlS,
                                           int colBase,
                                           __half* __restrict__ AS,
                                           float* __restrict__ red,
                                           float* __restrict__ d, int tid) {
    const int w = tid >> 5, lane = tid & 31;
    const int g = lane >> 2, t = lane & 3;
    const int mi = w >> 2;
    const int ni = (NT == 2) ? ((w >> 1) & 1) : 0;
    const int ks = w & (KSEG - 1);
    const int SEGK = 256 / KSEG;
    const uint32_t as_b = (uint32_t)__cvta_generic_to_shared(AS);

    float da[4] = {0.f, 0.f, 0.f, 0.f};
    float db[4] = {0.f, 0.f, 0.f, 0.f};

    // prologue: chunk 0 -> buf 0 (64 rows x 256 k fp16 = 32KB; 4 cpa/thread)
#pragma unroll
    for (int p = 0; p < 4; p++) {
        int pos = p * 512 + tid;
        int row = pos >> 5, ku = (pos & 31) << 3;
        cpa16(as_b + (uint32_t)(row * AST2 + ku) * 2, &AG[row * 1024 + ku]);
    }
    CP_COMMIT();

    int buf = 0;
#pragma unroll 1
    for (int ch = 0; ch < 4; ch++) {
        if (ch < 3) {
            const int kb = (ch + 1) << 8;
            const uint32_t bb = as_b + (uint32_t)((buf ^ 1) * ACH) * 2;
#pragma unroll
            for (int p = 0; p < 4; p++) {
                int pos = p * 512 + tid;
                int row = pos >> 5, ku = (pos & 31) << 3;
                cpa16(bb + (uint32_t)(row * AST2 + ku) * 2, &AG[row * 1024 + kb + ku]);
            }
            CP_COMMIT();
            asm volatile("cp.async.wait_group 1;" ::: "memory");
        } else {
            asm volatile("cp.async.wait_group 0;" ::: "memory");
        }
        __syncthreads();

        const __half* AH = AS + buf * ACH;
        const int ar = (mi * 16 + g) * AST2 + ks * SEGK + 2 * t;
        const int wr = (colBase + ni * 8 + g) * WST2 + (ch << 8) + ks * SEGK + 2 * t;
#pragma unroll
        for (int j = 0; j < SEGK / 16; j++) {
            const int ka = ar + j * 16;
            const int kw = wr + j * 16;
            unsigned a[4], bh[2], bl[2];
            a[0] = *reinterpret_cast<const unsigned*>(&AH[ka]);
            a[1] = *reinterpret_cast<const unsigned*>(&AH[ka + 8 * AST2]);
            a[2] = *reinterpret_cast<const unsigned*>(&AH[ka + 8]);
            a[3] = *reinterpret_cast<const unsigned*>(&AH[ka + 8 * AST2 + 8]);
            bh[0] = *reinterpret_cast<const unsigned*>(&WhS[kw]);
            bh[1] = *reinterpret_cast<const unsigned*>(&WhS[kw + 8]);
            bl[0] = *reinterpret_cast<const unsigned*>(&WlS[kw]);
            bl[1] = *reinterpret_cast<const unsigned*>(&WlS[kw + 8]);
            mma_f16(da, a, bh);   // 2 independent chains
            mma_f16(db, a, bl);
        }
        __syncthreads();
        buf ^= 1;
    }

#pragma unroll
    for (int e = 0; e < 4; e++) d[e] = da[e] + db[e];

    // reduce k-segments
    if (ks != 0) {
        float* dst = red + (((mi * NT + ni) * (KSEG - 1) + (ks - 1)) * 32 + lane) * 4;
        dst[0] = d[0]; dst[1] = d[1]; dst[2] = d[2]; dst[3] = d[3];
    }
    __syncthreads();
    if (ks == 0) {
#pragma unroll
        for (int s = 0; s < KSEG - 1; s++) {
            const float* src = red + (((mi * NT + ni) * (KSEG - 1) + s) * 32 + lane) * 4;
            d[0] += src[0]; d[1] += src[1]; d[2] += src[2]; d[3] += src[3];
        }
    }
}

// ---------------------------------------------------------------------------
// Persistent recurrent kernel: 128 blocks x 512 threads, 512 steps.
// ---------------------------------------------------------------------------
__global__ void __launch_bounds__(THR, 1) gru_recurrent(const float* __restrict__ bp,
                                                        float* __restrict__ out) {
    extern __shared__ char smem[];
    __half* WhS = reinterpret_cast<__half*>(smem + SM_W16H);
    __half* WlS = reinterpret_cast<__half*>(smem + SM_W16L);
    __half* AS  = reinterpret_cast<__half*>(smem + SM_A);
    float*  red = reinterpret_cast<float*>(smem + SM_RED);

    const int tid = threadIdx.x;
    const int bid = blockIdx.x;
    const int w = tid >> 5, lane = tid & 31;
    const int g = lane >> 2, t = lane & 3;

    // Load this block's 32 weight columns (fp16 hi+lo) into SMEM once.
    for (int idx = tid; idx < 32 * 128; idx += THR) {
        int i = idx >> 7, ko = (idx & 127) << 3;
        int gc = (i < 16) ? (bid * 16 + i)
               : (i < 24) ? (2048 + bid * 8 + (i - 16))
                          : (3072 + bid * 8 + (i - 24));
        *reinterpret_cast<uint4*>(&WhS[i * WST2 + ko]) =
            *reinterpret_cast<const uint4*>(&g_w16h[(size_t)gc * 1024 + ko]);
        *reinterpret_cast<uint4*>(&WlS[i * WST2 + ko]) =
            *reinterpret_cast<const uint4*>(&g_w16l[(size_t)gc * 1024 + ko]);
    }
    __syncthreads();

    const bool isR = (bid >= 64);
    unsigned ep = 0;
    int p = 0;   // h lives in buffers [p] at step start

#pragma unroll 1
    for (int tt = 0; tt < TT; tt++) {
        const float* h = g_hbuf[p];

        // ---- phase 1: z (bid<64) ; sig(r_pre)*h -> rh fp16 (bid>=64) ----
        {
            const int mi = w >> 2, ni = (w >> 1) & 1;
            const int cz = (bid << 4) + ni * 8 + 2 * t;
            const int r0 = mi * 16 + g, r1 = r0 + 8;
            float p00 = 0.f, p01 = 0.f, p10 = 0.f, p11 = 0.f;
            float h00 = 0.f, h01 = 0.f, h10 = 0.f, h11 = 0.f;
            if ((w & 1) == 0) {   // prefetch epilogue operands
                p00 = __ldcs(&g_pre[(size_t)(r0 * TT + tt) * 3072 + cz]);
                p01 = __ldcs(&g_pre[(size_t)(r0 * TT + tt) * 3072 + cz + 1]);
                p10 = __ldcs(&g_pre[(size_t)(r1 * TT + tt) * 3072 + cz]);
                p11 = __ldcs(&g_pre[(size_t)(r1 * TT + tt) * 3072 + cz + 1]);
                if (isR) {
                    const int cn = cz - 1024;
                    h00 = __ldcg(&h[r0 * 1024 + cn]);
                    h01 = __ldcg(&h[r0 * 1024 + cn + 1]);
                    h10 = __ldcg(&h[r1 * 1024 + cn]);
                    h11 = __ldcg(&h[r1 * 1024 + cn + 1]);
                }
            }
            float d[4];
            mma_tile16<2, 2>(g_h16[p], WhS, WlS, 0, AS, red, d, tid);
            if ((w & 1) == 0) {
                float v00 = sig_(d[0] + p00);
                float v01 = sig_(d[1] + p01);
                float v10 = sig_(d[2] + p10);
                float v11 = sig_(d[3] + p11);
                if (isR) {
                    const int cn = cz - 1024;
                    __stcg(reinterpret_cast<unsigned*>(&g_rh16[r0 * 1024 + cn]),
                           packh2(v00 * h00, v01 * h01));
                    __stcg(reinterpret_cast<unsigned*>(&g_rh16[r1 * 1024 + cn]),
                           packh2(v10 * h10, v11 * h11));
                } else {
                    __stcg(&g_z[r0 * 1024 + cz],     v00);
                    __stcg(&g_z[r0 * 1024 + cz + 1], v01);
                    __stcg(&g_z[r1 * 1024 + cz],     v10);
                    __stcg(&g_z[r1 * 1024 + cz + 1], v11);
                }
            }
        }
        grid_barrier(++ep);

        // ---- phase 2: cand + gate combine ----
        const int pn = p ^ 1;
        {
            const int mi = w >> 2;
            const int c0 = (bid << 3) + 2 * t;
            const int r0 = mi * 16 + g, r1 = r0 + 8;
            float ph00 = 0.f, ph01 = 0.f, ph10 = 0.f, ph11 = 0.f;
            float z00 = 0.f, z01 = 0.f, z10 = 0.f, z11 = 0.f;
            float h00 = 0.f, h01 = 0.f, h10 = 0.f, h11 = 0.f;
            if ((w & 3) == 0) {   // prefetch epilogue operands
                ph00 = __ldcs(&g_pre[(size_t)(r0 * TT + tt) * 3072 + 2048 + c0]);
                ph01 = __ldcs(&g_pre[(size_t)(r0 * TT + tt) * 3072 + 2048 + c0 + 1]);
                ph10 = __ldcs(&g_pre[(size_t)(r1 * TT + tt) * 3072 + 2048 + c0]);
                ph11 = __ldcs(&g_pre[(size_t)(r1 * TT + tt) * 3072 + 2048 + c0 + 1]);
                z00 = __ldcg(&g_z[r0 * 1024 + c0]);
                z01 = __ldcg(&g_z[r0 * 1024 + c0 + 1]);
                z10 = __ldcg(&g_z[r1 * 1024 + c0]);
                z11 = __ldcg(&g_z[r1 * 1024 + c0 + 1]);
                h00 = __ldcg(&h[r0 * 1024 + c0]);
                h01 = __ldcg(&h[r0 * 1024 + c0 + 1]);
                h10 = __ldcg(&h[r1 * 1024 + c0]);
                h11 = __ldcg(&h[r1 * 1024 + c0 + 1]);
            }
            float d[4];
            mma_tile16<1, 4>(g_rh16, WhS, WlS, 16, AS, red, d, tid);
            if ((w & 3) == 0) {
                float hn00 = fmaf(z00, tanh_(d[0] + ph00) - h00, h00);
                float hn01 = fmaf(z01, tanh_(d[1] + ph01) - h01, h01);
                float hn10 = fmaf(z10, tanh_(d[2] + ph10) - h10, h10);
                float hn11 = fmaf(z11, tanh_(d[3] + ph11) - h11, h11);
                out[(size_t)(r0 * TT + tt) * 1024 + c0]     = hn00;
                out[(size_t)(r0 * TT + tt) * 1024 + c0 + 1] = hn01;
                out[(size_t)(r1 * TT + tt) * 1024 + c0]     = hn10;
                out[(size_t)(r1 * TT + tt) * 1024 + c0 + 1] = hn11;
                __stcg(&g_hbuf[pn][r0 * 1024 + c0],     hn00);
                __stcg(&g_hbuf[pn][r0 * 1024 + c0 + 1], hn01);
                __stcg(&g_hbuf[pn][r1 * 1024 + c0],     hn10);
                __stcg(&g_hbuf[pn][r1 * 1024 + c0 + 1], hn11);
                __stcg(reinterpret_cast<unsigned*>(&g_h16[pn][r0 * 1024 + c0]),
                       packh2(hn00, hn01));
                __stcg(reinterpret_cast<unsigned*>(&g_h16[pn][r1 * 1024 + c0]),
                       packh2(hn10, hn11));
            }
        }
        grid_barrier(++ep);

        // ---- phase 3: chunk-boundary projection ----
        const bool prop = ((tt & 3) == 3) && (tt != TT - 1);
        if (prop) {
            float d[4];
            mma_tile16<1, 4>(g_h16[pn], WhS, WlS, 24, AS, red, d, tid);
            if ((w & 3) == 0) {
                const int mi = w >> 2;
                const int c0 = (bid << 3) + 2 * t;
                const int r0 = mi * 16 + g, r1 = r0 + 8;
                float bp0 = bp[c0], bp1 = bp[c0 + 1];
                float v00 = tanh_(d[0] + bp0);
                float v01 = tanh_(d[1] + bp1);
                float v10 = tanh_(d[2] + bp0);
                float v11 = tanh_(d[3] + bp1);
                __stcg(&g_hbuf[p][r0 * 1024 + c0],     v00);
                __stcg(&g_hbuf[p][r0 * 1024 + c0 + 1], v01);
                __stcg(&g_hbuf[p][r1 * 1024 + c0],     v10);
                __stcg(&g_hbuf[p][r1 * 1024 + c0 + 1], v11);
                __stcg(reinterpret_cast<unsigned*>(&g_h16[p][r0 * 1024 + c0]),
                       packh2(v00, v01));
                __stcg(reinterpret_cast<unsigned*>(&g_h16[p][r1 * 1024 + c0]),
                       packh2(v10, v11));
            }
            grid_barrier(++ep);
            // h stays in buffers [p]
        } else {
            p ^= 1;
        }
    }
}

// ---------------------------------------------------------------------------
extern "C" void kernel_launch(void* const* d_in, const int* in_sizes, int n_in,
                              void* d_out, int out_size) {
    (void)in_sizes; (void)n_in; (void)out_size;
    const float* x  = (const float*)d_in[0];
    const float* h0 = (const float*)d_in[1];
    const float* Wz = (const float*)d_in[2];
    const float* bz = (const float*)d_in[3];
    const float* Wr = (const float*)d_in[4];
    const float* br = (const float*)d_in[5];
    const float* Wh = (const float*)d_in[6];
    const float* bh = (const float*)d_in[7];
    const float* Wp = (const float*)d_in[8];
    const float* bp = (const float*)d_in[9];
    float* out = (float*)d_out;

    static bool attr_set = false;
    if (!attr_set) {
        cudaFuncSetAttribute(gru_recurrent, cudaFuncAttributeMaxDynamicSharedMemorySize,
                             SM_TOTAL);
        cudaFuncSetAttribute(sgemm_pre_mma, cudaFuncAttributeMaxDynamicSharedMemorySize,
                             SG_SMEM_BYTES);
        attr_set = true;
    }

    transpose_weights<<<dim3(32, 32, 7), dim3(32, 32)>>>(Wz, Wr, Wh, Wp);
    split_weights<<<14336, 512>>>();
    split_x<<<65536, 512>>>(x);
    init_h<<<64, 1024>>>(h0);
    sgemm_pre_mma<<<dim3(8, 256, 3), 256, SG_SMEM_BYTES>>>(bz, br, bh);
    gru_recurrent<<<NB, THR, SM_TOTAL>>>(bp, out);
}

// round 15
// speedup vs baseline: 10.2906x; 1.1410x over previous
#include <cuda_runtime.h>
#include <cuda_fp16.h>
#include <cstdint>

// ---------------------------------------------------------------------------
// ChunkParallelGRU: B=64, T=512, D=1024, H=1024, CHUNK=4
//
//   pre[g][m][n] = x[m] @ Wg_x + bg          (fp16 2-term MMA GEMM)
//   per step t (sequential, persistent kernel):
//     P1: z = sig(pre_z + h @ Wz_h)          -> g_z    (blocks 0..63)
//         rh = sig(pre_r + h @ Wr_h) * h     -> rh fp16 (blocks 64..127)
//     P2: cand = tanh(pre_h + rh @ Wh_h);
//         h_new = h + z*(cand-h); out[t] = h_new
//     P3 (chunk boundary): h = tanh(h_new @ Wp + bp)
//
// v12 = v11 with (a) recurrent W single fp16 term (A-fp16 error already
//       dominates; MMA halves, K-chunks 256->512), (b) pre GEMM on fp16
//       A-single + W hi/lo 2-term (same validated error structure).
// ---------------------------------------------------------------------------

#define BB 64
#define TT 512
#define BT (BB * 512)
#define NB 128          // persistent grid (<=148 SMs -> co-resident)
#define THR 512

// Scratch (static device arrays; allocation-free)
__device__ float g_pre[(size_t)BT * 3072];            // [m][z|r|h]
__device__ float g_wt_all[(size_t)7168 * 1024];       // transposed fp32 weights
__device__ __half g_w16h[(size_t)7168 * 1024];        // fp16 hi: [zr_h|h_h|p|z_x|r_x|h_x]
__device__ __half g_w16l[(size_t)7168 * 1024];        // fp16 lo (used by pre GEMM)
__device__ __half g_x16[(size_t)BT * 1024];           // fp16 x
__device__ float g_hbuf[2][BB * 1024];                // fp32 state (epilogue reads)
__device__ __half g_h16[2][BB * 1024];                // fp16 state (MMA A)
__device__ __half g_rh16[BB * 1024];                  // fp16 sig(r)*h
__device__ float g_z[BB * 1024];                      // sigmoided z
__device__ unsigned g_ctr;                            // barrier counter (monotonic)

__device__ __forceinline__ float sig_(float x) {
    return 1.0f / (1.0f + __expf(-x));
}
__device__ __forceinline__ float tanh_(float x) {
    x = fminf(15.0f, fmaxf(-15.0f, x));
    float e = __expf(-2.0f * x);
    return (1.0f - e) / (1.0f + e);
}

// fp16 MMA: D(16x8,f32) += A(16x16,f16)*B(16x8,f16)
__device__ __forceinline__ void mma_f16(float* d, const unsigned* a, const unsigned* b) {
    asm volatile(
        "mma.sync.aligned.m16n8k16.row.col.f32.f16.f16.f32 "
        "{%0,%1,%2,%3}, {%4,%5,%6,%7}, {%8,%9}, {%0,%1,%2,%3};\n"
        : "+f"(d[0]), "+f"(d[1]), "+f"(d[2]), "+f"(d[3])
        : "r"(a[0]), "r"(a[1]), "r"(a[2]), "r"(a[3]), "r"(b[0]), "r"(b[1]));
}

// pack two floats to fp16x2 word (low = a, high = b)
__device__ __forceinline__ unsigned packh2(float a, float b) {
    __half2 p = __floats2half2_rn(a, b);
    return *reinterpret_cast<unsigned*>(&p);
}

// cp.async 16B via L2 (bypasses L1)
__device__ __forceinline__ void cpa16(uint32_t s, const void* g) {
    asm volatile("cp.async.cg.shared.global [%0], [%1], 16;" :: "r"(s), "l"(g) : "memory");
}
#define CP_COMMIT() asm volatile("cp.async.commit_group;" ::: "memory")

// ---------------------------------------------------------------------------
// Grid barrier (round-6, known good).
// ---------------------------------------------------------------------------
__device__ __forceinline__ void grid_barrier(unsigned ep) {
    __syncthreads();
    if (threadIdx.x == 0) {
        asm volatile("red.release.gpu.global.add.u32 [%0], 1;"
                     :: "l"(&g_ctr) : "memory");
        const unsigned target = ep * NB;
        unsigned v;
        do {
            asm volatile("ld.acquire.gpu.global.u32 %0, [%1];"
                         : "=r"(v) : "l"(&g_ctr) : "memory");
        } while ((int)(v - target) < 0);
    }
    __syncthreads();
}

// ---------------------------------------------------------------------------
// Weight transpose into unified array: g_wt_all[z*1024 + n][k] = src[off+k][n]
// ---------------------------------------------------------------------------
__global__ void transpose_weights(const float* __restrict__ Wz,
                                  const float* __restrict__ Wr,
                                  const float* __restrict__ Wh,
                                  const float* __restrict__ Wp) {
    __shared__ float tile[32][33];
    const int z = blockIdx.z;
    const float* src;
    int srcOff;
    switch (z) {
        case 0: src = Wz; srcOff = 1024; break;
        case 1: src = Wr; srcOff = 1024; break;
        case 2: src = Wh; srcOff = 1024; break;
        case 3: src = Wp; srcOff = 0;    break;
        case 4: src = Wz; srcOff = 0;    break;
        case 5: src = Wr; srcOff = 0;    break;
        default: src = Wh; srcOff = 0;   break;
    }
    float* dst = g_wt_all + (size_t)z * 1024 * 1024;
    const int kBase = blockIdx.x * 32;
    const int cBase = blockIdx.y * 32;
    tile[threadIdx.y][threadIdx.x] =
        src[(size_t)(srcOff + kBase + threadIdx.y) * 1024 + cBase + threadIdx.x];
    __syncthreads();
    dst[(size_t)(cBase + threadIdx.y) * 1024 + kBase + threadIdx.x] =
        tile[threadIdx.x][threadIdx.y];
}

__global__ void split_weights() {
    size_t i = (size_t)blockIdx.x * blockDim.x + threadIdx.x;
    if (i >= (size_t)7168 * 1024) return;
    float v = g_wt_all[i];
    __half h16 = __float2half_rn(v);
    g_w16h[i] = h16;
    g_w16l[i] = __float2half_rn(v - __half2float(h16));
}

__global__ void split_x(const float* __restrict__ x) {
    size_t i = (size_t)blockIdx.x * blockDim.x + threadIdx.x;
    if (i >= (size_t)BT * 1024) return;
    g_x16[i] = __float2half_rn(x[i]);
}

__global__ void init_h(const float* __restrict__ h0) {
    int i = blockIdx.x * blockDim.x + threadIdx.x;
    if (i == 0) g_ctr = 0u;
    if (i < BB * 1024) {
        float v = h0[i];
        g_hbuf[0][i] = v;
        g_h16[0][i] = __float2half_rn(v);
    }
}

// ---------------------------------------------------------------------------
// Precompute GEMM, fp16: g_pre = X16 @ (W16h + W16l) + b.  Block 128x128,
// K-chunks 32, cp.async double buffered. 8 warps: 32x64 tiles, 2x8 frags.
// ---------------------------------------------------------------------------
#define SG_AST 40
#define SG_A   (128 * SG_AST)             // one array (5120 fp16)
#define SG_BUFE (3 * SG_A)                // buffer: A | Bhi | Blo
#define SG_SMEM_BYTES (2 * SG_BUFE * 2)   // 61440

__global__ void __launch_bounds__(256, 1) sgemm_pre_mma(
    const float* __restrict__ bz, const float* __restrict__ br,
    const float* __restrict__ bh) {
    extern __shared__ __half sm[];
    const int gate = blockIdx.z;
    const int m0 = blockIdx.y * 128;
    const int n0 = blockIdx.x * 128;
    const float* bias = (gate == 0) ? bz : (gate == 1) ? br : bh;
    const size_t wrow = (size_t)(4096 + gate * 1024 + n0) * 1024;

    const int tid = threadIdx.x;
    const int w = tid >> 5, lane = tid & 31, g4 = lane >> 2, t = lane & 3;
    const int wm = (w & 3) * 32, wn = (w >> 2) * 64;
    const uint32_t smb = (uint32_t)__cvta_generic_to_shared(sm);

    float acc[2][8][4];
#pragma unroll
    for (int i = 0; i < 2; i++)
#pragma unroll
        for (int j = 0; j < 8; j++)
#pragma unroll
            for (int e = 0; e < 4; e++) acc[i][j][e] = 0.0f;

#pragma unroll
    for (int q = 0; q < 2; q++) {
        int pos = q * 256 + tid;
        int row = pos >> 2, ku = (pos & 3) * 8;
        uint32_t soff = (uint32_t)(row * SG_AST + ku) * 2;
        cpa16(smb + 0 * SG_A * 2 + soff, &g_x16[(size_t)(m0 + row) * 1024 + ku]);
        cpa16(smb + 1 * SG_A * 2 + soff, &g_w16h[wrow + (size_t)row * 1024 + ku]);
        cpa16(smb + 2 * SG_A * 2 + soff, &g_w16l[wrow + (size_t)row * 1024 + ku]);
    }
    CP_COMMIT();

    int buf = 0;
#pragma unroll 1
    for (int ch = 0; ch < 32; ch++) {
        const bool hasNext = (ch < 31);
        if (hasNext) {
            const int k0 = (ch + 1) * 32;
            const uint32_t b0 = smb + (uint32_t)((buf ^ 1) * SG_BUFE) * 2;
#pragma unroll
            for (int q = 0; q < 2; q++) {
                int pos = q * 256 + tid;
                int row = pos >> 2, ku = (pos & 3) * 8;
                uint32_t soff = (uint32_t)(row * SG_AST + ku) * 2;
                cpa16(b0 + 0 * SG_A * 2 + soff, &g_x16[(size_t)(m0 + row) * 1024 + k0 + ku]);
                cpa16(b0 + 1 * SG_A * 2 + soff, &g_w16h[wrow + (size_t)row * 1024 + k0 + ku]);
                cpa16(b0 + 2 * SG_A * 2 + soff, &g_w16l[wrow + (size_t)row * 1024 + k0 + ku]);
            }
            CP_COMMIT();
            asm volatile("cp.async.wait_group 1;" ::: "memory");
        } else {
            asm volatile("cp.async.wait_group 0;" ::: "memory");
        }
        __syncthreads();

        const __half* bb = sm + buf * SG_BUFE;
        const __half* AA = bb;
        const __half* BH = bb + SG_A;
        const __half* BL = bb + 2 * SG_A;
#pragma unroll
        for (int kf = 0; kf < 2; kf++) {
            const int koff = kf * 16 + 2 * t;
            unsigned a[2][4];
#pragma unroll
            for (int mi = 0; mi < 2; mi++) {
                int ra = (wm + mi * 16 + g4) * SG_AST + koff;
                a[mi][0] = *reinterpret_cast<const unsigned*>(&AA[ra]);
                a[mi][1] = *reinterpret_cast<const unsigned*>(&AA[ra + 8 * SG_AST]);
                a[mi][2] = *reinterpret_cast<const unsigned*>(&AA[ra + 8]);
                a[mi][3] = *reinterpret_cast<const unsigned*>(&AA[ra + 8 * SG_AST + 8]);
            }
#pragma unroll
            for (int nj = 0; nj < 8; nj++) {
                int rb = (wn + nj * 8 + g4) * SG_AST + koff;
                unsigned bhi[2], blo[2];
                bhi[0] = *reinterpret_cast<const unsigned*>(&BH[rb]);
                bhi[1] = *reinterpret_cast<const unsigned*>(&BH[rb + 8]);
                blo[0] = *reinterpret_cast<const unsigned*>(&BL[rb]);
                blo[1] = *reinterpret_cast<const unsigned*>(&BL[rb + 8]);
#pragma unroll
                for (int mi = 0; mi < 2; mi++) {
                    mma_f16(acc[mi][nj], a[mi], bhi);
                    mma_f16(acc[mi][nj], a[mi], blo);
                }
            }
        }
        __syncthreads();
        buf ^= 1;
    }

#pragma unroll
    for (int nj = 0; nj < 8; nj++) {
        int c = n0 + wn + nj * 8 + 2 * t;
        float b0v = bias[c], b1v = bias[c + 1];
#pragma unroll
        for (int mi = 0; mi < 2; mi++) {
            int r = m0 + wm + mi * 16 + g4;
            float2 o0 = make_float2(acc[mi][nj][0] + b0v, acc[mi][nj][1] + b1v);
            float2 o1 = make_float2(acc[mi][nj][2] + b0v, acc[mi][nj][3] + b1v);
            *reinterpret_cast<float2*>(&g_pre[(size_t)r * 3072 + gate * 1024 + c]) = o0;
            *reinterpret_cast<float2*>(&g_pre[(size_t)(r + 8) * 3072 + gate * 1024 + c]) = o1;
        }
    }
}

// ---------------------------------------------------------------------------
// Recurrent SMEM layout. W single fp16 (hi only). A in K=512 chunks, double
// buffered. AST2=520 fp16 (1040 B = 260 words == 4 mod 32: conflict-free).
// ---------------------------------------------------------------------------
#define AST2 520
#define ACH  (64 * AST2)                  // 33280 fp16
#define WST2 1032
#define SM_W     0                        // 32*1032*2 = 66048
#define SM_A     66048                    // 2*ACH*2   = 133120
#define SM_RED   199168                   // float[1536] = 6144
#define SM_TOTAL 205312

// ---------------------------------------------------------------------------
// fp16 MMA tile, single W term: C(64 x NT*8) = A16 @ W16. 2 chains by
// j-parity. cp.async double-buffered K=512 chunks (2 chunks/phase).
// ---------------------------------------------------------------------------
template <int NT, int KSEG>
__device__ __forceinline__ void mma_tile16(const __half* __restrict__ AG,
                                           const __half* __restrict__ WS,
                                           int colBase,
                                           __half* __restrict__ AS,
                                           float* __restrict__ red,
                                           float* __restrict__ d, int tid) {
    const int w = tid >> 5, lane = tid & 31;
    const int g = lane >> 2, t = lane & 3;
    const int mi = w >> 2;
    const int ni = (NT == 2) ? ((w >> 1) & 1) : 0;
    const int ks = w & (KSEG - 1);
    const int SEGK = 512 / KSEG;
    const uint32_t as_b = (uint32_t)__cvta_generic_to_shared(AS);

    float da[4] = {0.f, 0.f, 0.f, 0.f};
    float db[4] = {0.f, 0.f, 0.f, 0.f};

    // prologue: chunk 0 -> buf 0 (64 rows x 512 k fp16 = 64KB; 8 cpa/thread)
#pragma unroll
    for (int p = 0; p < 8; p++) {
        int pos = p * 512 + tid;
        int row = pos >> 6, ku = (pos & 63) << 3;
        cpa16(as_b + (uint32_t)(row * AST2 + ku) * 2, &AG[row * 1024 + ku]);
    }
    CP_COMMIT();

    int buf = 0;
#pragma unroll 1
    for (int ch = 0; ch < 2; ch++) {
        if (ch == 0) {
            const uint32_t bb = as_b + (uint32_t)ACH * 2;
#pragma unroll
            for (int p = 0; p < 8; p++) {
                int pos = p * 512 + tid;
                int row = pos >> 6, ku = (pos & 63) << 3;
                cpa16(bb + (uint32_t)(row * AST2 + ku) * 2, &AG[row * 1024 + 512 + ku]);
            }
            CP_COMMIT();
            asm volatile("cp.async.wait_group 1;" ::: "memory");
        } else {
            asm volatile("cp.async.wait_group 0;" ::: "memory");
        }
        __syncthreads();

        const __half* AH = AS + buf * ACH;
        const int ar = (mi * 16 + g) * AST2 + ks * SEGK + 2 * t;
        const int wr = (colBase + ni * 8 + g) * WST2 + (ch << 9) + ks * SEGK + 2 * t;
#pragma unroll
        for (int j = 0; j < SEGK / 16; j++) {
            const int ka = ar + j * 16;
            const int kw = wr + j * 16;
            unsigned a[4], bw[2];
            a[0] = *reinterpret_cast<const unsigned*>(&AH[ka]);
            a[1] = *reinterpret_cast<const unsigned*>(&AH[ka + 8 * AST2]);
            a[2] = *reinterpret_cast<const unsigned*>(&AH[ka + 8]);
            a[3] = *reinterpret_cast<const unsigned*>(&AH[ka + 8 * AST2 + 8]);
            bw[0] = *reinterpret_cast<const unsigned*>(&WS[kw]);
            bw[1] = *reinterpret_cast<const unsigned*>(&WS[kw + 8]);
            mma_f16((j & 1) ? db : da, a, bw);
        }
        __syncthreads();
        buf ^= 1;
    }

#pragma unroll
    for (int e = 0; e < 4; e++) d[e] = da[e] + db[e];

    // reduce k-segments
    if (ks != 0) {
        float* dst = red + (((mi * NT + ni) * (KSEG - 1) + (ks - 1)) * 32 + lane) * 4;
        dst[0] = d[0]; dst[1] = d[1]; dst[2] = d[2]; dst[3] = d[3];
    }
    __syncthreads();
    if (ks == 0) {
#pragma unroll
        for (int s = 0; s < KSEG - 1; s++) {
            const float* src = red + (((mi * NT + ni) * (KSEG - 1) + s) * 32 + lane) * 4;
            d[0] += src[0]; d[1] += src[1]; d[2] += src[2]; d[3] += src[3];
        }
    }
}

// ---------------------------------------------------------------------------
// Persistent recurrent kernel: 128 blocks x 512 threads, 512 steps.
// ---------------------------------------------------------------------------
__global__ void __launch_bounds__(THR, 1) gru_recurrent(const float* __restrict__ bp,
                                                        float* __restrict__ out) {
    extern __shared__ char smem[];
    __half* WS  = reinterpret_cast<__half*>(smem + SM_W);
    __half* AS  = reinterpret_cast<__half*>(smem + SM_A);
    float*  red = reinterpret_cast<float*>(smem + SM_RED);

    const int tid = threadIdx.x;
    const int bid = blockIdx.x;
    const int w = tid >> 5, lane = tid & 31;
    const int g = lane >> 2, t = lane & 3;

    // Load this block's 32 weight columns (fp16 hi only) into SMEM once.
    for (int idx = tid; idx < 32 * 128; idx += THR) {
        int i = idx >> 7, ko = (idx & 127) << 3;
        int gc = (i < 16) ? (bid * 16 + i)
               : (i < 24) ? (2048 + bid * 8 + (i - 16))
                          : (3072 + bid * 8 + (i - 24));
        *reinterpret_cast<uint4*>(&WS[i * WST2 + ko]) =
            *reinterpret_cast<const uint4*>(&g_w16h[(size_t)gc * 1024 + ko]);
    }
    __syncthreads();

    const bool isR = (bid >= 64);
    unsigned ep = 0;
    int p = 0;   // h lives in buffers [p] at step start

#pragma unroll 1
    for (int tt = 0; tt < TT; tt++) {
        const float* h = g_hbuf[p];

        // ---- phase 1: z (bid<64) ; sig(r_pre)*h -> rh fp16 (bid>=64) ----
        {
            const int mi = w >> 2, ni = (w >> 1) & 1;
            const int cz = (bid << 4) + ni * 8 + 2 * t;
            const int r0 = mi * 16 + g, r1 = r0 + 8;
            float p00 = 0.f, p01 = 0.f, p10 = 0.f, p11 = 0.f;
            float h00 = 0.f, h01 = 0.f, h10 = 0.f, h11 = 0.f;
            if ((w & 1) == 0) {   // prefetch epilogue operands
                p00 = __ldcs(&g_pre[(size_t)(r0 * TT + tt) * 3072 + cz]);
                p01 = __ldcs(&g_pre[(size_t)(r0 * TT + tt) * 3072 + cz + 1]);
                p10 = __ldcs(&g_pre[(size_t)(r1 * TT + tt) * 3072 + cz]);
                p11 = __ldcs(&g_pre[(size_t)(r1 * TT + tt) * 3072 + cz + 1]);
                if (isR) {
                    const int cn = cz - 1024;
                    h00 = __ldcg(&h[r0 * 1024 + cn]);
                    h01 = __ldcg(&h[r0 * 1024 + cn + 1]);
                    h10 = __ldcg(&h[r1 * 1024 + cn]);
                    h11 = __ldcg(&h[r1 * 1024 + cn + 1]);
                }
            }
            float d[4];
            mma_tile16<2, 2>(g_h16[p], WS, 0, AS, red, d, tid);
            if ((w & 1) == 0) {
                float v00 = sig_(d[0] + p00);
                float v01 = sig_(d[1] + p01);
                float v10 = sig_(d[2] + p10);
                float v11 = sig_(d[3] + p11);
                if (isR) {
                    const int cn = cz - 1024;
                    __stcg(reinterpret_cast<unsigned*>(&g_rh16[r0 * 1024 + cn]),
                           packh2(v00 * h00, v01 * h01));
                    __stcg(reinterpret_cast<unsigned*>(&g_rh16[r1 * 1024 + cn]),
                           packh2(v10 * h10, v11 * h11));
                } else {
                    __stcg(&g_z[r0 * 1024 + cz],     v00);
                    __stcg(&g_z[r0 * 1024 + cz + 1], v01);
                    __stcg(&g_z[r1 * 1024 + cz],     v10);
                    __stcg(&g_z[r1 * 1024 + cz + 1], v11);
                }
            }
        }
        grid_barrier(++ep);

        // ---- phase 2: cand + gate combine ----
        const int pn = p ^ 1;
        {
            const int mi = w >> 2;
            const int c0 = (bid << 3) + 2 * t;
            const int r0 = mi * 16 + g, r1 = r0 + 8;
            float ph00 = 0.f, ph01 = 0.f, ph10 = 0.f, ph11 = 0.f;
            float z00 = 0.f, z01 = 0.f, z10 = 0.f, z11 = 0.f;
            float h00 = 0.f, h01 = 0.f, h10 = 0.f, h11 = 0.f;
            if ((w & 3) == 0) {   // prefetch epilogue operands
                ph00 = __ldcs(&g_pre[(size_t)(r0 * TT + tt) * 3072 + 2048 + c0]);
                ph01 = __ldcs(&g_pre[(size_t)(r0 * TT + tt) * 3072 + 2048 + c0 + 1]);
                ph10 = __ldcs(&g_pre[(size_t)(r1 * TT + tt) * 3072 + 2048 + c0]);
                ph11 = __ldcs(&g_pre[(size_t)(r1 * TT + tt) * 3072 + 2048 + c0 + 1]);
                z00 = __ldcg(&g_z[r0 * 1024 + c0]);
                z01 = __ldcg(&g_z[r0 * 1024 + c0 + 1]);
                z10 = __ldcg(&g_z[r1 * 1024 + c0]);
                z11 = __ldcg(&g_z[r1 * 1024 + c0 + 1]);
                h00 = __ldcg(&h[r0 * 1024 + c0]);
                h01 = __ldcg(&h[r0 * 1024 + c0 + 1]);
                h10 = __ldcg(&h[r1 * 1024 + c0]);
                h11 = __ldcg(&h[r1 * 1024 + c0 + 1]);
            }
            float d[4];
            mma_tile16<1, 4>(g_rh16, WS, 16, AS, red, d, tid);
            if ((w & 3) == 0) {
                float hn00 = fmaf(z00, tanh_(d[0] + ph00) - h00, h00);
                float hn01 = fmaf(z01, tanh_(d[1] + ph01) - h01, h01);
                float hn10 = fmaf(z10, tanh_(d[2] + ph10) - h10, h10);
                float hn11 = fmaf(z11, tanh_(d[3] + ph11) - h11, h11);
                out[(size_t)(r0 * TT + tt) * 1024 + c0]     = hn00;
                out[(size_t)(r0 * TT + tt) * 1024 + c0 + 1] = hn01;
                out[(size_t)(r1 * TT + tt) * 1024 + c0]     = hn10;
                out[(size_t)(r1 * TT + tt) * 1024 + c0 + 1] = hn11;
                __stcg(&g_hbuf[pn][r0 * 1024 + c0],     hn00);
                __stcg(&g_hbuf[pn][r0 * 1024 + c0 + 1], hn01);
                __stcg(&g_hbuf[pn][r1 * 1024 + c0],     hn10);
                __stcg(&g_hbuf[pn][r1 * 1024 + c0 + 1], hn11);
                __stcg(reinterpret_cast<unsigned*>(&g_h16[pn][r0 * 1024 + c0]),
                       packh2(hn00, hn01));
                __stcg(reinterpret_cast<unsigned*>(&g_h16[pn][r1 * 1024 + c0]),
                       packh2(hn10, hn11));
            }
        }
        grid_barrier(++ep);

        // ---- phase 3: chunk-boundary projection ----
        const bool prop = ((tt & 3) == 3) && (tt != TT - 1);
        if (prop) {
            float d[4];
            mma_tile16<1, 4>(g_h16[pn], WS, 24, AS, red, d, tid);
            if ((w & 3) == 0) {
                const int mi = w >> 2;
                const int c0 = (bid << 3) + 2 * t;
                const int r0 = mi * 16 + g, r1 = r0 + 8;
                float bp0 = bp[c0], bp1 = bp[c0 + 1];
                float v00 = tanh_(d[0] + bp0);
                float v01 = tanh_(d[1] + bp1);
                float v10 = tanh_(d[2] + bp0);
                float v11 = tanh_(d[3] + bp1);
                __stcg(&g_hbuf[p][r0 * 1024 + c0],     v00);
                __stcg(&g_hbuf[p][r0 * 1024 + c0 + 1], v01);
                __stcg(&g_hbuf[p][r1 * 1024 + c0],     v10);
                __stcg(&g_hbuf[p][r1 * 1024 + c0 + 1], v11);
                __stcg(reinterpret_cast<unsigned*>(&g_h16[p][r0 * 1024 + c0]),
                       packh2(v00, v01));
                __stcg(reinterpret_cast<unsigned*>(&g_h16[p][r1 * 1024 + c0]),
                       packh2(v10, v11));
            }
            grid_barrier(++ep);
            // h stays in buffers [p]
        } else {
            p ^= 1;
        }
    }
}

// ---------------------------------------------------------------------------
extern "C" void kernel_launch(void* const* d_in, const int* in_sizes, int n_in,
                              void* d_out, int out_size) {
    (void)in_sizes; (void)n_in; (void)out_size;
    const float* x  = (const float*)d_in[0];
    const float* h0 = (const float*)d_in[1];
    const float* Wz = (const float*)d_in[2];
    const float* bz = (const float*)d_in[3];
    const float* Wr = (const float*)d_in[4];
    const float* br = (const float*)d_in[5];
    const float* Wh = (const float*)d_in[6];
    const float* bh = (const float*)d_in[7];
    const float* Wp = (const float*)d_in[8];
    const float* bp = (const float*)d_in[9];
    float* out = (float*)d_out;

    static bool attr_set = false;
    if (!attr_set) {
        cudaFuncSetAttribute(gru_recurrent, cudaFuncAttributeMaxDynamicSharedMemorySize,
                             SM_TOTAL);
        cudaFuncSetAttribute(sgemm_pre_mma, cudaFuncAttributeMaxDynamicSharedMemorySize,
                             SG_SMEM_BYTES);
        attr_set = true;
    }

    transpose_weights<<<dim3(32, 32, 7), dim3(32, 32)>>>(Wz, Wr, Wh, Wp);
    split_weights<<<14336, 512>>>();
    split_x<<<65536, 512>>>(x);
    init_h<<<64, 1024>>>(h0);
    sgemm_pre_mma<<<dim3(8, 256, 3), 256, SG_SMEM_BYTES>>>(bz, br, bh);
    gru_recurrent<<<NB, THR, SM_TOTAL>>>(bp, out);
}

// round 16
// speedup vs baseline: 10.4603x; 1.0165x over previous
#include <cuda_runtime.h>
#include <cuda_fp16.h>
#include <cstdint>

// ---------------------------------------------------------------------------
// ChunkParallelGRU: B=64, T=512, D=1024, H=1024, CHUNK=4
//
//   pre[g][m][n] = x[m] @ Wg_x + bg          (fp16 2-term MMA GEMM)
//   per step t (sequential, persistent kernel):
//     P1: z = sig(pre_z + h @ Wz_h)          -> g_z    (blocks 0..63)
//         rh = sig(pre_r + h @ Wr_h) * h     -> rh fp16 (blocks 64..127)
//     P2: cand = tanh(pre_h + rh @ Wh_h);
//         h_new = h + z*(cand-h); out[t] = h_new
//     P3 (chunk boundary): h = tanh(h_new @ Wp + bp)
//
// v13 = v12 + per-block ROTATED staging order (anti L2-hotspot): all blocks
//       read the same A bytes but start bid*512B apart within each chunk, so
//       the synchronized burst spreads across all LTS slices instead of
//       hammering one narrow address window in lockstep.
// ---------------------------------------------------------------------------

#define BB 64
#define TT 512
#define BT (BB * 512)
#define NB 128          // persistent grid (<=148 SMs -> co-resident)
#define THR 512

// Scratch (static device arrays; allocation-free)
__device__ float g_pre[(size_t)BT * 3072];            // [m][z|r|h]
__device__ float g_wt_all[(size_t)7168 * 1024];       // transposed fp32 weights
__device__ __half g_w16h[(size_t)7168 * 1024];        // fp16 hi: [zr_h|h_h|p|z_x|r_x|h_x]
__device__ __half g_w16l[(size_t)7168 * 1024];        // fp16 lo (used by pre GEMM)
__device__ __half g_x16[(size_t)BT * 1024];           // fp16 x
__device__ float g_hbuf[2][BB * 1024];                // fp32 state (epilogue reads)
__device__ __half g_h16[2][BB * 1024];                // fp16 state (MMA A)
__device__ __half g_rh16[BB * 1024];                  // fp16 sig(r)*h
__device__ float g_z[BB * 1024];                      // sigmoided z
__device__ unsigned g_ctr;                            // barrier counter (monotonic)

__device__ __forceinline__ float sig_(float x) {
    return 1.0f / (1.0f + __expf(-x));
}
__device__ __forceinline__ float tanh_(float x) {
    x = fminf(15.0f, fmaxf(-15.0f, x));
    float e = __expf(-2.0f * x);
    return (1.0f - e) / (1.0f + e);
}

// fp16 MMA: D(16x8,f32) += A(16x16,f16)*B(16x8,f16)
__device__ __forceinline__ void mma_f16(float* d, const unsigned* a, const unsigned* b) {
    asm volatile(
        "mma.sync.aligned.m16n8k16.row.col.f32.f16.f16.f32 "
        "{%0,%1,%2,%3}, {%4,%5,%6,%7}, {%8,%9}, {%0,%1,%2,%3};\n"
        : "+f"(d[0]), "+f"(d[1]), "+f"(d[2]), "+f"(d[3])
        : "r"(a[0]), "r"(a[1]), "r"(a[2]), "r"(a[3]), "r"(b[0]), "r"(b[1]));
}

// pack two floats to fp16x2 word (low = a, high = b)
__device__ __forceinline__ unsigned packh2(float a, float b) {
    __half2 p = __floats2half2_rn(a, b);
    return *reinterpret_cast<unsigned*>(&p);
}

// cp.async 16B via L2 (bypasses L1)
__device__ __forceinline__ void cpa16(uint32_t s, const void* g) {
    asm volatile("cp.async.cg.shared.global [%0], [%1], 16;" :: "r"(s), "l"(g) : "memory");
}
#define CP_COMMIT() asm volatile("cp.async.commit_group;" ::: "memory")

// ---------------------------------------------------------------------------
// Grid barrier (round-6, known good).
// ---------------------------------------------------------------------------
__device__ __forceinline__ void grid_barrier(unsigned ep) {
    __syncthreads();
    if (threadIdx.x == 0) {
        asm volatile("red.release.gpu.global.add.u32 [%0], 1;"
                     :: "l"(&g_ctr) : "memory");
        const unsigned target = ep * NB;
        unsigned v;
        do {
            asm volatile("ld.acquire.gpu.global.u32 %0, [%1];"
                         : "=r"(v) : "l"(&g_ctr) : "memory");
        } while ((int)(v - target) < 0);
    }
    __syncthreads();
}

// ---------------------------------------------------------------------------
// Weight transpose into unified array: g_wt_all[z*1024 + n][k] = src[off+k][n]
// ---------------------------------------------------------------------------
__global__ void transpose_weights(const float* __restrict__ Wz,
                                  const float* __restrict__ Wr,
                                  const float* __restrict__ Wh,
                                  const float* __restrict__ Wp) {
    __shared__ float tile[32][33];
    const int z = blockIdx.z;
    const float* src;
    int srcOff;
    switch (z) {
        case 0: src = Wz; srcOff = 1024; break;
        case 1: src = Wr; srcOff = 1024; break;
        case 2: src = Wh; srcOff = 1024; break;
        case 3: src = Wp; srcOff = 0;    break;
        case 4: src = Wz; srcOff = 0;    break;
        case 5: src = Wr; srcOff = 0;    break;
        default: src = Wh; srcOff = 0;   break;
    }
    float* dst = g_wt_all + (size_t)z * 1024 * 1024;
    const int kBase = blockIdx.x * 32;
    const int cBase = blockIdx.y * 32;
    tile[threadIdx.y][threadIdx.x] =
        src[(size_t)(srcOff + kBase + threadIdx.y) * 1024 + cBase + threadIdx.x];
    __syncthreads();
    dst[(size_t)(cBase + threadIdx.y) * 1024 + kBase + threadIdx.x] =
        tile[threadIdx.x][threadIdx.y];
}

__global__ void split_weights() {
    size_t i = (size_t)blockIdx.x * blockDim.x + threadIdx.x;
    if (i >= (size_t)7168 * 1024) return;
    float v = g_wt_all[i];
    __half h16 = __float2half_rn(v);
    g_w16h[i] = h16;
    g_w16l[i] = __float2half_rn(v - __half2float(h16));
}

__global__ void split_x(const float* __restrict__ x) {
    size_t i = (size_t)blockIdx.x * blockDim.x + threadIdx.x;
    if (i >= (size_t)BT * 1024) return;
    g_x16[i] = __float2half_rn(x[i]);
}

__global__ void init_h(const float* __restrict__ h0) {
    int i = blockIdx.x * blockDim.x + threadIdx.x;
    if (i == 0) g_ctr = 0u;
    if (i < BB * 1024) {
        float v = h0[i];
        g_hbuf[0][i] = v;
        g_h16[0][i] = __float2half_rn(v);
    }
}

// ---------------------------------------------------------------------------
// Precompute GEMM, fp16 (unchanged, round-15 proven).
// ---------------------------------------------------------------------------
#define SG_AST 40
#define SG_A   (128 * SG_AST)
#define SG_BUFE (3 * SG_A)
#define SG_SMEM_BYTES (2 * SG_BUFE * 2)

__global__ void __launch_bounds__(256, 1) sgemm_pre_mma(
    const float* __restrict__ bz, const float* __restrict__ br,
    const float* __restrict__ bh) {
    extern __shared__ __half sm[];
    const int gate = blockIdx.z;
    const int m0 = blockIdx.y * 128;
    const int n0 = blockIdx.x * 128;
    const float* bias = (gate == 0) ? bz : (gate == 1) ? br : bh;
    const size_t wrow = (size_t)(4096 + gate * 1024 + n0) * 1024;

    const int tid = threadIdx.x;
    const int w = tid >> 5, lane = tid & 31, g4 = lane >> 2, t = lane & 3;
    const int wm = (w & 3) * 32, wn = (w >> 2) * 64;
    const uint32_t smb = (uint32_t)__cvta_generic_to_shared(sm);

    float acc[2][8][4];
#pragma unroll
    for (int i = 0; i < 2; i++)
#pragma unroll
        for (int j = 0; j < 8; j++)
#pragma unroll
            for (int e = 0; e < 4; e++) acc[i][j][e] = 0.0f;

#pragma unroll
    for (int q = 0; q < 2; q++) {
        int pos = q * 256 + tid;
        int row = pos >> 2, ku = (pos & 3) * 8;
        uint32_t soff = (uint32_t)(row * SG_AST + ku) * 2;
        cpa16(smb + 0 * SG_A * 2 + soff, &g_x16[(size_t)(m0 + row) * 1024 + ku]);
        cpa16(smb + 1 * SG_A * 2 + soff, &g_w16h[wrow + (size_t)row * 1024 + ku]);
        cpa16(smb + 2 * SG_A * 2 + soff, &g_w16l[wrow + (size_t)row * 1024 + ku]);
    }
    CP_COMMIT();

    int buf = 0;
#pragma unroll 1
    for (int ch = 0; ch < 32; ch++) {
        const bool hasNext = (ch < 31);
        if (hasNext) {
            const int k0 = (ch + 1) * 32;
            const uint32_t b0 = smb + (uint32_t)((buf ^ 1) * SG_BUFE) * 2;
#pragma unroll
            for (int q = 0; q < 2; q++) {
                int pos = q * 256 + tid;
                int row = pos >> 2, ku = (pos & 3) * 8;
                uint32_t soff = (uint32_t)(row * SG_AST + ku) * 2;
                cpa16(b0 + 0 * SG_A * 2 + soff, &g_x16[(size_t)(m0 + row) * 1024 + k0 + ku]);
                cpa16(b0 + 1 * SG_A * 2 + soff, &g_w16h[wrow + (size_t)row * 1024 + k0 + ku]);
                cpa16(b0 + 2 * SG_A * 2 + soff, &g_w16l[wrow + (size_t)row * 1024 + k0 + ku]);
            }
            CP_COMMIT();
            asm volatile("cp.async.wait_group 1;" ::: "memory");
        } else {
            asm volatile("cp.async.wait_group 0;" ::: "memory");
        }
        __syncthreads();

        const __half* bb = sm + buf * SG_BUFE;
        const __half* AA = bb;
        const __half* BH = bb + SG_A;
        const __half* BL = bb + 2 * SG_A;
#pragma unroll
        for (int kf = 0; kf < 2; kf++) {
            const int koff = kf * 16 + 2 * t;
            unsigned a[2][4];
#pragma unroll
            for (int mi = 0; mi < 2; mi++) {
                int ra = (wm + mi * 16 + g4) * SG_AST + koff;
                a[mi][0] = *reinterpret_cast<const unsigned*>(&AA[ra]);
                a[mi][1] = *reinterpret_cast<const unsigned*>(&AA[ra + 8 * SG_AST]);
                a[mi][2] = *reinterpret_cast<const unsigned*>(&AA[ra + 8]);
                a[mi][3] = *reinterpret_cast<const unsigned*>(&AA[ra + 8 * SG_AST + 8]);
            }
#pragma unroll
            for (int nj = 0; nj < 8; nj++) {
                int rb = (wn + nj * 8 + g4) * SG_AST + koff;
                unsigned bhi[2], blo[2];
                bhi[0] = *reinterpret_cast<const unsigned*>(&BH[rb]);
                bhi[1] = *reinterpret_cast<const unsigned*>(&BH[rb + 8]);
                blo[0] = *reinterpret_cast<const unsigned*>(&BL[rb]);
                blo[1] = *reinterpret_cast<const unsigned*>(&BL[rb + 8]);
#pragma unroll
                for (int mi = 0; mi < 2; mi++) {
                    mma_f16(acc[mi][nj], a[mi], bhi);
                    mma_f16(acc[mi][nj], a[mi], blo);
                }
            }
        }
        __syncthreads();
        buf ^= 1;
    }

#pragma unroll
    for (int nj = 0; nj < 8; nj++) {
        int c = n0 + wn + nj * 8 + 2 * t;
        float b0v = bias[c], b1v = bias[c + 1];
#pragma unroll
        for (int mi = 0; mi < 2; mi++) {
            int r = m0 + wm + mi * 16 + g4;
            float2 o0 = make_float2(acc[mi][nj][0] + b0v, acc[mi][nj][1] + b1v);
            float2 o1 = make_float2(acc[mi][nj][2] + b0v, acc[mi][nj][3] + b1v);
            *reinterpret_cast<float2*>(&g_pre[(size_t)r * 3072 + gate * 1024 + c]) = o0;
            *reinterpret_cast<float2*>(&g_pre[(size_t)(r + 8) * 3072 + gate * 1024 + c]) = o1;
        }
    }
}

// ---------------------------------------------------------------------------
// Recurrent SMEM layout (unchanged from round 15).
// ---------------------------------------------------------------------------
#define AST2 520
#define ACH  (64 * AST2)
#define WST2 1032
#define SM_W     0
#define SM_A     66048
#define SM_RED   199168
#define SM_TOTAL 205312

// ---------------------------------------------------------------------------
// fp16 MMA tile, single W term, ROTATED staging: each block's cp.async
// sequence starts bid*32 positions (512 B) into the chunk, wrapped, so the
// chip-wide synchronized burst spreads across all LTS slices.
// ---------------------------------------------------------------------------
template <int NT, int KSEG>
__device__ __forceinline__ void mma_tile16(const __half* __restrict__ AG,
                                           const __half* __restrict__ WS,
                                           int colBase,
                                           __half* __restrict__ AS,
                                           float* __restrict__ red,
                                           float* __restrict__ d, int tid, int bid) {
    const int w = tid >> 5, lane = tid & 31;
    const int g = lane >> 2, t = lane & 3;
    const int mi = w >> 2;
    const int ni = (NT == 2) ? ((w >> 1) & 1) : 0;
    const int ks = w & (KSEG - 1);
    const int SEGK = 512 / KSEG;
    const uint32_t as_b = (uint32_t)__cvta_generic_to_shared(AS);
    const int shift = bid << 5;   // 32 positions * 16B = 512 B per block

    float da[4] = {0.f, 0.f, 0.f, 0.f};
    float db[4] = {0.f, 0.f, 0.f, 0.f};

    // prologue: chunk 0 -> buf 0 (64 rows x 512 k fp16 = 4096 x 16B; rotated)
#pragma unroll
    for (int p = 0; p < 8; p++) {
        int pos = (p * 512 + tid + shift) & 4095;
        int row = pos >> 6, ku = (pos & 63) << 3;
        cpa16(as_b + (uint32_t)(row * AST2 + ku) * 2, &AG[row * 1024 + ku]);
    }
    CP_COMMIT();

    int buf = 0;
#pragma unroll 1
    for (int ch = 0; ch < 2; ch++) {
        if (ch == 0) {
            const uint32_t bb = as_b + (uint32_t)ACH * 2;
#pragma unroll
            for (int p = 0; p < 8; p++) {
                int pos = (p * 512 + tid + shift) & 4095;
                int row = pos >> 6, ku = (pos & 63) << 3;
                cpa16(bb + (uint32_t)(row * AST2 + ku) * 2, &AG[row * 1024 + 512 + ku]);
            }
            CP_COMMIT();
            asm volatile("cp.async.wait_group 1;" ::: "memory");
        } else {
            asm volatile("cp.async.wait_group 0;" ::: "memory");
        }
        __syncthreads();

        const __half* AH = AS + buf * ACH;
        const int ar = (mi * 16 + g) * AST2 + ks * SEGK + 2 * t;
        const int wr = (colBase + ni * 8 + g) * WST2 + (ch << 9) + ks * SEGK + 2 * t;
#pragma unroll
        for (int j = 0; j < SEGK / 16; j++) {
            const int ka = ar + j * 16;
            const int kw = wr + j * 16;
            unsigned a[4], bw[2];
            a[0] = *reinterpret_cast<const unsigned*>(&AH[ka]);
            a[1] = *reinterpret_cast<const unsigned*>(&AH[ka + 8 * AST2]);
            a[2] = *reinterpret_cast<const unsigned*>(&AH[ka + 8]);
            a[3] = *reinterpret_cast<const unsigned*>(&AH[ka + 8 * AST2 + 8]);
            bw[0] = *reinterpret_cast<const unsigned*>(&WS[kw]);
            bw[1] = *reinterpret_cast<const unsigned*>(&WS[kw + 8]);
            mma_f16((j & 1) ? db : da, a, bw);
        }
        __syncthreads();
        buf ^= 1;
    }

#pragma unroll
    for (int e = 0; e < 4; e++) d[e] = da[e] + db[e];

    // reduce k-segments
    if (ks != 0) {
        float* dst = red + (((mi * NT + ni) * (KSEG - 1) + (ks - 1)) * 32 + lane) * 4;
        dst[0] = d[0]; dst[1] = d[1]; dst[2] = d[2]; dst[3] = d[3];
    }
    __syncthreads();
    if (ks == 0) {
#pragma unroll
        for (int s = 0; s < KSEG - 1; s++) {
            const float* src = red + (((mi * NT + ni) * (KSEG - 1) + s) * 32 + lane) * 4;
            d[0] += src[0]; d[1] += src[1]; d[2] += src[2]; d[3] += src[3];
        }
    }
}

// ---------------------------------------------------------------------------
// Persistent recurrent kernel: 128 blocks x 512 threads, 512 steps.
// ---------------------------------------------------------------------------
__global__ void __launch_bounds__(THR, 1) gru_recurrent(const float* __restrict__ bp,
                                                        float* __restrict__ out) {
    extern __shared__ char smem[];
    __half* WS  = reinterpret_cast<__half*>(smem + SM_W);
    __half* AS  = reinterpret_cast<__half*>(smem + SM_A);
    float*  red = reinterpret_cast<float*>(smem + SM_RED);

    const int tid = threadIdx.x;
    const int bid = blockIdx.x;
    const int w = tid >> 5, lane = tid & 31;
    const int g = lane >> 2, t = lane & 3;

    // Load this block's 32 weight columns (fp16 hi only) into SMEM once.
    for (int idx = tid; idx < 32 * 128; idx += THR) {
        int i = idx >> 7, ko = (idx & 127) << 3;
        int gc = (i < 16) ? (bid * 16 + i)
               : (i < 24) ? (2048 + bid * 8 + (i - 16))
                          : (3072 + bid * 8 + (i - 24));
        *reinterpret_cast<uint4*>(&WS[i * WST2 + ko]) =
            *reinterpret_cast<const uint4*>(&g_w16h[(size_t)gc * 1024 + ko]);
    }
    __syncthreads();

    const bool isR = (bid >= 64);
    unsigned ep = 0;
    int p = 0;   // h lives in buffers [p] at step start

#pragma unroll 1
    for (int tt = 0; tt < TT; tt++) {
        const float* h = g_hbuf[p];

        // ---- phase 1: z (bid<64) ; sig(r_pre)*h -> rh fp16 (bid>=64) ----
        {
            const int mi = w >> 2, ni = (w >> 1) & 1;
            const int cz = (bid << 4) + ni * 8 + 2 * t;
            const int r0 = mi * 16 + g, r1 = r0 + 8;
            float p00 = 0.f, p01 = 0.f, p10 = 0.f, p11 = 0.f;
            float h00 = 0.f, h01 = 0.f, h10 = 0.f, h11 = 0.f;
            if ((w & 1) == 0) {   // prefetch epilogue operands
                p00 = __ldcs(&g_pre[(size_t)(r0 * TT + tt) * 3072 + cz]);
                p01 = __ldcs(&g_pre[(size_t)(r0 * TT + tt) * 3072 + cz + 1]);
                p10 = __ldcs(&g_pre[(size_t)(r1 * TT + tt) * 3072 + cz]);
                p11 = __ldcs(&g_pre[(size_t)(r1 * TT + tt) * 3072 + cz + 1]);
                if (isR) {
                    const int cn = cz - 1024;
                    h00 = __ldcg(&h[r0 * 1024 + cn]);
                    h01 = __ldcg(&h[r0 * 1024 + cn + 1]);
                    h10 = __ldcg(&h[r1 * 1024 + cn]);
                    h11 = __ldcg(&h[r1 * 1024 + cn + 1]);
                }
            }
            float d[4];
            mma_tile16<2, 2>(g_h16[p], WS, 0, AS, red, d, tid, bid);
            if ((w & 1) == 0) {
                float v00 = sig_(d[0] + p00);
                float v01 = sig_(d[1] + p01);
                float v10 = sig_(d[2] + p10);
                float v11 = sig_(d[3] + p11);
                if (isR) {
                    const int cn = cz - 1024;
                    __stcg(reinterpret_cast<unsigned*>(&g_rh16[r0 * 1024 + cn]),
                           packh2(v00 * h00, v01 * h01));
                    __stcg(reinterpret_cast<unsigned*>(&g_rh16[r1 * 1024 + cn]),
                           packh2(v10 * h10, v11 * h11));
                } else {
                    __stcg(&g_z[r0 * 1024 + cz],     v00);
                    __stcg(&g_z[r0 * 1024 + cz + 1], v01);
                    __stcg(&g_z[r1 * 1024 + cz],     v10);
                    __stcg(&g_z[r1 * 1024 + cz + 1], v11);
                }
            }
        }
        grid_barrier(++ep);

        // ---- phase 2: cand + gate combine ----
        const int pn = p ^ 1;
        {
            const int mi = w >> 2;
            const int c0 = (bid << 3) + 2 * t;
            const int r0 = mi * 16 + g, r1 = r0 + 8;
            float ph00 = 0.f, ph01 = 0.f, ph10 = 0.f, ph11 = 0.f;
            float z00 = 0.f, z01 = 0.f, z10 = 0.f, z11 = 0.f;
            float h00 = 0.f, h01 = 0.f, h10 = 0.f, h11 = 0.f;
            if ((w & 3) == 0) {   // prefetch epilogue operands
                ph00 = __ldcs(&g_pre[(size_t)(r0 * TT + tt) * 3072 + 2048 + c0]);
                ph01 = __ldcs(&g_pre[(size_t)(r0 * TT + tt) * 3072 + 2048 + c0 + 1]);
                ph10 = __ldcs(&g_pre[(size_t)(r1 * TT + tt) * 3072 + 2048 + c0]);
                ph11 = __ldcs(&g_pre[(size_t)(r1 * TT + tt) * 3072 + 2048 + c0 + 1]);
                z00 = __ldcg(&g_z[r0 * 1024 + c0]);
                z01 = __ldcg(&g_z[r0 * 1024 + c0 + 1]);
                z10 = __ldcg(&g_z[r1 * 1024 + c0]);
                z11 = __ldcg(&g_z[r1 * 1024 + c0 + 1]);
                h00 = __ldcg(&h[r0 * 1024 + c0]);
                h01 = __ldcg(&h[r0 * 1024 + c0 + 1]);
                h10 = __ldcg(&h[r1 * 1024 + c0]);
                h11 = __ldcg(&h[r1 * 1024 + c0 + 1]);
            }
            float d[4];
            mma_tile16<1, 4>(g_rh16, WS, 16, AS, red, d, tid, bid);
            if ((w & 3) == 0) {
                float hn00 = fmaf(z00, tanh_(d[0] + ph00) - h00, h00);
                float hn01 = fmaf(z01, tanh_(d[1] + ph01) - h01, h01);
                float hn10 = fmaf(z10, tanh_(d[2] + ph10) - h10, h10);
                float hn11 = fmaf(z11, tanh_(d[3] + ph11) - h11, h11);
                out[(size_t)(r0 * TT + tt) * 1024 + c0]     = hn00;
                out[(size_t)(r0 * TT + tt) * 1024 + c0 + 1] = hn01;
                out[(size_t)(r1 * TT + tt) * 1024 + c0]     = hn10;
                out[(size_t)(r1 * TT + tt) * 1024 + c0 + 1] = hn11;
                __stcg(&g_hbuf[pn][r0 * 1024 + c0],     hn00);
                __stcg(&g_hbuf[pn][r0 * 1024 + c0 + 1], hn01);
                __stcg(&g_hbuf[pn][r1 * 1024 + c0],     hn10);
                __stcg(&g_hbuf[pn][r1 * 1024 + c0 + 1], hn11);
                __stcg(reinterpret_cast<unsigned*>(&g_h16[pn][r0 * 1024 + c0]),
                       packh2(hn00, hn01));
                __stcg(reinterpret_cast<unsigned*>(&g_h16[pn][r1 * 1024 + c0]),
                       packh2(hn10, hn11));
            }
        }
        grid_barrier(++ep);

        // ---- phase 3: chunk-boundary projection ----
        const bool prop = ((tt & 3) == 3) && (tt != TT - 1);
        if (prop) {
            float d[4];
            mma_tile16<1, 4>(g_h16[pn], WS, 24, AS, red, d, tid, bid);
            if ((w & 3) == 0) {
                const int mi = w >> 2;
                const int c0 = (bid << 3) + 2 * t;
                const int r0 = mi * 16 + g, r1 = r0 + 8;
                float bp0 = bp[c0], bp1 = bp[c0 + 1];
                float v00 = tanh_(d[0] + bp0);
                float v01 = tanh_(d[1] + bp1);
                float v10 = tanh_(d[2] + bp0);
                float v11 = tanh_(d[3] + bp1);
                __stcg(&g_hbuf[p][r0 * 1024 + c0],     v00);
                __stcg(&g_hbuf[p][r0 * 1024 + c0 + 1], v01);
                __stcg(&g_hbuf[p][r1 * 1024 + c0],     v10);
                __stcg(&g_hbuf[p][r1 * 1024 + c0 + 1], v11);
                __stcg(reinterpret_cast<unsigned*>(&g_h16[p][r0 * 1024 + c0]),
                       packh2(v00, v01));
                __stcg(reinterpret_cast<unsigned*>(&g_h16[p][r1 * 1024 + c0]),
                       packh2(v10, v11));
            }
            grid_barrier(++ep);
            // h stays in buffers [p]
        } else {
            p ^= 1;
        }
    }
}

// ---------------------------------------------------------------------------
extern "C" void kernel_launch(void* const* d_in, const int* in_sizes, int n_in,
                              void* d_out, int out_size) {
    (void)in_sizes; (void)n_in; (void)out_size;
    const float* x  = (const float*)d_in[0];
    const float* h0 = (const float*)d_in[1];
    const float* Wz = (const float*)d_in[2];
    const float* bz = (const float*)d_in[3];
    const float* Wr = (const float*)d_in[4];
    const float* br = (const float*)d_in[5];
    const float* Wh = (const float*)d_in[6];
    const float* bh = (const float*)d_in[7];
    const float* Wp = (const float*)d_in[8];
    const float* bp = (const float*)d_in[9];
    float* out = (float*)d_out;

    static bool attr_set = false;
    if (!attr_set) {
        cudaFuncSetAttribute(gru_recurrent, cudaFuncAttributeMaxDynamicSharedMemorySize,
                             SM_TOTAL);
        cudaFuncSetAttribute(sgemm_pre_mma, cudaFuncAttributeMaxDynamicSharedMemorySize,
                             SG_SMEM_BYTES);
        attr_set = true;
    }

    transpose_weights<<<dim3(32, 32, 7), dim3(32, 32)>>>(Wz, Wr, Wh, Wp);
    split_weights<<<14336, 512>>>();
    split_x<<<65536, 512>>>(x);
    init_h<<<64, 1024>>>(h0);
    sgemm_pre_mma<<<dim3(8, 256, 3), 256, SG_SMEM_BYTES>>>(bz, br, bh);
    gru_recurrent<<<NB, THR, SM_TOTAL>>>(bp, out);
}